// round 10
// baseline (speedup 1.0000x reference)
#include <cuda_runtime.h>
#include <cuda_fp16.h>
#include <cstdint>

#define ND 32768
#define NE 524288
#define DD 128
#define NH 8

// ---------------- scratch (static device memory; no allocations) ----------------
__device__ float    g_Qnodes[(size_t)ND * DD];   // 16 MB
__device__ __half   g_Vh[(size_t)NE * DD];       // 128 MB (fp16 V)
__device__ float    g_logits[(size_t)NE * NH];   // 16 MB
__device__ float    g_agg[ND * DD];              // 16 MB
__device__ float    g_bqeff[DD];
// preconverted [Wk;Wv] fp16, chunk-tiled: [12 chunks][256 rows][16 u32]
__device__ uint32_t g_WH[12 * 256 * 16];
// CSR edge binning
__device__ int g_cnt[ND];
__device__ int g_off[ND + 1];
__device__ int g_pos[ND];
__device__ int g_elist[NE];

// ---------------- CSR build ----------------
__global__ void k_zero() {
    int i = blockIdx.x * blockDim.x + threadIdx.x;
    if (i < ND) g_cnt[i] = 0;
}
__global__ void k_count(const int* __restrict__ dst_idx) {
    int e = blockIdx.x * blockDim.x + threadIdx.x;
    if (e < NE) atomicAdd(&g_cnt[dst_idx[e]], 1);
}
__global__ void __launch_bounds__(1024) k_scan() {
    __shared__ int ps[1024];
    int t = threadIdx.x;
    int base = t * 32;
    int loc[32];
    int s = 0;
#pragma unroll
    for (int j = 0; j < 32; j++) { loc[j] = s; s += g_cnt[base + j]; }
    ps[t] = s;
    __syncthreads();
    for (int off = 1; off < 1024; off <<= 1) {
        int v = (t >= off) ? ps[t - off] : 0;
        __syncthreads();
        ps[t] += v;
        __syncthreads();
    }
    int excl = (t == 0) ? 0 : ps[t - 1];
#pragma unroll
    for (int j = 0; j < 32; j++) {
        int o = excl + loc[j];
        g_off[base + j] = o;
        g_pos[base + j] = o;
    }
    if (t == 1023) g_off[ND] = ps[1023];
}
__global__ void k_scatter(const int* __restrict__ dst_idx) {
    int e = blockIdx.x * blockDim.x + threadIdx.x;
    if (e < NE) {
        int p = atomicAdd(&g_pos[dst_idx[e]], 1);
        g_elist[p] = e;
    }
}

__global__ void k_bqeff(const float* __restrict__ Wq, const float* __restrict__ bq,
                        const float* __restrict__ tb) {
    int j = threadIdx.x;
    float s = bq[j];
    for (int t = 0; t < DD; t++) s += cosf(tb[t]) * Wq[j * 256 + 128 + t];
    g_bqeff[j] = s;
}

// ======== fp16 pack helpers ========
__device__ __forceinline__ uint32_t pack2h(float x, float y) {
    __half hx = __float2half_rn(x), hy = __float2half_rn(y);
    return (uint32_t)__half_as_ushort(hx) | ((uint32_t)__half_as_ushort(hy) << 16);
}
__device__ __forceinline__ void cstoreH(uint32_t* H, int i, float4 v) {
    *(uint2*)(H + i) = make_uint2(pack2h(v.x, v.y), pack2h(v.z, v.w));
}

// ---------------- weight preconversion: single fp16 ----------------
__global__ void k_wconv(const float* __restrict__ Wk, const float* __restrict__ Wv) {
    int i = blockIdx.x * blockDim.x + threadIdx.x;   // 49152 u32 slots
    int c = i >> 12;
    int n = (i >> 4) & 255;
    int q = i & 15;
    int k = c * 32 + q * 2;
    const float* src = (n < 128) ? &Wk[n * 384 + k] : &Wv[(n - 128) * 384 + k];
    g_WH[i] = pack2h(src[0], src[1]);
}

// ---------------- Q projection (SIMT fp32, small) ----------------
__global__ void __launch_bounds__(256) k_gemmQ(const float* __restrict__ h,
                                               const float* __restrict__ Wq) {
    __shared__ float As[32][132];
    __shared__ float Bs[32][132];
    int tid = threadIdx.x, tx = tid & 15, ty = tid >> 4;
    int m0 = blockIdx.x * 128;
    float c[8][8];
#pragma unroll
    for (int i = 0; i < 8; i++)
#pragma unroll
        for (int j = 0; j < 8; j++) c[i][j] = 0.f;

    for (int kc = 0; kc < 128; kc += 32) {
#pragma unroll
        for (int r = 0; r < 16; r++) {
            int t = tid + r * 256;
            int m = t >> 5, k = t & 31;
            As[k][m] = h[(size_t)(m0 + m) * DD + kc + k];
            Bs[k][m] = Wq[m * 256 + kc + k];
        }
        __syncthreads();
#pragma unroll 8
        for (int k = 0; k < 32; k++) {
            float a[8], b[8];
            *(float4*)&a[0] = *(const float4*)&As[k][ty * 8];
            *(float4*)&a[4] = *(const float4*)&As[k][ty * 8 + 4];
            *(float4*)&b[0] = *(const float4*)&Bs[k][tx * 8];
            *(float4*)&b[4] = *(const float4*)&Bs[k][tx * 8 + 4];
#pragma unroll
            for (int i = 0; i < 8; i++)
#pragma unroll
                for (int j = 0; j < 8; j++) c[i][j] = fmaf(a[i], b[j], c[i][j]);
        }
        __syncthreads();
    }
#pragma unroll
    for (int i = 0; i < 8; i++) {
        int m = m0 + ty * 8 + i;
#pragma unroll
        for (int jg = 0; jg < 2; jg++) {
            float4 o;
            o.x = c[i][jg * 4 + 0] + g_bqeff[tx * 8 + jg * 4 + 0];
            o.y = c[i][jg * 4 + 1] + g_bqeff[tx * 8 + jg * 4 + 1];
            o.z = c[i][jg * 4 + 2] + g_bqeff[tx * 8 + jg * 4 + 2];
            o.w = c[i][jg * 4 + 3] + g_bqeff[tx * 8 + jg * 4 + 3];
            *(float4*)&g_Qnodes[(size_t)m * DD + tx * 8 + jg * 4] = o;
        }
    }
}

// ======== mma.sync / ldmatrix / cp.async primitives ========
__device__ __forceinline__ void mma_f16(float* d, const uint32_t* a, const uint32_t* b) {
    asm volatile(
        "mma.sync.aligned.m16n8k16.row.col.f32.f16.f16.f32 "
        "{%0,%1,%2,%3},{%4,%5,%6,%7},{%8,%9},{%0,%1,%2,%3};"
        : "+f"(d[0]), "+f"(d[1]), "+f"(d[2]), "+f"(d[3])
        : "r"(a[0]), "r"(a[1]), "r"(a[2]), "r"(a[3]), "r"(b[0]), "r"(b[1]));
}
#define LDMX4(r, addr) \
    asm volatile("ldmatrix.sync.aligned.m8n8.x4.shared.b16 {%0,%1,%2,%3}, [%4];" \
        : "=r"((r)[0]), "=r"((r)[1]), "=r"((r)[2]), "=r"((r)[3]) : "r"(addr))

__device__ __forceinline__ uint32_t smem_u32(const void* p) {
    uint32_t a;
    asm("{ .reg .u64 t; cvta.to.shared.u64 t, %1; cvt.u32.u64 %0, t; }" : "=r"(a) : "l"(p));
    return a;
}
#define CP_ASYNC16(saddr, gptr) \
    asm volatile("cp.async.ca.shared.global [%0], [%1], 16;" :: "r"(saddr), "l"(gptr))
#define CP_COMMIT() asm volatile("cp.async.commit_group;" ::: "memory")
#define CP_WAIT1()  asm volatile("cp.async.wait_group 1;" ::: "memory")
#define CP_WAIT0()  asm volatile("cp.async.wait_group 0;" ::: "memory")

// ---------------- SMEM layout for k_kv (dynamic, 94720 B) ----------------
// 3-stage pipeline. tiles: row stride 20 u32 (80 B) -> ldmatrix conflict-free.
#define OFF_BK    0
#define OFF_BV    512
#define OFF_DT    1024
#define OFF_FREQ  1536
#define OFF_TB    2048
#define OFF_AH    2560                        // [3 stages][128*20 u32] = 3*10240
#define OFF_BH    (OFF_AH + 30720)            // 33280: [3 stages][256*20 u32] = 3*20480
#define KV_SMEM   (OFF_BH + 61440)            // 94720

// ================= fused K+V projection (3-stage, 1 sync/chunk, mma.sync fp16) =================
__global__ void __launch_bounds__(512, 1) k_kv(const float* __restrict__ h,
                                               const float* __restrict__ f,
                                               const float* __restrict__ dt,
                                               const float* __restrict__ freq,
                                               const float* __restrict__ tb,
                                               const float* __restrict__ bk,
                                               const float* __restrict__ bv,
                                               const int* __restrict__ dst_idx) {
    extern __shared__ char smem[];
    uint32_t sb = smem_u32(smem);
    int tid = threadIdx.x, wid = tid >> 5, lane = tid & 31;
    int e0 = blockIdx.x * 128;

    float* sbk   = (float*)(smem + OFF_BK);
    float* sbv   = (float*)(smem + OFF_BV);
    float* dts   = (float*)(smem + OFF_DT);
    float* freqs = (float*)(smem + OFF_FREQ);
    float* tbs   = (float*)(smem + OFF_TB);
    if (tid < 128) {
        sbk[tid] = bk[tid];
        sbv[tid] = bv[tid];
        dts[tid] = dt[e0 + tid];
        freqs[tid] = freq[tid];
        tbs[tid] = tb[tid];
    }

    auto issueB = [&](int g) {
        int s = g % 3;
#pragma unroll
        for (int r = 0; r < 2; r++) {
            int idx = tid + r * 512;
            int n = idx >> 2, q4 = (idx & 3) * 4;
            CP_ASYNC16(sb + OFF_BH + s * 20480 + (n * 20 + q4) * 4,
                       &g_WH[(g * 256 + n) * 16 + q4]);
        }
        CP_COMMIT();
    };

    auto ldgA = [&](int g, float4* av) {
        if (g < 8) {
            const float* base = (g < 4) ? h + (size_t)(ND + e0) * DD + g * 32
                                        : f + (size_t)e0 * DD + (g - 4) * 32;
#pragma unroll
            for (int r = 0; r < 2; r++) {
                int idx = tid + r * 512;
                int m = idx >> 3, kq = (idx & 7) * 4;
                av[r] = *(const float4*)(base + (size_t)m * DD + kq);
            }
        }
    };
    auto convA = [&](int g, const float4* av) {
        int s = g % 3;
        uint32_t* AH = (uint32_t*)(smem + OFF_AH + s * 10240);
#pragma unroll
        for (int r = 0; r < 2; r++) {
            int idx = tid + r * 512;
            int m = idx >> 3, kq = (idx & 7) * 4;
            float4 v;
            if (g < 8) v = av[r];
            else {
                int ko = (g - 8) * 32 + kq;
                float d = dts[m];
                v.x = __cosf(fmaf(d, freqs[ko + 0], tbs[ko + 0]));
                v.y = __cosf(fmaf(d, freqs[ko + 1], tbs[ko + 1]));
                v.z = __cosf(fmaf(d, freqs[ko + 2], tbs[ko + 2]));
                v.w = __cosf(fmaf(d, freqs[ko + 3], tbs[ko + 3]));
            }
            cstoreH(AH, m * 20 + (kq >> 1), v);
        }
    };

    int wm = wid & 3, wn = wid >> 2;
    int qr = lane >> 2, qc = (lane & 3) * 2;
    float d[2][8][4];
#pragma unroll
    for (int mt = 0; mt < 2; mt++)
#pragma unroll
        for (int nt = 0; nt < 8; nt++)
#pragma unroll
            for (int j = 0; j < 4; j++) d[mt][nt][j] = 0.f;

    uint32_t aoff = (uint32_t)(wm * 32 + (lane & 7) + ((lane >> 3) & 1) * 8) * 80
                  + ((lane >> 4) & 1) * 16;
    uint32_t boff = (uint32_t)(wn * 64 + (lane & 7) + ((lane >> 4) & 1) * 8) * 80
                  + ((lane >> 3) & 1) * 16;

    // ---- prologue: stage 0 ready, B(1) in flight, A(1) in regs ----
    float4 av[2];
    issueB(0);
    issueB(1);
    ldgA(0, av);
    convA(0, av);
    ldgA(1, av);
    CP_WAIT1();          // B(0) landed
    __syncthreads();     // stage 0 + smem consts visible

    for (int c = 0; c < 12; c++) {
        int s = c % 3;
        if (c + 2 <= 11) issueB(c + 2);
        if (c + 1 <= 11) convA(c + 1, av);   // STS into stage (c+1)%3
        if (c + 2 <= 11) ldgA(c + 2, av);    // regs for next conv

        // ---- MMA(c) on stage s ----
        uint32_t baseAH = sb + OFF_AH + s * 10240 + aoff;
        uint32_t baseBH = sb + OFF_BH + s * 20480 + boff;
#pragma unroll
        for (int ks = 0; ks < 2; ks++) {
            uint32_t ah[2][4];
            LDMX4(ah[0], baseAH + ks * 32);
            LDMX4(ah[1], baseAH + 1280 + ks * 32);
#pragma unroll
            for (int ntp = 0; ntp < 4; ntp++) {
                uint32_t bh[4];
                LDMX4(bh, baseBH + ntp * 1280 + ks * 32);
#pragma unroll
                for (int mt = 0; mt < 2; mt++) {
                    mma_f16(d[mt][2 * ntp],     ah[mt], &bh[0]);
                    mma_f16(d[mt][2 * ntp + 1], ah[mt], &bh[2]);
                }
            }
        }
        if (c + 2 <= 11)      { CP_WAIT1(); }   // B(c+1) landed (B(c+2) may fly)
        else if (c + 1 <= 11) { CP_WAIT0(); }   // tail: B(11) landed
        __syncthreads();     // publish convA(c+1) + B(c+1); stage (c+1)%3 ready
    }

    // ---- epilogue: K warps write logits; V warps write V (fp16) ----
    if (wn < 2) {
#pragma unroll
        for (int mt = 0; mt < 2; mt++) {
#pragma unroll
            for (int hh2 = 0; hh2 < 2; hh2++) {
                int e = e0 + wm * 32 + mt * 16 + qr + hh2 * 8;
                int dsti = dst_idx[e];
                const float* q = &g_Qnodes[(size_t)dsti * DD];
                float part[4] = {0.f, 0.f, 0.f, 0.f};
#pragma unroll
                for (int nt = 0; nt < 8; nt++) {
                    int cc = wn * 64 + nt * 8 + qc;
                    float v0 = d[mt][nt][hh2 * 2 + 0] + sbk[cc];
                    float v1 = d[mt][nt][hh2 * 2 + 1] + sbk[cc + 1];
                    float2 qv = *(const float2*)&q[cc];
                    part[(nt * 8 + qc) >> 4] += v0 * qv.x + v1 * qv.y;
                }
#pragma unroll
                for (int i = 0; i < 4; i++) {
                    part[i] += __shfl_xor_sync(0xffffffffu, part[i], 1);
                    part[i] += __shfl_xor_sync(0xffffffffu, part[i], 2);
                }
                if ((lane & 3) == 0) {
#pragma unroll
                    for (int hh = 0; hh < 4; hh++) {
                        int head = wn * 4 + hh;
                        float p = part[hh];
                        float l = p > 0.f ? p : 0.2f * p;
                        g_logits[(size_t)e * NH + head] = l;
                    }
                }
            }
        }
    } else {
        int cvb = (wn - 2) * 64;
#pragma unroll
        for (int mt = 0; mt < 2; mt++) {
#pragma unroll
            for (int hh2 = 0; hh2 < 2; hh2++) {
                int e = e0 + wm * 32 + mt * 16 + qr + hh2 * 8;
#pragma unroll
                for (int nt = 0; nt < 8; nt++) {
                    int cc = cvb + nt * 8 + qc;
                    float v0 = d[mt][nt][hh2 * 2 + 0] + sbv[cc];
                    float v1 = d[mt][nt][hh2 * 2 + 1] + sbv[cc + 1];
                    *(uint32_t*)&g_Vh[(size_t)e * DD + cc] = pack2h(v0, v1);
                }
            }
        }
    }
}

// ---------------- per-node softmax + aggregation (warp per dst node, no atomics) ----------------
__global__ void __launch_bounds__(256) k_node() {
    int n = blockIdx.x * 8 + (threadIdx.x >> 5);
    int lane = threadIdx.x & 31;
    int beg = g_off[n], end = g_off[n + 1];

    float mx[NH];
#pragma unroll
    for (int hh = 0; hh < NH; hh++) mx[hh] = -1e30f;
    for (int i = beg + lane; i < end; i += 32) {
        int e = g_elist[i];
        float4 l0 = *(const float4*)&g_logits[(size_t)e * NH];
        float4 l1 = *(const float4*)&g_logits[(size_t)e * NH + 4];
        mx[0] = fmaxf(mx[0], l0.x); mx[1] = fmaxf(mx[1], l0.y);
        mx[2] = fmaxf(mx[2], l0.z); mx[3] = fmaxf(mx[3], l0.w);
        mx[4] = fmaxf(mx[4], l1.x); mx[5] = fmaxf(mx[5], l1.y);
        mx[6] = fmaxf(mx[6], l1.z); mx[7] = fmaxf(mx[7], l1.w);
    }
#pragma unroll
    for (int hh = 0; hh < NH; hh++)
#pragma unroll
        for (int off = 16; off >= 1; off >>= 1)
            mx[hh] = fmaxf(mx[hh], __shfl_xor_sync(0xffffffffu, mx[hh], off));

    float sm[NH];
#pragma unroll
    for (int hh = 0; hh < NH; hh++) sm[hh] = 0.f;
    for (int i = beg + lane; i < end; i += 32) {
        int e = g_elist[i];
        float4 l0 = *(const float4*)&g_logits[(size_t)e * NH];
        float4 l1 = *(const float4*)&g_logits[(size_t)e * NH + 4];
        sm[0] += expf(l0.x - mx[0]); sm[1] += expf(l0.y - mx[1]);
        sm[2] += expf(l0.z - mx[2]); sm[3] += expf(l0.w - mx[3]);
        sm[4] += expf(l1.x - mx[4]); sm[5] += expf(l1.y - mx[5]);
        sm[6] += expf(l1.z - mx[6]); sm[7] += expf(l1.w - mx[7]);
    }
#pragma unroll
    for (int hh = 0; hh < NH; hh++)
#pragma unroll
        for (int off = 16; off >= 1; off >>= 1)
            sm[hh] += __shfl_xor_sync(0xffffffffu, sm[hh], off);

    int head = lane >> 2;
    float mh = mx[head];
    float ish = (sm[head] > 0.f) ? 1.f / sm[head] : 0.f;
    float4 acc = make_float4(0.f, 0.f, 0.f, 0.f);
    for (int i = beg; i < end; i++) {
        int e = __ldg(&g_elist[i]);
        float att = expf(g_logits[(size_t)e * NH + head] - mh) * ish;
        uint2 vp = *(const uint2*)&g_Vh[(size_t)e * DD + lane * 4];
        float2 v01 = __half22float2(*(const __half2*)&vp.x);
        float2 v23 = __half22float2(*(const __half2*)&vp.y);
        acc.x = fmaf(att, v01.x, acc.x);
        acc.y = fmaf(att, v01.y, acc.y);
        acc.z = fmaf(att, v23.x, acc.z);
        acc.w = fmaf(att, v23.y, acc.w);
    }
    *(float4*)&g_agg[n * DD + lane * 4] = acc;
}

// ---------------- output projection + relu + layernorm ----------------
__global__ void __launch_bounds__(256) k_gemmOut(const float* __restrict__ h,
                                                 const float* __restrict__ Wout,
                                                 const float* __restrict__ bout,
                                                 const float* __restrict__ gam,
                                                 const float* __restrict__ bet,
                                                 float* __restrict__ out) {
    __shared__ float As[32][132];
    __shared__ float Bs[32][132];
    int tid = threadIdx.x, tx = tid & 15, ty = tid >> 4;
    int m0 = blockIdx.x * 128;
    float c[8][8];
#pragma unroll
    for (int i = 0; i < 8; i++)
#pragma unroll
        for (int j = 0; j < 8; j++) c[i][j] = 0.f;

    for (int kc = 0; kc < 256; kc += 32) {
#pragma unroll
        for (int r = 0; r < 16; r++) {
            int t = tid + r * 256;
            int m = t >> 5, k = t & 31;
            int kg = kc + k;
            float v;
            if (kg < 128) v = g_agg[(m0 + m) * DD + kg];
            else v = h[(size_t)(m0 + m) * DD + (kg - 128)];
            As[k][m] = v;
            Bs[k][m] = Wout[m * 256 + kg];
        }
        __syncthreads();
#pragma unroll 8
        for (int k = 0; k < 32; k++) {
            float a[8], b[8];
            *(float4*)&a[0] = *(const float4*)&As[k][ty * 8];
            *(float4*)&a[4] = *(const float4*)&As[k][ty * 8 + 4];
            *(float4*)&b[0] = *(const float4*)&Bs[k][tx * 8];
            *(float4*)&b[4] = *(const float4*)&Bs[k][tx * 8 + 4];
#pragma unroll
            for (int i = 0; i < 8; i++)
#pragma unroll
                for (int j = 0; j < 8; j++) c[i][j] = fmaf(a[i], b[j], c[i][j]);
        }
        __syncthreads();
    }

    float bj[8], gj[8], bb[8];
#pragma unroll
    for (int j = 0; j < 8; j++) {
        int col = tx * 8 + j;
        bj[j] = bout[col];
        gj[j] = gam[col];
        bb[j] = bet[col];
    }
#pragma unroll
    for (int i = 0; i < 8; i++) {
        float x[8];
        float s = 0.f, s2 = 0.f;
#pragma unroll
        for (int j = 0; j < 8; j++) {
            x[j] = fmaxf(c[i][j] + bj[j], 0.f);
            s += x[j];
            s2 += x[j] * x[j];
        }
#pragma unroll
        for (int off = 8; off >= 1; off >>= 1) {
            s  += __shfl_xor_sync(0xffffffffu, s,  off, 16);
            s2 += __shfl_xor_sync(0xffffffffu, s2, off, 16);
        }
        float mu = s * (1.f / 128.f);
        float var = s2 * (1.f / 128.f) - mu * mu;
        float inv = rsqrtf(fmaxf(var, 0.f) + 1e-5f);
        int m = m0 + ty * 8 + i;
#pragma unroll
        for (int jg = 0; jg < 2; jg++) {
            float4 o;
            o.x = (x[jg * 4 + 0] - mu) * inv * gj[jg * 4 + 0] + bb[jg * 4 + 0];
            o.y = (x[jg * 4 + 1] - mu) * inv * gj[jg * 4 + 1] + bb[jg * 4 + 1];
            o.z = (x[jg * 4 + 2] - mu) * inv * gj[jg * 4 + 2] + bb[jg * 4 + 2];
            o.w = (x[jg * 4 + 3] - mu) * inv * gj[jg * 4 + 3] + bb[jg * 4 + 3];
            *(float4*)&out[(size_t)m * DD + tx * 8 + jg * 4] = o;
        }
    }
}

// ---------------- launch ----------------
extern "C" void kernel_launch(void* const* d_in, const int* in_sizes, int n_in,
                              void* d_out, int out_size) {
    const float* h    = (const float*)d_in[0];
    const float* f    = (const float*)d_in[1];
    const float* dt   = (const float*)d_in[2];
    const int*   dst  = (const int*)d_in[3];
    const float* freq = (const float*)d_in[4];
    const float* tb   = (const float*)d_in[5];
    const float* Wq   = (const float*)d_in[6];
    const float* bq   = (const float*)d_in[7];
    const float* Wk   = (const float*)d_in[8];
    const float* bk   = (const float*)d_in[9];
    const float* Wv   = (const float*)d_in[10];
    const float* bv   = (const float*)d_in[11];
    const float* Wout = (const float*)d_in[12];
    const float* bout = (const float*)d_in[13];
    const float* gam  = (const float*)d_in[14];
    const float* bet  = (const float*)d_in[15];
    float* out = (float*)d_out;

    cudaFuncSetAttribute(k_kv, cudaFuncAttributeMaxDynamicSharedMemorySize, KV_SMEM);

    k_wconv<<<48, 1024>>>(Wk, Wv);
    k_bqeff<<<1, 128>>>(Wq, bq, tb);
    k_zero<<<ND / 256, 256>>>();
    k_count<<<NE / 256, 256>>>(dst);
    k_scan<<<1, 1024>>>();
    k_scatter<<<NE / 256, 256>>>(dst);
    k_gemmQ<<<ND / 128, 256>>>(h, Wq);
    k_kv<<<NE / 128, 512, KV_SMEM>>>(h, f, dt, freq, tb, bk, bv, dst);
    k_node<<<ND / 8, 256>>>();
    k_gemmOut<<<ND / 128, 256>>>(h, Wout, bout, gam, bet, out);
}

// round 11
// speedup vs baseline: 1.0376x; 1.0376x over previous
#include <cuda_runtime.h>
#include <cuda_fp16.h>
#include <cstdint>

#define ND 32768
#define NE 524288
#define DD 128
#define NH 8

// ---------------- scratch (static device memory; no allocations) ----------------
__device__ float    g_Qnodes[(size_t)ND * DD];   // 16 MB
__device__ __half   g_Vh[(size_t)NE * DD];       // 128 MB (fp16 V)
__device__ float    g_logits[(size_t)NE * NH];   // 16 MB
__device__ float    g_agg[ND * DD];              // 16 MB
__device__ float    g_bqeff[DD];
// preconverted [Wk;Wv] fp16, chunk-tiled: [12 chunks][256 rows][16 u32]
__device__ uint32_t g_WH[12 * 256 * 16];
// CSR edge binning
__device__ int g_cnt[ND];
__device__ int g_off[ND + 1];
__device__ int g_pos[ND];
__device__ int g_elist[NE];

// ---------------- CSR build ----------------
__global__ void k_zero() {
    int i = blockIdx.x * blockDim.x + threadIdx.x;
    if (i < ND) g_cnt[i] = 0;
}
__global__ void k_count(const int* __restrict__ dst_idx) {
    int e = blockIdx.x * blockDim.x + threadIdx.x;
    if (e < NE) atomicAdd(&g_cnt[dst_idx[e]], 1);
}
__global__ void __launch_bounds__(1024) k_scan() {
    __shared__ int ps[1024];
    int t = threadIdx.x;
    int base = t * 32;
    int loc[32];
    int s = 0;
#pragma unroll
    for (int j = 0; j < 32; j++) { loc[j] = s; s += g_cnt[base + j]; }
    ps[t] = s;
    __syncthreads();
    for (int off = 1; off < 1024; off <<= 1) {
        int v = (t >= off) ? ps[t - off] : 0;
        __syncthreads();
        ps[t] += v;
        __syncthreads();
    }
    int excl = (t == 0) ? 0 : ps[t - 1];
#pragma unroll
    for (int j = 0; j < 32; j++) {
        int o = excl + loc[j];
        g_off[base + j] = o;
        g_pos[base + j] = o;
    }
    if (t == 1023) g_off[ND] = ps[1023];
}
__global__ void k_scatter(const int* __restrict__ dst_idx) {
    int e = blockIdx.x * blockDim.x + threadIdx.x;
    if (e < NE) {
        int p = atomicAdd(&g_pos[dst_idx[e]], 1);
        g_elist[p] = e;
    }
}

__global__ void k_bqeff(const float* __restrict__ Wq, const float* __restrict__ bq,
                        const float* __restrict__ tb) {
    int j = threadIdx.x;
    float s = bq[j];
    for (int t = 0; t < DD; t++) s += cosf(tb[t]) * Wq[j * 256 + 128 + t];
    g_bqeff[j] = s;
}

// ======== fp16 pack helpers ========
__device__ __forceinline__ uint32_t pack2h(float x, float y) {
    __half hx = __float2half_rn(x), hy = __float2half_rn(y);
    return (uint32_t)__half_as_ushort(hx) | ((uint32_t)__half_as_ushort(hy) << 16);
}
__device__ __forceinline__ void cstoreH(uint32_t* H, int i, float4 v) {
    *(uint2*)(H + i) = make_uint2(pack2h(v.x, v.y), pack2h(v.z, v.w));
}

// ---------------- weight preconversion: single fp16 ----------------
__global__ void k_wconv(const float* __restrict__ Wk, const float* __restrict__ Wv) {
    int i = blockIdx.x * blockDim.x + threadIdx.x;   // 49152 u32 slots
    int c = i >> 12;
    int n = (i >> 4) & 255;
    int q = i & 15;
    int k = c * 32 + q * 2;
    const float* src = (n < 128) ? &Wk[n * 384 + k] : &Wv[(n - 128) * 384 + k];
    g_WH[i] = pack2h(src[0], src[1]);
}

// ---------------- Q projection (SIMT fp32, small) ----------------
__global__ void __launch_bounds__(256) k_gemmQ(const float* __restrict__ h,
                                               const float* __restrict__ Wq) {
    __shared__ float As[32][132];
    __shared__ float Bs[32][132];
    int tid = threadIdx.x, tx = tid & 15, ty = tid >> 4;
    int m0 = blockIdx.x * 128;
    float c[8][8];
#pragma unroll
    for (int i = 0; i < 8; i++)
#pragma unroll
        for (int j = 0; j < 8; j++) c[i][j] = 0.f;

    for (int kc = 0; kc < 128; kc += 32) {
#pragma unroll
        for (int r = 0; r < 16; r++) {
            int t = tid + r * 256;
            int m = t >> 5, k = t & 31;
            As[k][m] = h[(size_t)(m0 + m) * DD + kc + k];
            Bs[k][m] = Wq[m * 256 + kc + k];
        }
        __syncthreads();
#pragma unroll 8
        for (int k = 0; k < 32; k++) {
            float a[8], b[8];
            *(float4*)&a[0] = *(const float4*)&As[k][ty * 8];
            *(float4*)&a[4] = *(const float4*)&As[k][ty * 8 + 4];
            *(float4*)&b[0] = *(const float4*)&Bs[k][tx * 8];
            *(float4*)&b[4] = *(const float4*)&Bs[k][tx * 8 + 4];
#pragma unroll
            for (int i = 0; i < 8; i++)
#pragma unroll
                for (int j = 0; j < 8; j++) c[i][j] = fmaf(a[i], b[j], c[i][j]);
        }
        __syncthreads();
    }
#pragma unroll
    for (int i = 0; i < 8; i++) {
        int m = m0 + ty * 8 + i;
#pragma unroll
        for (int jg = 0; jg < 2; jg++) {
            float4 o;
            o.x = c[i][jg * 4 + 0] + g_bqeff[tx * 8 + jg * 4 + 0];
            o.y = c[i][jg * 4 + 1] + g_bqeff[tx * 8 + jg * 4 + 1];
            o.z = c[i][jg * 4 + 2] + g_bqeff[tx * 8 + jg * 4 + 2];
            o.w = c[i][jg * 4 + 3] + g_bqeff[tx * 8 + jg * 4 + 3];
            *(float4*)&g_Qnodes[(size_t)m * DD + tx * 8 + jg * 4] = o;
        }
    }
}

// ======== mma.sync / ldmatrix / cp.async primitives ========
__device__ __forceinline__ void mma_f16(float* d, const uint32_t* a, const uint32_t* b) {
    asm volatile(
        "mma.sync.aligned.m16n8k16.row.col.f32.f16.f16.f32 "
        "{%0,%1,%2,%3},{%4,%5,%6,%7},{%8,%9},{%0,%1,%2,%3};"
        : "+f"(d[0]), "+f"(d[1]), "+f"(d[2]), "+f"(d[3])
        : "r"(a[0]), "r"(a[1]), "r"(a[2]), "r"(a[3]), "r"(b[0]), "r"(b[1]));
}
#define LDMX4(r, addr) \
    asm volatile("ldmatrix.sync.aligned.m8n8.x4.shared.b16 {%0,%1,%2,%3}, [%4];" \
        : "=r"((r)[0]), "=r"((r)[1]), "=r"((r)[2]), "=r"((r)[3]) : "r"(addr))

__device__ __forceinline__ uint32_t smem_u32(const void* p) {
    uint32_t a;
    asm("{ .reg .u64 t; cvta.to.shared.u64 t, %1; cvt.u32.u64 %0, t; }" : "=r"(a) : "l"(p));
    return a;
}
#define CP_ASYNC16(saddr, gptr) \
    asm volatile("cp.async.ca.shared.global [%0], [%1], 16;" :: "r"(saddr), "l"(gptr))
#define CP_COMMIT() asm volatile("cp.async.commit_group;" ::: "memory")
#define CP_WAIT1()  asm volatile("cp.async.wait_group 1;" ::: "memory")
#define CP_WAIT0()  asm volatile("cp.async.wait_group 0;" ::: "memory")

// ---------------- SMEM layout for k_kv (dynamic, 53760 B; 2 CTAs/SM) ----------------
// A tile: 64 rows x 20 u32 (80 B row stride). B tile: 256 rows x 20 u32.
#define OFF_BK    0
#define OFF_BV    512
#define OFF_DT    1024
#define OFF_FREQ  1536
#define OFF_TB    2048
#define OFF_AH    2560                        // [2 stages][64*20 u32] = 2*5120
#define OFF_BH    (OFF_AH + 10240)            // 12800: [2 stages][256*20 u32] = 2*20480
#define KV_SMEM   (OFF_BH + 40960)            // 53760

// ================= fused K+V projection (M=64/CTA, 2 CTAs/SM, mma.sync fp16) =================
__global__ void __launch_bounds__(256, 2) k_kv(const float* __restrict__ h,
                                               const float* __restrict__ f,
                                               const float* __restrict__ dt,
                                               const float* __restrict__ freq,
                                               const float* __restrict__ tb,
                                               const float* __restrict__ bk,
                                               const float* __restrict__ bv,
                                               const int* __restrict__ dst_idx) {
    extern __shared__ char smem[];
    uint32_t sb = smem_u32(smem);
    int tid = threadIdx.x, wid = tid >> 5, lane = tid & 31;
    int e0 = blockIdx.x * 64;

    float* sbk   = (float*)(smem + OFF_BK);
    float* sbv   = (float*)(smem + OFF_BV);
    float* dts   = (float*)(smem + OFF_DT);
    float* freqs = (float*)(smem + OFF_FREQ);
    float* tbs   = (float*)(smem + OFF_TB);
    if (tid < 128) {
        sbk[tid] = bk[tid];
        sbv[tid] = bv[tid];
        freqs[tid] = freq[tid];
        tbs[tid] = tb[tid];
        if (tid < 64) dts[tid] = dt[e0 + tid];
    }

    // B: 256 rows x 16 u32 per chunk; 256 thr x 4 cp.async16 = 4096 u32
    auto issueB = [&](int g) {
        int s = g & 1;
#pragma unroll
        for (int r = 0; r < 4; r++) {
            int idx = tid + r * 256;
            int n = idx >> 2, q4 = (idx & 3) * 4;
            CP_ASYNC16(sb + OFF_BH + s * 20480 + (n * 20 + q4) * 4,
                       &g_WH[(g * 256 + n) * 16 + q4]);
        }
        CP_COMMIT();
    };

    // A: 64 rows x 32 cols = 512 float4; 256 thr x 2
    auto ldgA = [&](int g, float4* av) {
        if (g < 8) {
            const float* base = (g < 4) ? h + (size_t)(ND + e0) * DD + g * 32
                                        : f + (size_t)e0 * DD + (g - 4) * 32;
#pragma unroll
            for (int r = 0; r < 2; r++) {
                int idx = tid + r * 256;
                int m = idx >> 3, kq = (idx & 7) * 4;
                av[r] = *(const float4*)(base + (size_t)m * DD + kq);
            }
        }
    };
    auto convA = [&](int g, const float4* av) {
        int s = g & 1;
        uint32_t* AH = (uint32_t*)(smem + OFF_AH + s * 5120);
#pragma unroll
        for (int r = 0; r < 2; r++) {
            int idx = tid + r * 256;
            int m = idx >> 3, kq = (idx & 7) * 4;
            float4 v;
            if (g < 8) v = av[r];
            else {
                int ko = (g - 8) * 32 + kq;
                float d = dts[m];
                v.x = __cosf(fmaf(d, freqs[ko + 0], tbs[ko + 0]));
                v.y = __cosf(fmaf(d, freqs[ko + 1], tbs[ko + 1]));
                v.z = __cosf(fmaf(d, freqs[ko + 2], tbs[ko + 2]));
                v.w = __cosf(fmaf(d, freqs[ko + 3], tbs[ko + 3]));
            }
            cstoreH(AH, m * 20 + (kq >> 1), v);
        }
    };

    int wm = wid & 1, wn = wid >> 1;      // 2 warps in M x 4 warps in N
    int qr = lane >> 2, qc = (lane & 3) * 2;
    float d[2][8][4];
#pragma unroll
    for (int mt = 0; mt < 2; mt++)
#pragma unroll
        for (int nt = 0; nt < 8; nt++)
#pragma unroll
            for (int j = 0; j < 4; j++) d[mt][nt][j] = 0.f;

    uint32_t aoff = (uint32_t)(wm * 32 + (lane & 7) + ((lane >> 3) & 1) * 8) * 80
                  + ((lane >> 4) & 1) * 16;
    uint32_t boff = (uint32_t)(wn * 64 + (lane & 7) + ((lane >> 4) & 1) * 8) * 80
                  + ((lane >> 3) & 1) * 16;

    float4 av[2];
    issueB(0);
    issueB(1);
    ldgA(0, av);
    convA(0, av);
    ldgA(1, av);
    CP_WAIT1();
    __syncthreads();

    for (int c = 0; c < 12; c++) {
        int s = c & 1;
        if (c + 1 <= 11) convA(c + 1, av);   // into stage s^1, overlaps MMA
        if (c + 2 <= 11) ldgA(c + 2, av);

        uint32_t baseAH = sb + OFF_AH + s * 5120 + aoff;
        uint32_t baseBH = sb + OFF_BH + s * 20480 + boff;
#pragma unroll
        for (int ks = 0; ks < 2; ks++) {
            uint32_t ah[2][4];
            LDMX4(ah[0], baseAH + ks * 32);
            LDMX4(ah[1], baseAH + 1280 + ks * 32);   // +16 rows
#pragma unroll
            for (int ntp = 0; ntp < 4; ntp++) {
                uint32_t bh[4];
                LDMX4(bh, baseBH + ntp * 1280 + ks * 32);
#pragma unroll
                for (int mt = 0; mt < 2; mt++) {
                    mma_f16(d[mt][2 * ntp],     ah[mt], &bh[0]);
                    mma_f16(d[mt][2 * ntp + 1], ah[mt], &bh[2]);
                }
            }
        }
        __syncthreads();                     // stage s free
        if (c + 2 <= 11) { issueB(c + 2); CP_WAIT1(); }
        else if (c + 1 <= 11) { CP_WAIT0(); }
        __syncthreads();                     // B(c+1) + A(c+1) visible
    }

    // ---- epilogue: K warps (wn<2) write logits; V warps write V (fp16) ----
    if (wn < 2) {
#pragma unroll
        for (int mt = 0; mt < 2; mt++) {
#pragma unroll
            for (int hh2 = 0; hh2 < 2; hh2++) {
                int e = e0 + wm * 32 + mt * 16 + qr + hh2 * 8;
                int dsti = dst_idx[e];
                const float* q = &g_Qnodes[(size_t)dsti * DD];
                float part[4] = {0.f, 0.f, 0.f, 0.f};
#pragma unroll
                for (int nt = 0; nt < 8; nt++) {
                    int cc = wn * 64 + nt * 8 + qc;
                    float v0 = d[mt][nt][hh2 * 2 + 0] + sbk[cc];
                    float v1 = d[mt][nt][hh2 * 2 + 1] + sbk[cc + 1];
                    float2 qv = *(const float2*)&q[cc];
                    part[(nt * 8 + qc) >> 4] += v0 * qv.x + v1 * qv.y;
                }
#pragma unroll
                for (int i = 0; i < 4; i++) {
                    part[i] += __shfl_xor_sync(0xffffffffu, part[i], 1);
                    part[i] += __shfl_xor_sync(0xffffffffu, part[i], 2);
                }
                if ((lane & 3) == 0) {
#pragma unroll
                    for (int hh = 0; hh < 4; hh++) {
                        int head = wn * 4 + hh;
                        float p = part[hh];
                        float l = p > 0.f ? p : 0.2f * p;
                        g_logits[(size_t)e * NH + head] = l;
                    }
                }
            }
        }
    } else {
        int cvb = (wn - 2) * 64;
#pragma unroll
        for (int mt = 0; mt < 2; mt++) {
#pragma unroll
            for (int hh2 = 0; hh2 < 2; hh2++) {
                int e = e0 + wm * 32 + mt * 16 + qr + hh2 * 8;
#pragma unroll
                for (int nt = 0; nt < 8; nt++) {
                    int cc = cvb + nt * 8 + qc;
                    float v0 = d[mt][nt][hh2 * 2 + 0] + sbv[cc];
                    float v1 = d[mt][nt][hh2 * 2 + 1] + sbv[cc + 1];
                    *(uint32_t*)&g_Vh[(size_t)e * DD + cc] = pack2h(v0, v1);
                }
            }
        }
    }
}

// ---------------- per-node softmax + aggregation (warp per dst node, no atomics) ----------------
__global__ void __launch_bounds__(256) k_node() {
    int n = blockIdx.x * 8 + (threadIdx.x >> 5);
    int lane = threadIdx.x & 31;
    int beg = g_off[n], end = g_off[n + 1];

    float mx[NH];
#pragma unroll
    for (int hh = 0; hh < NH; hh++) mx[hh] = -1e30f;
    for (int i = beg + lane; i < end; i += 32) {
        int e = g_elist[i];
        float4 l0 = *(const float4*)&g_logits[(size_t)e * NH];
        float4 l1 = *(const float4*)&g_logits[(size_t)e * NH + 4];
        mx[0] = fmaxf(mx[0], l0.x); mx[1] = fmaxf(mx[1], l0.y);
        mx[2] = fmaxf(mx[2], l0.z); mx[3] = fmaxf(mx[3], l0.w);
        mx[4] = fmaxf(mx[4], l1.x); mx[5] = fmaxf(mx[5], l1.y);
        mx[6] = fmaxf(mx[6], l1.z); mx[7] = fmaxf(mx[7], l1.w);
    }
#pragma unroll
    for (int hh = 0; hh < NH; hh++)
#pragma unroll
        for (int off = 16; off >= 1; off >>= 1)
            mx[hh] = fmaxf(mx[hh], __shfl_xor_sync(0xffffffffu, mx[hh], off));

    float sm[NH];
#pragma unroll
    for (int hh = 0; hh < NH; hh++) sm[hh] = 0.f;
    for (int i = beg + lane; i < end; i += 32) {
        int e = g_elist[i];
        float4 l0 = *(const float4*)&g_logits[(size_t)e * NH];
        float4 l1 = *(const float4*)&g_logits[(size_t)e * NH + 4];
        sm[0] += expf(l0.x - mx[0]); sm[1] += expf(l0.y - mx[1]);
        sm[2] += expf(l0.z - mx[2]); sm[3] += expf(l0.w - mx[3]);
        sm[4] += expf(l1.x - mx[4]); sm[5] += expf(l1.y - mx[5]);
        sm[6] += expf(l1.z - mx[6]); sm[7] += expf(l1.w - mx[7]);
    }
#pragma unroll
    for (int hh = 0; hh < NH; hh++)
#pragma unroll
        for (int off = 16; off >= 1; off >>= 1)
            sm[hh] += __shfl_xor_sync(0xffffffffu, sm[hh], off);

    int head = lane >> 2;
    float mh = mx[head];
    float ish = (sm[head] > 0.f) ? 1.f / sm[head] : 0.f;
    float4 acc = make_float4(0.f, 0.f, 0.f, 0.f);
    for (int i = beg; i < end; i++) {
        int e = __ldg(&g_elist[i]);
        float att = expf(g_logits[(size_t)e * NH + head] - mh) * ish;
        uint2 vp = *(const uint2*)&g_Vh[(size_t)e * DD + lane * 4];
        float2 v01 = __half22float2(*(const __half2*)&vp.x);
        float2 v23 = __half22float2(*(const __half2*)&vp.y);
        acc.x = fmaf(att, v01.x, acc.x);
        acc.y = fmaf(att, v01.y, acc.y);
        acc.z = fmaf(att, v23.x, acc.z);
        acc.w = fmaf(att, v23.y, acc.w);
    }
    *(float4*)&g_agg[n * DD + lane * 4] = acc;
}

// ---------------- output projection + relu + layernorm ----------------
__global__ void __launch_bounds__(256) k_gemmOut(const float* __restrict__ h,
                                                 const float* __restrict__ Wout,
                                                 const float* __restrict__ bout,
                                                 const float* __restrict__ gam,
                                                 const float* __restrict__ bet,
                                                 float* __restrict__ out) {
    __shared__ float As[32][132];
    __shared__ float Bs[32][132];
    int tid = threadIdx.x, tx = tid & 15, ty = tid >> 4;
    int m0 = blockIdx.x * 128;
    float c[8][8];
#pragma unroll
    for (int i = 0; i < 8; i++)
#pragma unroll
        for (int j = 0; j < 8; j++) c[i][j] = 0.f;

    for (int kc = 0; kc < 256; kc += 32) {
#pragma unroll
        for (int r = 0; r < 16; r++) {
            int t = tid + r * 256;
            int m = t >> 5, k = t & 31;
            int kg = kc + k;
            float v;
            if (kg < 128) v = g_agg[(m0 + m) * DD + kg];
            else v = h[(size_t)(m0 + m) * DD + (kg - 128)];
            As[k][m] = v;
            Bs[k][m] = Wout[m * 256 + kg];
        }
        __syncthreads();
#pragma unroll 8
        for (int k = 0; k < 32; k++) {
            float a[8], b[8];
            *(float4*)&a[0] = *(const float4*)&As[k][ty * 8];
            *(float4*)&a[4] = *(const float4*)&As[k][ty * 8 + 4];
            *(float4*)&b[0] = *(const float4*)&Bs[k][tx * 8];
            *(float4*)&b[4] = *(const float4*)&Bs[k][tx * 8 + 4];
#pragma unroll
            for (int i = 0; i < 8; i++)
#pragma unroll
                for (int j = 0; j < 8; j++) c[i][j] = fmaf(a[i], b[j], c[i][j]);
        }
        __syncthreads();
    }

    float bj[8], gj[8], bb[8];
#pragma unroll
    for (int j = 0; j < 8; j++) {
        int col = tx * 8 + j;
        bj[j] = bout[col];
        gj[j] = gam[col];
        bb[j] = bet[col];
    }
#pragma unroll
    for (int i = 0; i < 8; i++) {
        float x[8];
        float s = 0.f, s2 = 0.f;
#pragma unroll
        for (int j = 0; j < 8; j++) {
            x[j] = fmaxf(c[i][j] + bj[j], 0.f);
            s += x[j];
            s2 += x[j] * x[j];
        }
#pragma unroll
        for (int off = 8; off >= 1; off >>= 1) {
            s  += __shfl_xor_sync(0xffffffffu, s,  off, 16);
            s2 += __shfl_xor_sync(0xffffffffu, s2, off, 16);
        }
        float mu = s * (1.f / 128.f);
        float var = s2 * (1.f / 128.f) - mu * mu;
        float inv = rsqrtf(fmaxf(var, 0.f) + 1e-5f);
        int m = m0 + ty * 8 + i;
#pragma unroll
        for (int jg = 0; jg < 2; jg++) {
            float4 o;
            o.x = (x[jg * 4 + 0] - mu) * inv * gj[jg * 4 + 0] + bb[jg * 4 + 0];
            o.y = (x[jg * 4 + 1] - mu) * inv * gj[jg * 4 + 1] + bb[jg * 4 + 1];
            o.z = (x[jg * 4 + 2] - mu) * inv * gj[jg * 4 + 2] + bb[jg * 4 + 2];
            o.w = (x[jg * 4 + 3] - mu) * inv * gj[jg * 4 + 3] + bb[jg * 4 + 3];
            *(float4*)&out[(size_t)m * DD + tx * 8 + jg * 4] = o;
        }
    }
}

// ---------------- launch ----------------
extern "C" void kernel_launch(void* const* d_in, const int* in_sizes, int n_in,
                              void* d_out, int out_size) {
    const float* h    = (const float*)d_in[0];
    const float* f    = (const float*)d_in[1];
    const float* dt   = (const float*)d_in[2];
    const int*   dst  = (const int*)d_in[3];
    const float* freq = (const float*)d_in[4];
    const float* tb   = (const float*)d_in[5];
    const float* Wq   = (const float*)d_in[6];
    const float* bq   = (const float*)d_in[7];
    const float* Wk   = (const float*)d_in[8];
    const float* bk   = (const float*)d_in[9];
    const float* Wv   = (const float*)d_in[10];
    const float* bv   = (const float*)d_in[11];
    const float* Wout = (const float*)d_in[12];
    const float* bout = (const float*)d_in[13];
    const float* gam  = (const float*)d_in[14];
    const float* bet  = (const float*)d_in[15];
    float* out = (float*)d_out;

    cudaFuncSetAttribute(k_kv, cudaFuncAttributeMaxDynamicSharedMemorySize, KV_SMEM);

    k_wconv<<<48, 1024>>>(Wk, Wv);
    k_bqeff<<<1, 128>>>(Wq, bq, tb);
    k_zero<<<ND / 256, 256>>>();
    k_count<<<NE / 256, 256>>>(dst);
    k_scan<<<1, 1024>>>();
    k_scatter<<<NE / 256, 256>>>(dst);
    k_gemmQ<<<ND / 128, 256>>>(h, Wq);
    k_kv<<<NE / 64, 256, KV_SMEM>>>(h, f, dt, freq, tb, bk, bv, dst);
    k_node<<<ND / 8, 256>>>();
    k_gemmOut<<<ND / 128, 256>>>(h, Wout, bout, gam, bet, out);
}

// round 12
// speedup vs baseline: 1.1396x; 1.0983x over previous
#include <cuda_runtime.h>
#include <cuda_fp16.h>
#include <cstdint>

#define ND 32768
#define NE 524288
#define DD 128
#define NH 8

// ---------------- scratch (static device memory; no allocations) ----------------
__device__ float    g_Qnodes[(size_t)ND * DD];   // 16 MB
__device__ __half   g_Vh[(size_t)NE * DD];       // 128 MB (fp16 V)
__device__ float    g_logits[(size_t)NE * NH];   // 16 MB
__device__ float    g_agg[ND * DD];              // 16 MB
__device__ float    g_bqeff[DD];
// preconverted [Wk;Wv] fp16, chunk-tiled: [12 chunks][256 rows][16 u32]
__device__ uint32_t g_WH[12 * 256 * 16];
// preconverted Wout fp16, chunk-tiled: [8 chunks][128 rows][16 u32]
__device__ uint32_t g_WOH[8 * 128 * 16];
// CSR edge binning
__device__ int g_cnt[ND];
__device__ int g_off[ND + 1];
__device__ int g_pos[ND];
__device__ int g_elist[NE];

// ---------------- CSR build ----------------
__global__ void k_zero() {
    int i = blockIdx.x * blockDim.x + threadIdx.x;
    if (i < ND) g_cnt[i] = 0;
}
__global__ void k_count(const int* __restrict__ dst_idx) {
    int e = blockIdx.x * blockDim.x + threadIdx.x;
    if (e < NE) atomicAdd(&g_cnt[dst_idx[e]], 1);
}
__global__ void __launch_bounds__(1024) k_scan() {
    __shared__ int ps[1024];
    int t = threadIdx.x;
    int base = t * 32;
    int loc[32];
    int s = 0;
#pragma unroll
    for (int j = 0; j < 32; j++) { loc[j] = s; s += g_cnt[base + j]; }
    ps[t] = s;
    __syncthreads();
    for (int off = 1; off < 1024; off <<= 1) {
        int v = (t >= off) ? ps[t - off] : 0;
        __syncthreads();
        ps[t] += v;
        __syncthreads();
    }
    int excl = (t == 0) ? 0 : ps[t - 1];
#pragma unroll
    for (int j = 0; j < 32; j++) {
        int o = excl + loc[j];
        g_off[base + j] = o;
        g_pos[base + j] = o;
    }
    if (t == 1023) g_off[ND] = ps[1023];
}
__global__ void k_scatter(const int* __restrict__ dst_idx) {
    int e = blockIdx.x * blockDim.x + threadIdx.x;
    if (e < NE) {
        int p = atomicAdd(&g_pos[dst_idx[e]], 1);
        g_elist[p] = e;
    }
}

__global__ void k_bqeff(const float* __restrict__ Wq, const float* __restrict__ bq,
                        const float* __restrict__ tb) {
    int j = threadIdx.x;
    float s = bq[j];
    for (int t = 0; t < DD; t++) s += cosf(tb[t]) * Wq[j * 256 + 128 + t];
    g_bqeff[j] = s;
}

// ======== fp16 pack/split helpers ========
__device__ __forceinline__ uint32_t pack2h(float x, float y) {
    __half hx = __float2half_rn(x), hy = __float2half_rn(y);
    return (uint32_t)__half_as_ushort(hx) | ((uint32_t)__half_as_ushort(hy) << 16);
}
__device__ __forceinline__ void cstoreH(uint32_t* H, int i, float4 v) {
    *(uint2*)(H + i) = make_uint2(pack2h(v.x, v.y), pack2h(v.z, v.w));
}
__device__ __forceinline__ void split2h(float x, float y, uint32_t& hi, uint32_t& lo) {
    __half hx = __float2half_rn(x), hy = __float2half_rn(y);
    __half lx = __float2half_rn(x - __half2float(hx));
    __half ly = __float2half_rn(y - __half2float(hy));
    hi = (uint32_t)__half_as_ushort(hx) | ((uint32_t)__half_as_ushort(hy) << 16);
    lo = (uint32_t)__half_as_ushort(lx) | ((uint32_t)__half_as_ushort(ly) << 16);
}
__device__ __forceinline__ void cstoreHL(uint32_t* H, uint32_t* L, int i, float4 v) {
    uint32_t h0, l0, h1, l1;
    split2h(v.x, v.y, h0, l0);
    split2h(v.z, v.w, h1, l1);
    *(uint2*)(H + i) = make_uint2(h0, h1);
    *(uint2*)(L + i) = make_uint2(l0, l1);
}

// ---------------- weight preconversion ----------------
__global__ void k_wconv(const float* __restrict__ Wk, const float* __restrict__ Wv) {
    int i = blockIdx.x * blockDim.x + threadIdx.x;   // 49152 u32 slots
    int c = i >> 12;
    int n = (i >> 4) & 255;
    int q = i & 15;
    int k = c * 32 + q * 2;
    const float* src = (n < 128) ? &Wk[n * 384 + k] : &Wv[(n - 128) * 384 + k];
    g_WH[i] = pack2h(src[0], src[1]);
}
__global__ void k_wconvO(const float* __restrict__ Wout) {
    int i = blockIdx.x * blockDim.x + threadIdx.x;   // 16384 u32 slots
    int c = i >> 11;           // chunk (128 rows * 16 u32)
    int n = (i >> 4) & 127;
    int q = i & 15;
    int k = c * 32 + q * 2;
    g_WOH[i] = pack2h(Wout[n * 256 + k], Wout[n * 256 + k + 1]);
}

// ---------------- Q projection (SIMT fp32, small) ----------------
__global__ void __launch_bounds__(256) k_gemmQ(const float* __restrict__ h,
                                               const float* __restrict__ Wq) {
    __shared__ float As[32][132];
    __shared__ float Bs[32][132];
    int tid = threadIdx.x, tx = tid & 15, ty = tid >> 4;
    int m0 = blockIdx.x * 128;
    float c[8][8];
#pragma unroll
    for (int i = 0; i < 8; i++)
#pragma unroll
        for (int j = 0; j < 8; j++) c[i][j] = 0.f;

    for (int kc = 0; kc < 128; kc += 32) {
#pragma unroll
        for (int r = 0; r < 16; r++) {
            int t = tid + r * 256;
            int m = t >> 5, k = t & 31;
            As[k][m] = h[(size_t)(m0 + m) * DD + kc + k];
            Bs[k][m] = Wq[m * 256 + kc + k];
        }
        __syncthreads();
#pragma unroll 8
        for (int k = 0; k < 32; k++) {
            float a[8], b[8];
            *(float4*)&a[0] = *(const float4*)&As[k][ty * 8];
            *(float4*)&a[4] = *(const float4*)&As[k][ty * 8 + 4];
            *(float4*)&b[0] = *(const float4*)&Bs[k][tx * 8];
            *(float4*)&b[4] = *(const float4*)&Bs[k][tx * 8 + 4];
#pragma unroll
            for (int i = 0; i < 8; i++)
#pragma unroll
                for (int j = 0; j < 8; j++) c[i][j] = fmaf(a[i], b[j], c[i][j]);
        }
        __syncthreads();
    }
#pragma unroll
    for (int i = 0; i < 8; i++) {
        int m = m0 + ty * 8 + i;
#pragma unroll
        for (int jg = 0; jg < 2; jg++) {
            float4 o;
            o.x = c[i][jg * 4 + 0] + g_bqeff[tx * 8 + jg * 4 + 0];
            o.y = c[i][jg * 4 + 1] + g_bqeff[tx * 8 + jg * 4 + 1];
            o.z = c[i][jg * 4 + 2] + g_bqeff[tx * 8 + jg * 4 + 2];
            o.w = c[i][jg * 4 + 3] + g_bqeff[tx * 8 + jg * 4 + 3];
            *(float4*)&g_Qnodes[(size_t)m * DD + tx * 8 + jg * 4] = o;
        }
    }
}

// ======== mma.sync / ldmatrix / cp.async primitives ========
__device__ __forceinline__ void mma_f16(float* d, const uint32_t* a, const uint32_t* b) {
    asm volatile(
        "mma.sync.aligned.m16n8k16.row.col.f32.f16.f16.f32 "
        "{%0,%1,%2,%3},{%4,%5,%6,%7},{%8,%9},{%0,%1,%2,%3};"
        : "+f"(d[0]), "+f"(d[1]), "+f"(d[2]), "+f"(d[3])
        : "r"(a[0]), "r"(a[1]), "r"(a[2]), "r"(a[3]), "r"(b[0]), "r"(b[1]));
}
#define LDMX4(r, addr) \
    asm volatile("ldmatrix.sync.aligned.m8n8.x4.shared.b16 {%0,%1,%2,%3}, [%4];" \
        : "=r"((r)[0]), "=r"((r)[1]), "=r"((r)[2]), "=r"((r)[3]) : "r"(addr))

__device__ __forceinline__ uint32_t smem_u32(const void* p) {
    uint32_t a;
    asm("{ .reg .u64 t; cvta.to.shared.u64 t, %1; cvt.u32.u64 %0, t; }" : "=r"(a) : "l"(p));
    return a;
}
#define CP_ASYNC16(saddr, gptr) \
    asm volatile("cp.async.ca.shared.global [%0], [%1], 16;" :: "r"(saddr), "l"(gptr))
#define CP_COMMIT() asm volatile("cp.async.commit_group;" ::: "memory")
#define CP_WAIT1()  asm volatile("cp.async.wait_group 1;" ::: "memory")
#define CP_WAIT0()  asm volatile("cp.async.wait_group 0;" ::: "memory")

// ---------------- SMEM layout for k_kv (dynamic, 53760 B; 2 CTAs/SM) ----------------
#define OFF_BK    0
#define OFF_BV    512
#define OFF_DT    1024
#define OFF_FREQ  1536
#define OFF_TB    2048
#define OFF_AH    2560                        // [2 stages][64*20 u32] = 2*5120
#define OFF_BH    (OFF_AH + 10240)            // 12800: [2 stages][256*20 u32] = 2*20480
#define KV_SMEM   (OFF_BH + 40960)            // 53760

// ================= fused K+V projection (M=64/CTA, 2 CTAs/SM, mma.sync fp16) =================
__global__ void __launch_bounds__(256, 2) k_kv(const float* __restrict__ h,
                                               const float* __restrict__ f,
                                               const float* __restrict__ dt,
                                               const float* __restrict__ freq,
                                               const float* __restrict__ tb,
                                               const float* __restrict__ bk,
                                               const float* __restrict__ bv,
                                               const int* __restrict__ dst_idx) {
    extern __shared__ char smem[];
    uint32_t sb = smem_u32(smem);
    int tid = threadIdx.x, wid = tid >> 5, lane = tid & 31;
    int e0 = blockIdx.x * 64;

    float* sbk   = (float*)(smem + OFF_BK);
    float* sbv   = (float*)(smem + OFF_BV);
    float* dts   = (float*)(smem + OFF_DT);
    float* freqs = (float*)(smem + OFF_FREQ);
    float* tbs   = (float*)(smem + OFF_TB);
    if (tid < 128) {
        sbk[tid] = bk[tid];
        sbv[tid] = bv[tid];
        freqs[tid] = freq[tid];
        tbs[tid] = tb[tid];
        if (tid < 64) dts[tid] = dt[e0 + tid];
    }

    auto issueB = [&](int g) {
        int s = g & 1;
#pragma unroll
        for (int r = 0; r < 4; r++) {
            int idx = tid + r * 256;
            int n = idx >> 2, q4 = (idx & 3) * 4;
            CP_ASYNC16(sb + OFF_BH + s * 20480 + (n * 20 + q4) * 4,
                       &g_WH[(g * 256 + n) * 16 + q4]);
        }
        CP_COMMIT();
    };

    auto ldgA = [&](int g, float4* av) {
        if (g < 8) {
            const float* base = (g < 4) ? h + (size_t)(ND + e0) * DD + g * 32
                                        : f + (size_t)e0 * DD + (g - 4) * 32;
#pragma unroll
            for (int r = 0; r < 2; r++) {
                int idx = tid + r * 256;
                int m = idx >> 3, kq = (idx & 7) * 4;
                av[r] = *(const float4*)(base + (size_t)m * DD + kq);
            }
        }
    };
    auto convA = [&](int g, const float4* av) {
        int s = g & 1;
        uint32_t* AH = (uint32_t*)(smem + OFF_AH + s * 5120);
#pragma unroll
        for (int r = 0; r < 2; r++) {
            int idx = tid + r * 256;
            int m = idx >> 3, kq = (idx & 7) * 4;
            float4 v;
            if (g < 8) v = av[r];
            else {
                int ko = (g - 8) * 32 + kq;
                float d = dts[m];
                v.x = __cosf(fmaf(d, freqs[ko + 0], tbs[ko + 0]));
                v.y = __cosf(fmaf(d, freqs[ko + 1], tbs[ko + 1]));
                v.z = __cosf(fmaf(d, freqs[ko + 2], tbs[ko + 2]));
                v.w = __cosf(fmaf(d, freqs[ko + 3], tbs[ko + 3]));
            }
            cstoreH(AH, m * 20 + (kq >> 1), v);
        }
    };

    int wm = wid & 1, wn = wid >> 1;
    int qr = lane >> 2, qc = (lane & 3) * 2;
    float d[2][8][4];
#pragma unroll
    for (int mt = 0; mt < 2; mt++)
#pragma unroll
        for (int nt = 0; nt < 8; nt++)
#pragma unroll
            for (int j = 0; j < 4; j++) d[mt][nt][j] = 0.f;

    uint32_t aoff = (uint32_t)(wm * 32 + (lane & 7) + ((lane >> 3) & 1) * 8) * 80
                  + ((lane >> 4) & 1) * 16;
    uint32_t boff = (uint32_t)(wn * 64 + (lane & 7) + ((lane >> 4) & 1) * 8) * 80
                  + ((lane >> 3) & 1) * 16;

    float4 av[2];
    issueB(0);
    issueB(1);
    ldgA(0, av);
    convA(0, av);
    ldgA(1, av);
    CP_WAIT1();
    __syncthreads();

    for (int c = 0; c < 12; c++) {
        int s = c & 1;
        if (c + 1 <= 11) convA(c + 1, av);
        if (c + 2 <= 11) ldgA(c + 2, av);

        uint32_t baseAH = sb + OFF_AH + s * 5120 + aoff;
        uint32_t baseBH = sb + OFF_BH + s * 20480 + boff;
#pragma unroll
        for (int ks = 0; ks < 2; ks++) {
            uint32_t ah[2][4];
            LDMX4(ah[0], baseAH + ks * 32);
            LDMX4(ah[1], baseAH + 1280 + ks * 32);
#pragma unroll
            for (int ntp = 0; ntp < 4; ntp++) {
                uint32_t bh[4];
                LDMX4(bh, baseBH + ntp * 1280 + ks * 32);
#pragma unroll
                for (int mt = 0; mt < 2; mt++) {
                    mma_f16(d[mt][2 * ntp],     ah[mt], &bh[0]);
                    mma_f16(d[mt][2 * ntp + 1], ah[mt], &bh[2]);
                }
            }
        }
        __syncthreads();
        if (c + 2 <= 11) { issueB(c + 2); CP_WAIT1(); }
        else if (c + 1 <= 11) { CP_WAIT0(); }
        __syncthreads();
    }

    // ---- epilogue: K warps (wn<2) write logits; V warps write V (fp16) ----
    if (wn < 2) {
#pragma unroll
        for (int mt = 0; mt < 2; mt++) {
#pragma unroll
            for (int hh2 = 0; hh2 < 2; hh2++) {
                int e = e0 + wm * 32 + mt * 16 + qr + hh2 * 8;
                int dsti = dst_idx[e];
                const float* q = &g_Qnodes[(size_t)dsti * DD];
                float part[4] = {0.f, 0.f, 0.f, 0.f};
#pragma unroll
                for (int nt = 0; nt < 8; nt++) {
                    int cc = wn * 64 + nt * 8 + qc;
                    float v0 = d[mt][nt][hh2 * 2 + 0] + sbk[cc];
                    float v1 = d[mt][nt][hh2 * 2 + 1] + sbk[cc + 1];
                    float2 qv = *(const float2*)&q[cc];
                    part[(nt * 8 + qc) >> 4] += v0 * qv.x + v1 * qv.y;
                }
#pragma unroll
                for (int i = 0; i < 4; i++) {
                    part[i] += __shfl_xor_sync(0xffffffffu, part[i], 1);
                    part[i] += __shfl_xor_sync(0xffffffffu, part[i], 2);
                }
                if ((lane & 3) == 0) {
#pragma unroll
                    for (int hh = 0; hh < 4; hh++) {
                        int head = wn * 4 + hh;
                        float p = part[hh];
                        float l = p > 0.f ? p : 0.2f * p;
                        g_logits[(size_t)e * NH + head] = l;
                    }
                }
            }
        }
    } else {
        int cvb = (wn - 2) * 64;
#pragma unroll
        for (int mt = 0; mt < 2; mt++) {
#pragma unroll
            for (int hh2 = 0; hh2 < 2; hh2++) {
                int e = e0 + wm * 32 + mt * 16 + qr + hh2 * 8;
#pragma unroll
                for (int nt = 0; nt < 8; nt++) {
                    int cc = cvb + nt * 8 + qc;
                    float v0 = d[mt][nt][hh2 * 2 + 0] + sbv[cc];
                    float v1 = d[mt][nt][hh2 * 2 + 1] + sbv[cc + 1];
                    *(uint32_t*)&g_Vh[(size_t)e * DD + cc] = pack2h(v0, v1);
                }
            }
        }
    }
}

// ---------------- per-node softmax + aggregation (warp per dst node, no atomics) ----------------
__global__ void __launch_bounds__(256) k_node() {
    int n = blockIdx.x * 8 + (threadIdx.x >> 5);
    int lane = threadIdx.x & 31;
    int beg = g_off[n], end = g_off[n + 1];

    float mx[NH];
#pragma unroll
    for (int hh = 0; hh < NH; hh++) mx[hh] = -1e30f;
    for (int i = beg + lane; i < end; i += 32) {
        int e = g_elist[i];
        float4 l0 = *(const float4*)&g_logits[(size_t)e * NH];
        float4 l1 = *(const float4*)&g_logits[(size_t)e * NH + 4];
        mx[0] = fmaxf(mx[0], l0.x); mx[1] = fmaxf(mx[1], l0.y);
        mx[2] = fmaxf(mx[2], l0.z); mx[3] = fmaxf(mx[3], l0.w);
        mx[4] = fmaxf(mx[4], l1.x); mx[5] = fmaxf(mx[5], l1.y);
        mx[6] = fmaxf(mx[6], l1.z); mx[7] = fmaxf(mx[7], l1.w);
    }
#pragma unroll
    for (int hh = 0; hh < NH; hh++)
#pragma unroll
        for (int off = 16; off >= 1; off >>= 1)
            mx[hh] = fmaxf(mx[hh], __shfl_xor_sync(0xffffffffu, mx[hh], off));

    float sm[NH];
#pragma unroll
    for (int hh = 0; hh < NH; hh++) sm[hh] = 0.f;
    for (int i = beg + lane; i < end; i += 32) {
        int e = g_elist[i];
        float4 l0 = *(const float4*)&g_logits[(size_t)e * NH];
        float4 l1 = *(const float4*)&g_logits[(size_t)e * NH + 4];
        sm[0] += expf(l0.x - mx[0]); sm[1] += expf(l0.y - mx[1]);
        sm[2] += expf(l0.z - mx[2]); sm[3] += expf(l0.w - mx[3]);
        sm[4] += expf(l1.x - mx[4]); sm[5] += expf(l1.y - mx[5]);
        sm[6] += expf(l1.z - mx[6]); sm[7] += expf(l1.w - mx[7]);
    }
#pragma unroll
    for (int hh = 0; hh < NH; hh++)
#pragma unroll
        for (int off = 16; off >= 1; off >>= 1)
            sm[hh] += __shfl_xor_sync(0xffffffffu, sm[hh], off);

    int head = lane >> 2;
    float mh = mx[head];
    float ish = (sm[head] > 0.f) ? 1.f / sm[head] : 0.f;
    float4 acc = make_float4(0.f, 0.f, 0.f, 0.f);
    for (int i = beg; i < end; i++) {
        int e = __ldg(&g_elist[i]);
        float att = expf(g_logits[(size_t)e * NH + head] - mh) * ish;
        uint2 vp = *(const uint2*)&g_Vh[(size_t)e * DD + lane * 4];
        float2 v01 = __half22float2(*(const __half2*)&vp.x);
        float2 v23 = __half22float2(*(const __half2*)&vp.y);
        acc.x = fmaf(att, v01.x, acc.x);
        acc.y = fmaf(att, v01.y, acc.y);
        acc.z = fmaf(att, v23.x, acc.z);
        acc.w = fmaf(att, v23.y, acc.w);
    }
    *(float4*)&g_agg[n * DD + lane * 4] = acc;
}

// ================= output projection via mma.sync fp16 (A hi/lo 2-product) + relu + LN =================
// M=64 nodes/CTA, N=128, K=256 in 8 chunks. A = [agg | h_dst] split hi/lo; B = Wout fp16.
__global__ void __launch_bounds__(256, 2) k_gemmOutT(const float* __restrict__ h,
                                                     const float* __restrict__ bout,
                                                     const float* __restrict__ gam,
                                                     const float* __restrict__ bet,
                                                     float* __restrict__ out) {
    __shared__ uint32_t sAH[2][64 * 20];
    __shared__ uint32_t sAL[2][64 * 20];
    __shared__ uint32_t sBH[2][128 * 20];
    __shared__ float sb_bout[128], sb_gam[128], sb_bet[128];
    __shared__ float rs[64], rs2[64];

    int tid = threadIdx.x, wid = tid >> 5, lane = tid & 31;
    int m0 = blockIdx.x * 64;
    uint32_t sbAH = smem_u32(&sAH[0][0]);
    uint32_t sbAL = smem_u32(&sAL[0][0]);
    uint32_t sbBH = smem_u32(&sBH[0][0]);

    if (tid < 128) {
        sb_bout[tid] = bout[tid];
        sb_gam[tid] = gam[tid];
        sb_bet[tid] = bet[tid];
        if (tid < 64) { rs[tid] = 0.f; rs2[tid] = 0.f; }
    }

    auto issueB = [&](int g) {
        int s = g & 1;
#pragma unroll
        for (int r = 0; r < 2; r++) {
            int idx = tid + r * 256;
            int n = idx >> 2, q4 = (idx & 3) * 4;
            CP_ASYNC16(sbBH + s * 10240 + (n * 20 + q4) * 4,
                       &g_WOH[(g * 128 + n) * 16 + q4]);
        }
        CP_COMMIT();
    };
    auto ldgA = [&](int g, float4* av) {
        const float* base = (g < 4) ? g_agg + (size_t)m0 * DD + g * 32
                                    : h + (size_t)m0 * DD + (g - 4) * 32;
#pragma unroll
        for (int r = 0; r < 2; r++) {
            int idx = tid + r * 256;
            int m = idx >> 3, kq = (idx & 7) * 4;
            av[r] = *(const float4*)(base + (size_t)m * DD + kq);
        }
    };
    auto convA = [&](int g, const float4* av) {
        int s = g & 1;
        uint32_t* AH = (uint32_t*)&sAH[s][0];
        uint32_t* AL = (uint32_t*)&sAL[s][0];
#pragma unroll
        for (int r = 0; r < 2; r++) {
            int idx = tid + r * 256;
            int m = idx >> 3, kq = (idx & 7) * 4;
            cstoreHL(AH, AL, m * 20 + (kq >> 1), av[r]);
        }
    };

    int wm = wid & 1, wn = wid >> 1;      // 2 warps in M x 4 warps in N (32 cols each)
    int qr = lane >> 2, qc = (lane & 3) * 2;
    float d[2][4][4];
#pragma unroll
    for (int mt = 0; mt < 2; mt++)
#pragma unroll
        for (int nt = 0; nt < 4; nt++)
#pragma unroll
            for (int j = 0; j < 4; j++) d[mt][nt][j] = 0.f;

    uint32_t aoff = (uint32_t)(wm * 32 + (lane & 7) + ((lane >> 3) & 1) * 8) * 80
                  + ((lane >> 4) & 1) * 16;
    uint32_t boff = (uint32_t)(wn * 32 + (lane & 7) + ((lane >> 4) & 1) * 8) * 80
                  + ((lane >> 3) & 1) * 16;

    float4 av[2];
    issueB(0);
    issueB(1);
    ldgA(0, av);
    convA(0, av);
    ldgA(1, av);
    CP_WAIT1();
    __syncthreads();

    for (int c = 0; c < 8; c++) {
        int s = c & 1;
        if (c + 1 <= 7) convA(c + 1, av);
        if (c + 2 <= 7) ldgA(c + 2, av);

        uint32_t baseAH = sbAH + s * 5120 + aoff;
        uint32_t baseAL = sbAL + s * 5120 + aoff;
        uint32_t baseBH = sbBH + s * 10240 + boff;
#pragma unroll
        for (int ks = 0; ks < 2; ks++) {
            uint32_t ah[2][4], al[2][4];
            LDMX4(ah[0], baseAH + ks * 32);
            LDMX4(ah[1], baseAH + 1280 + ks * 32);
            LDMX4(al[0], baseAL + ks * 32);
            LDMX4(al[1], baseAL + 1280 + ks * 32);
#pragma unroll
            for (int ntp = 0; ntp < 2; ntp++) {
                uint32_t bh[4];
                LDMX4(bh, baseBH + ntp * 1280 + ks * 32);
#pragma unroll
                for (int mt = 0; mt < 2; mt++) {
                    mma_f16(d[mt][2 * ntp],     ah[mt], &bh[0]);
                    mma_f16(d[mt][2 * ntp],     al[mt], &bh[0]);
                    mma_f16(d[mt][2 * ntp + 1], ah[mt], &bh[2]);
                    mma_f16(d[mt][2 * ntp + 1], al[mt], &bh[2]);
                }
            }
        }
        __syncthreads();
        if (c + 2 <= 7) { issueB(c + 2); CP_WAIT1(); }
        else if (c + 1 <= 7) { CP_WAIT0(); }
        __syncthreads();
    }

    // ---- epilogue: bias + relu, row sums (cross-warp via shared atomics), LN, store ----
#pragma unroll
    for (int mt = 0; mt < 2; mt++) {
#pragma unroll
        for (int hh2 = 0; hh2 < 2; hh2++) {
            float s = 0.f, s2 = 0.f;
#pragma unroll
            for (int nt = 0; nt < 4; nt++) {
#pragma unroll
                for (int cc2 = 0; cc2 < 2; cc2++) {
                    int col = wn * 32 + nt * 8 + qc + cc2;
                    float xv = fmaxf(d[mt][nt][hh2 * 2 + cc2] + sb_bout[col], 0.f);
                    d[mt][nt][hh2 * 2 + cc2] = xv;
                    s += xv;
                    s2 += xv * xv;
                }
            }
            s  += __shfl_xor_sync(0xffffffffu, s, 1);
            s  += __shfl_xor_sync(0xffffffffu, s, 2);
            s2 += __shfl_xor_sync(0xffffffffu, s2, 1);
            s2 += __shfl_xor_sync(0xffffffffu, s2, 2);
            if ((lane & 3) == 0) {
                int r = wm * 32 + mt * 16 + qr + hh2 * 8;
                atomicAdd(&rs[r], s);
                atomicAdd(&rs2[r], s2);
            }
        }
    }
    __syncthreads();
#pragma unroll
    for (int mt = 0; mt < 2; mt++) {
#pragma unroll
        for (int hh2 = 0; hh2 < 2; hh2++) {
            int r = wm * 32 + mt * 16 + qr + hh2 * 8;
            float mu = rs[r] * (1.f / 128.f);
            float var = rs2[r] * (1.f / 128.f) - mu * mu;
            float inv = rsqrtf(fmaxf(var, 0.f) + 1e-5f);
            int m = m0 + r;
#pragma unroll
            for (int nt = 0; nt < 4; nt++) {
                int col = wn * 32 + nt * 8 + qc;
                float2 o;
                o.x = (d[mt][nt][hh2 * 2 + 0] - mu) * inv * sb_gam[col] + sb_bet[col];
                o.y = (d[mt][nt][hh2 * 2 + 1] - mu) * inv * sb_gam[col + 1] + sb_bet[col + 1];
                *(float2*)&out[(size_t)m * DD + col] = o;
            }
        }
    }
}

// ---------------- launch ----------------
extern "C" void kernel_launch(void* const* d_in, const int* in_sizes, int n_in,
                              void* d_out, int out_size) {
    const float* h    = (const float*)d_in[0];
    const float* f    = (const float*)d_in[1];
    const float* dt   = (const float*)d_in[2];
    const int*   dst  = (const int*)d_in[3];
    const float* freq = (const float*)d_in[4];
    const float* tb   = (const float*)d_in[5];
    const float* Wq   = (const float*)d_in[6];
    const float* bq   = (const float*)d_in[7];
    const float* Wk   = (const float*)d_in[8];
    const float* bk   = (const float*)d_in[9];
    const float* Wv   = (const float*)d_in[10];
    const float* bv   = (const float*)d_in[11];
    const float* Wout = (const float*)d_in[12];
    const float* bout = (const float*)d_in[13];
    const float* gam  = (const float*)d_in[14];
    const float* bet  = (const float*)d_in[15];
    float* out = (float*)d_out;

    cudaFuncSetAttribute(k_kv, cudaFuncAttributeMaxDynamicSharedMemorySize, KV_SMEM);

    k_wconv<<<48, 1024>>>(Wk, Wv);
    k_wconvO<<<16, 1024>>>(Wout);
    k_bqeff<<<1, 128>>>(Wq, bq, tb);
    k_zero<<<ND / 256, 256>>>();
    k_count<<<NE / 256, 256>>>(dst);
    k_scan<<<1, 1024>>>();
    k_scatter<<<NE / 256, 256>>>(dst);
    k_gemmQ<<<ND / 128, 256>>>(h, Wq);
    k_kv<<<NE / 64, 256, KV_SMEM>>>(h, f, dt, freq, tb, bk, bv, dst);
    k_node<<<ND / 8, 256>>>();
    k_gemmOutT<<<ND / 64, 256>>>(h, bout, gam, bet, out);
}

// round 13
// speedup vs baseline: 1.1642x; 1.0216x over previous
#include <cuda_runtime.h>
#include <cuda_fp16.h>
#include <cstdint>

#define ND 32768
#define NE 524288
#define DD 128
#define NH 8

// ---------------- scratch (static device memory; no allocations) ----------------
__device__ float    g_Qnodes[(size_t)ND * DD];   // 16 MB
__device__ __half   g_Vh[(size_t)NE * DD];       // 128 MB (fp16 V)
__device__ float    g_logits[(size_t)NE * NH];   // 16 MB
__device__ float    g_agg[ND * DD];              // 16 MB
__device__ float    g_bqeff[DD];
// preconverted weights fp16, chunk-tiled
__device__ uint32_t g_WH[12 * 256 * 16];   // [Wk;Wv]
__device__ uint32_t g_WOH[8 * 128 * 16];   // Wout
__device__ uint32_t g_WQH[4 * 128 * 16];   // Wq[:, :128]
// CSR edge binning
__device__ int g_cnt[ND];
__device__ int g_off[ND + 1];
__device__ int g_pos[ND];
__device__ int g_elist[NE];

// ---------------- CSR build ----------------
__global__ void k_zero() {
    int i = blockIdx.x * blockDim.x + threadIdx.x;
    if (i < ND) g_cnt[i] = 0;
}
__global__ void k_count(const int* __restrict__ dst_idx) {
    int e = blockIdx.x * blockDim.x + threadIdx.x;
    if (e < NE) atomicAdd(&g_cnt[dst_idx[e]], 1);
}
__global__ void __launch_bounds__(1024) k_scan() {
    __shared__ int ps[1024];
    int t = threadIdx.x;
    int base = t * 32;
    int loc[32];
    int s = 0;
#pragma unroll
    for (int j = 0; j < 32; j++) { loc[j] = s; s += g_cnt[base + j]; }
    ps[t] = s;
    __syncthreads();
    for (int off = 1; off < 1024; off <<= 1) {
        int v = (t >= off) ? ps[t - off] : 0;
        __syncthreads();
        ps[t] += v;
        __syncthreads();
    }
    int excl = (t == 0) ? 0 : ps[t - 1];
#pragma unroll
    for (int j = 0; j < 32; j++) {
        int o = excl + loc[j];
        g_off[base + j] = o;
        g_pos[base + j] = o;
    }
    if (t == 1023) g_off[ND] = ps[1023];
}
__global__ void k_scatter(const int* __restrict__ dst_idx) {
    int e = blockIdx.x * blockDim.x + threadIdx.x;
    if (e < NE) {
        int p = atomicAdd(&g_pos[dst_idx[e]], 1);
        g_elist[p] = e;
    }
}

__global__ void k_bqeff(const float* __restrict__ Wq, const float* __restrict__ bq,
                        const float* __restrict__ tb) {
    int j = threadIdx.x;
    float s = bq[j];
    for (int t = 0; t < DD; t++) s += cosf(tb[t]) * Wq[j * 256 + 128 + t];
    g_bqeff[j] = s;
}

// ======== fp16 pack/split helpers ========
__device__ __forceinline__ uint32_t pack2h(float x, float y) {
    __half hx = __float2half_rn(x), hy = __float2half_rn(y);
    return (uint32_t)__half_as_ushort(hx) | ((uint32_t)__half_as_ushort(hy) << 16);
}
__device__ __forceinline__ void cstoreH(uint32_t* H, int i, float4 v) {
    *(uint2*)(H + i) = make_uint2(pack2h(v.x, v.y), pack2h(v.z, v.w));
}
__device__ __forceinline__ void split2h(float x, float y, uint32_t& hi, uint32_t& lo) {
    __half hx = __float2half_rn(x), hy = __float2half_rn(y);
    __half lx = __float2half_rn(x - __half2float(hx));
    __half ly = __float2half_rn(y - __half2float(hy));
    hi = (uint32_t)__half_as_ushort(hx) | ((uint32_t)__half_as_ushort(hy) << 16);
    lo = (uint32_t)__half_as_ushort(lx) | ((uint32_t)__half_as_ushort(ly) << 16);
}
__device__ __forceinline__ void cstoreHL(uint32_t* H, uint32_t* L, int i, float4 v) {
    uint32_t h0, l0, h1, l1;
    split2h(v.x, v.y, h0, l0);
    split2h(v.z, v.w, h1, l1);
    *(uint2*)(H + i) = make_uint2(h0, h1);
    *(uint2*)(L + i) = make_uint2(l0, l1);
}

// ---------------- weight preconversion ----------------
__global__ void k_wconv(const float* __restrict__ Wk, const float* __restrict__ Wv) {
    int i = blockIdx.x * blockDim.x + threadIdx.x;   // 49152 u32 slots
    int c = i >> 12;
    int n = (i >> 4) & 255;
    int q = i & 15;
    int k = c * 32 + q * 2;
    const float* src = (n < 128) ? &Wk[n * 384 + k] : &Wv[(n - 128) * 384 + k];
    g_WH[i] = pack2h(src[0], src[1]);
}
__global__ void k_wconvO(const float* __restrict__ Wout) {
    int i = blockIdx.x * blockDim.x + threadIdx.x;   // 16384 u32 slots
    int c = i >> 11;
    int n = (i >> 4) & 127;
    int q = i & 15;
    int k = c * 32 + q * 2;
    g_WOH[i] = pack2h(Wout[n * 256 + k], Wout[n * 256 + k + 1]);
}
__global__ void k_wconvQ(const float* __restrict__ Wq) {
    int i = blockIdx.x * blockDim.x + threadIdx.x;   // 8192 u32 slots
    int c = i >> 11;
    int n = (i >> 4) & 127;
    int q = i & 15;
    int k = c * 32 + q * 2;
    g_WQH[i] = pack2h(Wq[n * 256 + k], Wq[n * 256 + k + 1]);
}

// ======== mma.sync / ldmatrix / cp.async primitives ========
__device__ __forceinline__ void mma_f16(float* d, const uint32_t* a, const uint32_t* b) {
    asm volatile(
        "mma.sync.aligned.m16n8k16.row.col.f32.f16.f16.f32 "
        "{%0,%1,%2,%3},{%4,%5,%6,%7},{%8,%9},{%0,%1,%2,%3};"
        : "+f"(d[0]), "+f"(d[1]), "+f"(d[2]), "+f"(d[3])
        : "r"(a[0]), "r"(a[1]), "r"(a[2]), "r"(a[3]), "r"(b[0]), "r"(b[1]));
}
#define LDMX4(r, addr) \
    asm volatile("ldmatrix.sync.aligned.m8n8.x4.shared.b16 {%0,%1,%2,%3}, [%4];" \
        : "=r"((r)[0]), "=r"((r)[1]), "=r"((r)[2]), "=r"((r)[3]) : "r"(addr))

__device__ __forceinline__ uint32_t smem_u32(const void* p) {
    uint32_t a;
    asm("{ .reg .u64 t; cvta.to.shared.u64 t, %1; cvt.u32.u64 %0, t; }" : "=r"(a) : "l"(p));
    return a;
}
#define CP_ASYNC16(saddr, gptr) \
    asm volatile("cp.async.ca.shared.global [%0], [%1], 16;" :: "r"(saddr), "l"(gptr))
#define CP_COMMIT() asm volatile("cp.async.commit_group;" ::: "memory")
#define CP_WAIT1()  asm volatile("cp.async.wait_group 1;" ::: "memory")
#define CP_WAIT0()  asm volatile("cp.async.wait_group 0;" ::: "memory")

// ---------------- SMEM layout for k_kv (dynamic, 53760 B; 2 CTAs/SM) ----------------
#define OFF_BK    0
#define OFF_BV    512
#define OFF_DT    1024
#define OFF_FREQ  1536
#define OFF_TB    2048
#define OFF_AH    2560
#define OFF_BH    (OFF_AH + 10240)
#define KV_SMEM   (OFF_BH + 40960)            // 53760

// ================= fused K+V projection (M=64/CTA, 2 CTAs/SM, mma.sync fp16) =================
__global__ void __launch_bounds__(256, 2) k_kv(const float* __restrict__ h,
                                               const float* __restrict__ f,
                                               const float* __restrict__ dt,
                                               const float* __restrict__ freq,
                                               const float* __restrict__ tb,
                                               const float* __restrict__ bk,
                                               const float* __restrict__ bv,
                                               const int* __restrict__ dst_idx) {
    extern __shared__ char smem[];
    uint32_t sb = smem_u32(smem);
    int tid = threadIdx.x, wid = tid >> 5, lane = tid & 31;
    int e0 = blockIdx.x * 64;

    float* sbk   = (float*)(smem + OFF_BK);
    float* sbv   = (float*)(smem + OFF_BV);
    float* dts   = (float*)(smem + OFF_DT);
    float* freqs = (float*)(smem + OFF_FREQ);
    float* tbs   = (float*)(smem + OFF_TB);
    if (tid < 128) {
        sbk[tid] = bk[tid];
        sbv[tid] = bv[tid];
        freqs[tid] = freq[tid];
        tbs[tid] = tb[tid];
        if (tid < 64) dts[tid] = dt[e0 + tid];
    }

    auto issueB = [&](int g) {
        int s = g & 1;
#pragma unroll
        for (int r = 0; r < 4; r++) {
            int idx = tid + r * 256;
            int n = idx >> 2, q4 = (idx & 3) * 4;
            CP_ASYNC16(sb + OFF_BH + s * 20480 + (n * 20 + q4) * 4,
                       &g_WH[(g * 256 + n) * 16 + q4]);
        }
        CP_COMMIT();
    };

    auto ldgA = [&](int g, float4* av) {
        if (g < 8) {
            const float* base = (g < 4) ? h + (size_t)(ND + e0) * DD + g * 32
                                        : f + (size_t)e0 * DD + (g - 4) * 32;
#pragma unroll
            for (int r = 0; r < 2; r++) {
                int idx = tid + r * 256;
                int m = idx >> 3, kq = (idx & 7) * 4;
                av[r] = *(const float4*)(base + (size_t)m * DD + kq);
            }
        }
    };
    auto convA = [&](int g, const float4* av) {
        int s = g & 1;
        uint32_t* AH = (uint32_t*)(smem + OFF_AH + s * 5120);
#pragma unroll
        for (int r = 0; r < 2; r++) {
            int idx = tid + r * 256;
            int m = idx >> 3, kq = (idx & 7) * 4;
            float4 v;
            if (g < 8) v = av[r];
            else {
                int ko = (g - 8) * 32 + kq;
                float d = dts[m];
                v.x = __cosf(fmaf(d, freqs[ko + 0], tbs[ko + 0]));
                v.y = __cosf(fmaf(d, freqs[ko + 1], tbs[ko + 1]));
                v.z = __cosf(fmaf(d, freqs[ko + 2], tbs[ko + 2]));
                v.w = __cosf(fmaf(d, freqs[ko + 3], tbs[ko + 3]));
            }
            cstoreH(AH, m * 20 + (kq >> 1), v);
        }
    };

    int wm = wid & 1, wn = wid >> 1;
    int qr = lane >> 2, qc = (lane & 3) * 2;
    float d[2][8][4];
#pragma unroll
    for (int mt = 0; mt < 2; mt++)
#pragma unroll
        for (int nt = 0; nt < 8; nt++)
#pragma unroll
            for (int j = 0; j < 4; j++) d[mt][nt][j] = 0.f;

    uint32_t aoff = (uint32_t)(wm * 32 + (lane & 7) + ((lane >> 3) & 1) * 8) * 80
                  + ((lane >> 4) & 1) * 16;
    uint32_t boff = (uint32_t)(wn * 64 + (lane & 7) + ((lane >> 4) & 1) * 8) * 80
                  + ((lane >> 3) & 1) * 16;

    float4 av[2];
    issueB(0);
    issueB(1);
    ldgA(0, av);
    convA(0, av);
    ldgA(1, av);
    CP_WAIT1();
    __syncthreads();

    for (int c = 0; c < 12; c++) {
        int s = c & 1;
        if (c + 1 <= 11) convA(c + 1, av);
        if (c + 2 <= 11) ldgA(c + 2, av);

        uint32_t baseAH = sb + OFF_AH + s * 5120 + aoff;
        uint32_t baseBH = sb + OFF_BH + s * 20480 + boff;
#pragma unroll
        for (int ks = 0; ks < 2; ks++) {
            uint32_t ah[2][4];
            LDMX4(ah[0], baseAH + ks * 32);
            LDMX4(ah[1], baseAH + 1280 + ks * 32);
#pragma unroll
            for (int ntp = 0; ntp < 4; ntp++) {
                uint32_t bh[4];
                LDMX4(bh, baseBH + ntp * 1280 + ks * 32);
#pragma unroll
                for (int mt = 0; mt < 2; mt++) {
                    mma_f16(d[mt][2 * ntp],     ah[mt], &bh[0]);
                    mma_f16(d[mt][2 * ntp + 1], ah[mt], &bh[2]);
                }
            }
        }
        __syncthreads();
        if (c + 2 <= 11) { issueB(c + 2); CP_WAIT1(); }
        else if (c + 1 <= 11) { CP_WAIT0(); }
        __syncthreads();
    }

    // ---- epilogue: K warps (wn<2) write logits; V warps write V (fp16) ----
    if (wn < 2) {
#pragma unroll
        for (int mt = 0; mt < 2; mt++) {
#pragma unroll
            for (int hh2 = 0; hh2 < 2; hh2++) {
                int e = e0 + wm * 32 + mt * 16 + qr + hh2 * 8;
                int dsti = dst_idx[e];
                const float* q = &g_Qnodes[(size_t)dsti * DD];
                float part[4] = {0.f, 0.f, 0.f, 0.f};
#pragma unroll
                for (int nt = 0; nt < 8; nt++) {
                    int cc = wn * 64 + nt * 8 + qc;
                    float v0 = d[mt][nt][hh2 * 2 + 0] + sbk[cc];
                    float v1 = d[mt][nt][hh2 * 2 + 1] + sbk[cc + 1];
                    float2 qv = *(const float2*)&q[cc];
                    part[(nt * 8 + qc) >> 4] += v0 * qv.x + v1 * qv.y;
                }
#pragma unroll
                for (int i = 0; i < 4; i++) {
                    part[i] += __shfl_xor_sync(0xffffffffu, part[i], 1);
                    part[i] += __shfl_xor_sync(0xffffffffu, part[i], 2);
                }
                if ((lane & 3) == 0) {
#pragma unroll
                    for (int hh = 0; hh < 4; hh++) {
                        int head = wn * 4 + hh;
                        float p = part[hh];
                        float l = p > 0.f ? p : 0.2f * p;
                        g_logits[(size_t)e * NH + head] = l;
                    }
                }
            }
        }
    } else {
        int cvb = (wn - 2) * 64;
#pragma unroll
        for (int mt = 0; mt < 2; mt++) {
#pragma unroll
            for (int hh2 = 0; hh2 < 2; hh2++) {
                int e = e0 + wm * 32 + mt * 16 + qr + hh2 * 8;
#pragma unroll
                for (int nt = 0; nt < 8; nt++) {
                    int cc = cvb + nt * 8 + qc;
                    float v0 = d[mt][nt][hh2 * 2 + 0] + sbv[cc];
                    float v1 = d[mt][nt][hh2 * 2 + 1] + sbv[cc + 1];
                    *(uint32_t*)&g_Vh[(size_t)e * DD + cc] = pack2h(v0, v1);
                }
            }
        }
    }
}

// ================= Q projection via mma.sync fp16 (A hi/lo 2-product) =================
// M=64 nodes/CTA, N=128, K=128 in 4 chunks. A = h_dst hi/lo; B = Wq fp16.
__global__ void __launch_bounds__(256, 2) k_gemmQT(const float* __restrict__ h) {
    __shared__ uint32_t sAH[2][64 * 20];
    __shared__ uint32_t sAL[2][64 * 20];
    __shared__ uint32_t sBH[2][128 * 20];
    __shared__ float sb_bq[128];

    int tid = threadIdx.x, wid = tid >> 5, lane = tid & 31;
    int m0 = blockIdx.x * 64;
    uint32_t sbAH = smem_u32(&sAH[0][0]);
    uint32_t sbAL = smem_u32(&sAL[0][0]);
    uint32_t sbBH = smem_u32(&sBH[0][0]);

    if (tid < 128) sb_bq[tid] = g_bqeff[tid];

    auto issueB = [&](int g) {
        int s = g & 1;
#pragma unroll
        for (int r = 0; r < 2; r++) {
            int idx = tid + r * 256;
            int n = idx >> 2, q4 = (idx & 3) * 4;
            CP_ASYNC16(sbBH + s * 10240 + (n * 20 + q4) * 4,
                       &g_WQH[(g * 128 + n) * 16 + q4]);
        }
        CP_COMMIT();
    };
    auto ldgA = [&](int g, float4* av) {
        const float* base = h + (size_t)m0 * DD + g * 32;
#pragma unroll
        for (int r = 0; r < 2; r++) {
            int idx = tid + r * 256;
            int m = idx >> 3, kq = (idx & 7) * 4;
            av[r] = *(const float4*)(base + (size_t)m * DD + kq);
        }
    };
    auto convA = [&](int g, const float4* av) {
        int s = g & 1;
        uint32_t* AH = (uint32_t*)&sAH[s][0];
        uint32_t* AL = (uint32_t*)&sAL[s][0];
#pragma unroll
        for (int r = 0; r < 2; r++) {
            int idx = tid + r * 256;
            int m = idx >> 3, kq = (idx & 7) * 4;
            cstoreHL(AH, AL, m * 20 + (kq >> 1), av[r]);
        }
    };

    int wm = wid & 1, wn = wid >> 1;
    int qr = lane >> 2, qc = (lane & 3) * 2;
    float d[2][4][4];
#pragma unroll
    for (int mt = 0; mt < 2; mt++)
#pragma unroll
        for (int nt = 0; nt < 4; nt++)
#pragma unroll
            for (int j = 0; j < 4; j++) d[mt][nt][j] = 0.f;

    uint32_t aoff = (uint32_t)(wm * 32 + (lane & 7) + ((lane >> 3) & 1) * 8) * 80
                  + ((lane >> 4) & 1) * 16;
    uint32_t boff = (uint32_t)(wn * 32 + (lane & 7) + ((lane >> 4) & 1) * 8) * 80
                  + ((lane >> 3) & 1) * 16;

    float4 av[2];
    issueB(0);
    issueB(1);
    ldgA(0, av);
    convA(0, av);
    ldgA(1, av);
    CP_WAIT1();
    __syncthreads();

    for (int c = 0; c < 4; c++) {
        int s = c & 1;
        if (c + 1 <= 3) convA(c + 1, av);
        if (c + 2 <= 3) ldgA(c + 2, av);

        uint32_t baseAH = sbAH + s * 5120 + aoff;
        uint32_t baseAL = sbAL + s * 5120 + aoff;
        uint32_t baseBH = sbBH + s * 10240 + boff;
#pragma unroll
        for (int ks = 0; ks < 2; ks++) {
            uint32_t ah[2][4], al[2][4];
            LDMX4(ah[0], baseAH + ks * 32);
            LDMX4(ah[1], baseAH + 1280 + ks * 32);
            LDMX4(al[0], baseAL + ks * 32);
            LDMX4(al[1], baseAL + 1280 + ks * 32);
#pragma unroll
            for (int ntp = 0; ntp < 2; ntp++) {
                uint32_t bh[4];
                LDMX4(bh, baseBH + ntp * 1280 + ks * 32);
#pragma unroll
                for (int mt = 0; mt < 2; mt++) {
                    mma_f16(d[mt][2 * ntp],     ah[mt], &bh[0]);
                    mma_f16(d[mt][2 * ntp],     al[mt], &bh[0]);
                    mma_f16(d[mt][2 * ntp + 1], ah[mt], &bh[2]);
                    mma_f16(d[mt][2 * ntp + 1], al[mt], &bh[2]);
                }
            }
        }
        __syncthreads();
        if (c + 2 <= 3) { issueB(c + 2); CP_WAIT1(); }
        else if (c + 1 <= 3) { CP_WAIT0(); }
        __syncthreads();
    }

#pragma unroll
    for (int mt = 0; mt < 2; mt++) {
#pragma unroll
        for (int hh2 = 0; hh2 < 2; hh2++) {
            int m = m0 + wm * 32 + mt * 16 + qr + hh2 * 8;
#pragma unroll
            for (int nt = 0; nt < 4; nt++) {
                int col = wn * 32 + nt * 8 + qc;
                float2 o;
                o.x = d[mt][nt][hh2 * 2 + 0] + sb_bq[col];
                o.y = d[mt][nt][hh2 * 2 + 1] + sb_bq[col + 1];
                *(float2*)&g_Qnodes[(size_t)m * DD + col] = o;
            }
        }
    }
}

// ---------------- per-node softmax + aggregation (warp per dst node, no atomics) ----------------
__global__ void __launch_bounds__(256) k_node() {
    int n = blockIdx.x * 8 + (threadIdx.x >> 5);
    int lane = threadIdx.x & 31;
    int beg = g_off[n], end = g_off[n + 1];

    float mx[NH];
#pragma unroll
    for (int hh = 0; hh < NH; hh++) mx[hh] = -1e30f;
    for (int i = beg + lane; i < end; i += 32) {
        int e = g_elist[i];
        float4 l0 = *(const float4*)&g_logits[(size_t)e * NH];
        float4 l1 = *(const float4*)&g_logits[(size_t)e * NH + 4];
        mx[0] = fmaxf(mx[0], l0.x); mx[1] = fmaxf(mx[1], l0.y);
        mx[2] = fmaxf(mx[2], l0.z); mx[3] = fmaxf(mx[3], l0.w);
        mx[4] = fmaxf(mx[4], l1.x); mx[5] = fmaxf(mx[5], l1.y);
        mx[6] = fmaxf(mx[6], l1.z); mx[7] = fmaxf(mx[7], l1.w);
    }
#pragma unroll
    for (int hh = 0; hh < NH; hh++)
#pragma unroll
        for (int off = 16; off >= 1; off >>= 1)
            mx[hh] = fmaxf(mx[hh], __shfl_xor_sync(0xffffffffu, mx[hh], off));

    float sm[NH];
#pragma unroll
    for (int hh = 0; hh < NH; hh++) sm[hh] = 0.f;
    for (int i = beg + lane; i < end; i += 32) {
        int e = g_elist[i];
        float4 l0 = *(const float4*)&g_logits[(size_t)e * NH];
        float4 l1 = *(const float4*)&g_logits[(size_t)e * NH + 4];
        sm[0] += expf(l0.x - mx[0]); sm[1] += expf(l0.y - mx[1]);
        sm[2] += expf(l0.z - mx[2]); sm[3] += expf(l0.w - mx[3]);
        sm[4] += expf(l1.x - mx[4]); sm[5] += expf(l1.y - mx[5]);
        sm[6] += expf(l1.z - mx[6]); sm[7] += expf(l1.w - mx[7]);
    }
#pragma unroll
    for (int hh = 0; hh < NH; hh++)
#pragma unroll
        for (int off = 16; off >= 1; off >>= 1)
            sm[hh] += __shfl_xor_sync(0xffffffffu, sm[hh], off);

    int head = lane >> 2;
    float mh = mx[head];
    float ish = (sm[head] > 0.f) ? 1.f / sm[head] : 0.f;
    float4 acc = make_float4(0.f, 0.f, 0.f, 0.f);
    int i = beg;
    // 2x unrolled V accumulation (doubles MLP on the dominant gather)
    for (; i + 2 <= end; i += 2) {
        int e0 = __ldg(&g_elist[i]);
        int e1 = __ldg(&g_elist[i + 1]);
        float lg0 = g_logits[(size_t)e0 * NH + head];
        float lg1 = g_logits[(size_t)e1 * NH + head];
        uint2 vp0 = *(const uint2*)&g_Vh[(size_t)e0 * DD + lane * 4];
        uint2 vp1 = *(const uint2*)&g_Vh[(size_t)e1 * DD + lane * 4];
        float a0 = expf(lg0 - mh) * ish;
        float a1 = expf(lg1 - mh) * ish;
        float2 v01 = __half22float2(*(const __half2*)&vp0.x);
        float2 v23 = __half22float2(*(const __half2*)&vp0.y);
        float2 w01 = __half22float2(*(const __half2*)&vp1.x);
        float2 w23 = __half22float2(*(const __half2*)&vp1.y);
        acc.x = fmaf(a0, v01.x, fmaf(a1, w01.x, acc.x));
        acc.y = fmaf(a0, v01.y, fmaf(a1, w01.y, acc.y));
        acc.z = fmaf(a0, v23.x, fmaf(a1, w23.x, acc.z));
        acc.w = fmaf(a0, v23.y, fmaf(a1, w23.y, acc.w));
    }
    for (; i < end; i++) {
        int e = __ldg(&g_elist[i]);
        float att = expf(g_logits[(size_t)e * NH + head] - mh) * ish;
        uint2 vp = *(const uint2*)&g_Vh[(size_t)e * DD + lane * 4];
        float2 v01 = __half22float2(*(const __half2*)&vp.x);
        float2 v23 = __half22float2(*(const __half2*)&vp.y);
        acc.x = fmaf(att, v01.x, acc.x);
        acc.y = fmaf(att, v01.y, acc.y);
        acc.z = fmaf(att, v23.x, acc.z);
        acc.w = fmaf(att, v23.y, acc.w);
    }
    *(float4*)&g_agg[n * DD + lane * 4] = acc;
}

// ================= output projection via mma.sync fp16 (A hi/lo 2-product) + relu + LN =================
__global__ void __launch_bounds__(256, 2) k_gemmOutT(const float* __restrict__ h,
                                                     const float* __restrict__ bout,
                                                     const float* __restrict__ gam,
                                                     const float* __restrict__ bet,
                                                     float* __restrict__ out) {
    __shared__ uint32_t sAH[2][64 * 20];
    __shared__ uint32_t sAL[2][64 * 20];
    __shared__ uint32_t sBH[2][128 * 20];
    __shared__ float sb_bout[128], sb_gam[128], sb_bet[128];
    __shared__ float rs[64], rs2[64];

    int tid = threadIdx.x, wid = tid >> 5, lane = tid & 31;
    int m0 = blockIdx.x * 64;
    uint32_t sbAH = smem_u32(&sAH[0][0]);
    uint32_t sbAL = smem_u32(&sAL[0][0]);
    uint32_t sbBH = smem_u32(&sBH[0][0]);

    if (tid < 128) {
        sb_bout[tid] = bout[tid];
        sb_gam[tid] = gam[tid];
        sb_bet[tid] = bet[tid];
        if (tid < 64) { rs[tid] = 0.f; rs2[tid] = 0.f; }
    }

    auto issueB = [&](int g) {
        int s = g & 1;
#pragma unroll
        for (int r = 0; r < 2; r++) {
            int idx = tid + r * 256;
            int n = idx >> 2, q4 = (idx & 3) * 4;
            CP_ASYNC16(sbBH + s * 10240 + (n * 20 + q4) * 4,
                       &g_WOH[(g * 128 + n) * 16 + q4]);
        }
        CP_COMMIT();
    };
    auto ldgA = [&](int g, float4* av) {
        const float* base = (g < 4) ? g_agg + (size_t)m0 * DD + g * 32
                                    : h + (size_t)m0 * DD + (g - 4) * 32;
#pragma unroll
        for (int r = 0; r < 2; r++) {
            int idx = tid + r * 256;
            int m = idx >> 3, kq = (idx & 7) * 4;
            av[r] = *(const float4*)(base + (size_t)m * DD + kq);
        }
    };
    auto convA = [&](int g, const float4* av) {
        int s = g & 1;
        uint32_t* AH = (uint32_t*)&sAH[s][0];
        uint32_t* AL = (uint32_t*)&sAL[s][0];
#pragma unroll
        for (int r = 0; r < 2; r++) {
            int idx = tid + r * 256;
            int m = idx >> 3, kq = (idx & 7) * 4;
            cstoreHL(AH, AL, m * 20 + (kq >> 1), av[r]);
        }
    };

    int wm = wid & 1, wn = wid >> 1;
    int qr = lane >> 2, qc = (lane & 3) * 2;
    float d[2][4][4];
#pragma unroll
    for (int mt = 0; mt < 2; mt++)
#pragma unroll
        for (int nt = 0; nt < 4; nt++)
#pragma unroll
            for (int j = 0; j < 4; j++) d[mt][nt][j] = 0.f;

    uint32_t aoff = (uint32_t)(wm * 32 + (lane & 7) + ((lane >> 3) & 1) * 8) * 80
                  + ((lane >> 4) & 1) * 16;
    uint32_t boff = (uint32_t)(wn * 32 + (lane & 7) + ((lane >> 4) & 1) * 8) * 80
                  + ((lane >> 3) & 1) * 16;

    float4 av[2];
    issueB(0);
    issueB(1);
    ldgA(0, av);
    convA(0, av);
    ldgA(1, av);
    CP_WAIT1();
    __syncthreads();

    for (int c = 0; c < 8; c++) {
        int s = c & 1;
        if (c + 1 <= 7) convA(c + 1, av);
        if (c + 2 <= 7) ldgA(c + 2, av);

        uint32_t baseAH = sbAH + s * 5120 + aoff;
        uint32_t baseAL = sbAL + s * 5120 + aoff;
        uint32_t baseBH = sbBH + s * 10240 + boff;
#pragma unroll
        for (int ks = 0; ks < 2; ks++) {
            uint32_t ah[2][4], al[2][4];
            LDMX4(ah[0], baseAH + ks * 32);
            LDMX4(ah[1], baseAH + 1280 + ks * 32);
            LDMX4(al[0], baseAL + ks * 32);
            LDMX4(al[1], baseAL + 1280 + ks * 32);
#pragma unroll
            for (int ntp = 0; ntp < 2; ntp++) {
                uint32_t bh[4];
                LDMX4(bh, baseBH + ntp * 1280 + ks * 32);
#pragma unroll
                for (int mt = 0; mt < 2; mt++) {
                    mma_f16(d[mt][2 * ntp],     ah[mt], &bh[0]);
                    mma_f16(d[mt][2 * ntp],     al[mt], &bh[0]);
                    mma_f16(d[mt][2 * ntp + 1], ah[mt], &bh[2]);
                    mma_f16(d[mt][2 * ntp + 1], al[mt], &bh[2]);
                }
            }
        }
        __syncthreads();
        if (c + 2 <= 7) { issueB(c + 2); CP_WAIT1(); }
        else if (c + 1 <= 7) { CP_WAIT0(); }
        __syncthreads();
    }

#pragma unroll
    for (int mt = 0; mt < 2; mt++) {
#pragma unroll
        for (int hh2 = 0; hh2 < 2; hh2++) {
            float s = 0.f, s2 = 0.f;
#pragma unroll
            for (int nt = 0; nt < 4; nt++) {
#pragma unroll
                for (int cc2 = 0; cc2 < 2; cc2++) {
                    int col = wn * 32 + nt * 8 + qc + cc2;
                    float xv = fmaxf(d[mt][nt][hh2 * 2 + cc2] + sb_bout[col], 0.f);
                    d[mt][nt][hh2 * 2 + cc2] = xv;
                    s += xv;
                    s2 += xv * xv;
                }
            }
            s  += __shfl_xor_sync(0xffffffffu, s, 1);
            s  += __shfl_xor_sync(0xffffffffu, s, 2);
            s2 += __shfl_xor_sync(0xffffffffu, s2, 1);
            s2 += __shfl_xor_sync(0xffffffffu, s2, 2);
            if ((lane & 3) == 0) {
                int r = wm * 32 + mt * 16 + qr + hh2 * 8;
                atomicAdd(&rs[r], s);
                atomicAdd(&rs2[r], s2);
            }
        }
    }
    __syncthreads();
#pragma unroll
    for (int mt = 0; mt < 2; mt++) {
#pragma unroll
        for (int hh2 = 0; hh2 < 2; hh2++) {
            int r = wm * 32 + mt * 16 + qr + hh2 * 8;
            float mu = rs[r] * (1.f / 128.f);
            float var = rs2[r] * (1.f / 128.f) - mu * mu;
            float inv = rsqrtf(fmaxf(var, 0.f) + 1e-5f);
            int m = m0 + r;
#pragma unroll
            for (int nt = 0; nt < 4; nt++) {
                int col = wn * 32 + nt * 8 + qc;
                float2 o;
                o.x = (d[mt][nt][hh2 * 2 + 0] - mu) * inv * sb_gam[col] + sb_bet[col];
                o.y = (d[mt][nt][hh2 * 2 + 1] - mu) * inv * sb_gam[col + 1] + sb_bet[col + 1];
                *(float2*)&out[(size_t)m * DD + col] = o;
            }
        }
    }
}

// ---------------- launch ----------------
extern "C" void kernel_launch(void* const* d_in, const int* in_sizes, int n_in,
                              void* d_out, int out_size) {
    const float* h    = (const float*)d_in[0];
    const float* f    = (const float*)d_in[1];
    const float* dt   = (const float*)d_in[2];
    const int*   dst  = (const int*)d_in[3];
    const float* freq = (const float*)d_in[4];
    const float* tb   = (const float*)d_in[5];
    const float* Wq   = (const float*)d_in[6];
    const float* bq   = (const float*)d_in[7];
    const float* Wk   = (const float*)d_in[8];
    const float* bk   = (const float*)d_in[9];
    const float* Wv   = (const float*)d_in[10];
    const float* bv   = (const float*)d_in[11];
    const float* Wout = (const float*)d_in[12];
    const float* bout = (const float*)d_in[13];
    const float* gam  = (const float*)d_in[14];
    const float* bet  = (const float*)d_in[15];
    float* out = (float*)d_out;

    cudaFuncSetAttribute(k_kv, cudaFuncAttributeMaxDynamicSharedMemorySize, KV_SMEM);

    k_wconv<<<48, 1024>>>(Wk, Wv);
    k_wconvO<<<16, 1024>>>(Wout);
    k_wconvQ<<<8, 1024>>>(Wq);
    k_bqeff<<<1, 128>>>(Wq, bq, tb);
    k_zero<<<ND / 256, 256>>>();
    k_count<<<NE / 256, 256>>>(dst);
    k_scan<<<1, 1024>>>();
    k_scatter<<<NE / 256, 256>>>(dst);
    k_gemmQT<<<ND / 64, 256>>>(h);
    k_kv<<<NE / 64, 256, KV_SMEM>>>(h, f, dt, freq, tb, bk, bv, dst);
    k_node<<<ND / 8, 256>>>();
    k_gemmOutT<<<ND / 64, 256>>>(h, bout, gam, bet, out);
}

// round 14
// speedup vs baseline: 1.2045x; 1.0347x over previous
#include <cuda_runtime.h>
#include <cuda_fp16.h>
#include <cstdint>

#define ND 32768
#define NE 524288
#define DD 128
#define NH 8

// ---------------- scratch (static device memory; no allocations) ----------------
__device__ float    g_Qnodes[(size_t)ND * DD];   // 16 MB
__device__ __half   g_Vh[(size_t)NE * DD];       // 128 MB (fp16 V)
__device__ float    g_logits[(size_t)NE * NH];   // 16 MB
__device__ float    g_agg[ND * DD];              // 16 MB
__device__ float    g_bqeff[DD];
// preconverted weights fp16, chunk-tiled
__device__ uint32_t g_WH[12 * 256 * 16];   // [Wk;Wv]
__device__ uint32_t g_WOH[8 * 128 * 16];   // Wout
__device__ uint32_t g_WQH[4 * 128 * 16];   // Wq[:, :128]
// CSR edge binning
__device__ int g_cnt[ND];
__device__ int g_off[ND + 1];
__device__ int g_pos[ND];
__device__ int g_elist[NE];

// ---------------- CSR build ----------------
__global__ void k_zero() {
    int i = blockIdx.x * blockDim.x + threadIdx.x;
    if (i < ND) g_cnt[i] = 0;
}
__global__ void k_count(const int* __restrict__ dst_idx) {
    int e = blockIdx.x * blockDim.x + threadIdx.x;
    if (e < NE) atomicAdd(&g_cnt[dst_idx[e]], 1);
}
__global__ void __launch_bounds__(1024) k_scan() {
    __shared__ int ps[1024];
    int t = threadIdx.x;
    int base = t * 32;
    int loc[32];
    int s = 0;
#pragma unroll
    for (int j = 0; j < 32; j++) { loc[j] = s; s += g_cnt[base + j]; }
    ps[t] = s;
    __syncthreads();
    for (int off = 1; off < 1024; off <<= 1) {
        int v = (t >= off) ? ps[t - off] : 0;
        __syncthreads();
        ps[t] += v;
        __syncthreads();
    }
    int excl = (t == 0) ? 0 : ps[t - 1];
#pragma unroll
    for (int j = 0; j < 32; j++) {
        int o = excl + loc[j];
        g_off[base + j] = o;
        g_pos[base + j] = o;
    }
    if (t == 1023) g_off[ND] = ps[1023];
}
__global__ void k_scatter(const int* __restrict__ dst_idx) {
    int e = blockIdx.x * blockDim.x + threadIdx.x;
    if (e < NE) {
        int p = atomicAdd(&g_pos[dst_idx[e]], 1);
        g_elist[p] = e;
    }
}

// bq_eff[j] = bq[j] + sum_t cos(tb[t]) * Wq[j, 128+t] — parallel: one block per j
__global__ void __launch_bounds__(128) k_bqeff(const float* __restrict__ Wq,
                                               const float* __restrict__ bq,
                                               const float* __restrict__ tb) {
    __shared__ float ws[4];
    int j = blockIdx.x, t = threadIdx.x;
    float v = cosf(tb[t]) * Wq[j * 256 + 128 + t];
#pragma unroll
    for (int off = 16; off >= 1; off >>= 1)
        v += __shfl_xor_sync(0xffffffffu, v, off);
    if ((t & 31) == 0) ws[t >> 5] = v;
    __syncthreads();
    if (t == 0) g_bqeff[j] = bq[j] + ws[0] + ws[1] + ws[2] + ws[3];
}

// ======== fp16 pack/split helpers ========
__device__ __forceinline__ uint32_t pack2h(float x, float y) {
    __half hx = __float2half_rn(x), hy = __float2half_rn(y);
    return (uint32_t)__half_as_ushort(hx) | ((uint32_t)__half_as_ushort(hy) << 16);
}
__device__ __forceinline__ void cstoreH(uint32_t* H, int i, float4 v) {
    *(uint2*)(H + i) = make_uint2(pack2h(v.x, v.y), pack2h(v.z, v.w));
}
__device__ __forceinline__ void split2h(float x, float y, uint32_t& hi, uint32_t& lo) {
    __half hx = __float2half_rn(x), hy = __float2half_rn(y);
    __half lx = __float2half_rn(x - __half2float(hx));
    __half ly = __float2half_rn(y - __half2float(hy));
    hi = (uint32_t)__half_as_ushort(hx) | ((uint32_t)__half_as_ushort(hy) << 16);
    lo = (uint32_t)__half_as_ushort(lx) | ((uint32_t)__half_as_ushort(ly) << 16);
}
__device__ __forceinline__ void cstoreHL(uint32_t* H, uint32_t* L, int i, float4 v) {
    uint32_t h0, l0, h1, l1;
    split2h(v.x, v.y, h0, l0);
    split2h(v.z, v.w, h1, l1);
    *(uint2*)(H + i) = make_uint2(h0, h1);
    *(uint2*)(L + i) = make_uint2(l0, l1);
}

// ---------------- weight preconversion ----------------
__global__ void k_wconv(const float* __restrict__ Wk, const float* __restrict__ Wv) {
    int i = blockIdx.x * blockDim.x + threadIdx.x;   // 49152 u32 slots
    int c = i >> 12;
    int n = (i >> 4) & 255;
    int q = i & 15;
    int k = c * 32 + q * 2;
    const float* src = (n < 128) ? &Wk[n * 384 + k] : &Wv[(n - 128) * 384 + k];
    g_WH[i] = pack2h(src[0], src[1]);
}
__global__ void k_wconvO(const float* __restrict__ Wout) {
    int i = blockIdx.x * blockDim.x + threadIdx.x;   // 16384 u32 slots
    int c = i >> 11;
    int n = (i >> 4) & 127;
    int q = i & 15;
    int k = c * 32 + q * 2;
    g_WOH[i] = pack2h(Wout[n * 256 + k], Wout[n * 256 + k + 1]);
}
__global__ void k_wconvQ(const float* __restrict__ Wq) {
    int i = blockIdx.x * blockDim.x + threadIdx.x;   // 8192 u32 slots
    int c = i >> 11;
    int n = (i >> 4) & 127;
    int q = i & 15;
    int k = c * 32 + q * 2;
    g_WQH[i] = pack2h(Wq[n * 256 + k], Wq[n * 256 + k + 1]);
}

// ======== mma.sync / ldmatrix / cp.async primitives ========
__device__ __forceinline__ void mma_f16(float* d, const uint32_t* a, const uint32_t* b) {
    asm volatile(
        "mma.sync.aligned.m16n8k16.row.col.f32.f16.f16.f32 "
        "{%0,%1,%2,%3},{%4,%5,%6,%7},{%8,%9},{%0,%1,%2,%3};"
        : "+f"(d[0]), "+f"(d[1]), "+f"(d[2]), "+f"(d[3])
        : "r"(a[0]), "r"(a[1]), "r"(a[2]), "r"(a[3]), "r"(b[0]), "r"(b[1]));
}
#define LDMX4(r, addr) \
    asm volatile("ldmatrix.sync.aligned.m8n8.x4.shared.b16 {%0,%1,%2,%3}, [%4];" \
        : "=r"((r)[0]), "=r"((r)[1]), "=r"((r)[2]), "=r"((r)[3]) : "r"(addr))

__device__ __forceinline__ uint32_t smem_u32(const void* p) {
    uint32_t a;
    asm("{ .reg .u64 t; cvta.to.shared.u64 t, %1; cvt.u32.u64 %0, t; }" : "=r"(a) : "l"(p));
    return a;
}
#define CP_ASYNC16(saddr, gptr) \
    asm volatile("cp.async.ca.shared.global [%0], [%1], 16;" :: "r"(saddr), "l"(gptr))
#define CP_COMMIT() asm volatile("cp.async.commit_group;" ::: "memory")
#define CP_WAIT1()  asm volatile("cp.async.wait_group 1;" ::: "memory")
#define CP_WAIT0()  asm volatile("cp.async.wait_group 0;" ::: "memory")

// ---------------- SMEM layout for k_kv (dynamic, 53760 B; 2 CTAs/SM) ----------------
#define OFF_BK    0
#define OFF_BV    512
#define OFF_DT    1024
#define OFF_FREQ  1536
#define OFF_TB    2048
#define OFF_AH    2560
#define OFF_BH    (OFF_AH + 10240)
#define KV_SMEM   (OFF_BH + 40960)            // 53760

// ================= fused K+V projection (M=64/CTA, 2 CTAs/SM, mma.sync fp16) =================
__global__ void __launch_bounds__(256, 2) k_kv(const float* __restrict__ h,
                                               const float* __restrict__ f,
                                               const float* __restrict__ dt,
                                               const float* __restrict__ freq,
                                               const float* __restrict__ tb,
                                               const float* __restrict__ bk,
                                               const float* __restrict__ bv,
                                               const int* __restrict__ dst_idx) {
    extern __shared__ char smem[];
    uint32_t sb = smem_u32(smem);
    int tid = threadIdx.x, wid = tid >> 5, lane = tid & 31;
    int e0 = blockIdx.x * 64;

    float* sbk   = (float*)(smem + OFF_BK);
    float* sbv   = (float*)(smem + OFF_BV);
    float* dts   = (float*)(smem + OFF_DT);
    float* freqs = (float*)(smem + OFF_FREQ);
    float* tbs   = (float*)(smem + OFF_TB);
    if (tid < 128) {
        sbk[tid] = bk[tid];
        sbv[tid] = bv[tid];
        freqs[tid] = freq[tid];
        tbs[tid] = tb[tid];
        if (tid < 64) dts[tid] = dt[e0 + tid];
    }

    auto issueB = [&](int g) {
        int s = g & 1;
#pragma unroll
        for (int r = 0; r < 4; r++) {
            int idx = tid + r * 256;
            int n = idx >> 2, q4 = (idx & 3) * 4;
            CP_ASYNC16(sb + OFF_BH + s * 20480 + (n * 20 + q4) * 4,
                       &g_WH[(g * 256 + n) * 16 + q4]);
        }
        CP_COMMIT();
    };

    auto ldgA = [&](int g, float4* av) {
        if (g < 8) {
            const float* base = (g < 4) ? h + (size_t)(ND + e0) * DD + g * 32
                                        : f + (size_t)e0 * DD + (g - 4) * 32;
#pragma unroll
            for (int r = 0; r < 2; r++) {
                int idx = tid + r * 256;
                int m = idx >> 3, kq = (idx & 7) * 4;
                av[r] = *(const float4*)(base + (size_t)m * DD + kq);
            }
        }
    };
    auto convA = [&](int g, const float4* av) {
        int s = g & 1;
        uint32_t* AH = (uint32_t*)(smem + OFF_AH + s * 5120);
#pragma unroll
        for (int r = 0; r < 2; r++) {
            int idx = tid + r * 256;
            int m = idx >> 3, kq = (idx & 7) * 4;
            float4 v;
            if (g < 8) v = av[r];
            else {
                int ko = (g - 8) * 32 + kq;
                float d = dts[m];
                v.x = __cosf(fmaf(d, freqs[ko + 0], tbs[ko + 0]));
                v.y = __cosf(fmaf(d, freqs[ko + 1], tbs[ko + 1]));
                v.z = __cosf(fmaf(d, freqs[ko + 2], tbs[ko + 2]));
                v.w = __cosf(fmaf(d, freqs[ko + 3], tbs[ko + 3]));
            }
            cstoreH(AH, m * 20 + (kq >> 1), v);
        }
    };

    int wm = wid & 1, wn = wid >> 1;
    int qr = lane >> 2, qc = (lane & 3) * 2;
    float d[2][8][4];
#pragma unroll
    for (int mt = 0; mt < 2; mt++)
#pragma unroll
        for (int nt = 0; nt < 8; nt++)
#pragma unroll
            for (int j = 0; j < 4; j++) d[mt][nt][j] = 0.f;

    uint32_t aoff = (uint32_t)(wm * 32 + (lane & 7) + ((lane >> 3) & 1) * 8) * 80
                  + ((lane >> 4) & 1) * 16;
    uint32_t boff = (uint32_t)(wn * 64 + (lane & 7) + ((lane >> 4) & 1) * 8) * 80
                  + ((lane >> 3) & 1) * 16;

    float4 av[2];
    issueB(0);
    issueB(1);
    ldgA(0, av);
    convA(0, av);
    ldgA(1, av);
    CP_WAIT1();
    __syncthreads();

    for (int c = 0; c < 12; c++) {
        int s = c & 1;
        if (c + 1 <= 11) convA(c + 1, av);
        if (c + 2 <= 11) ldgA(c + 2, av);

        uint32_t baseAH = sb + OFF_AH + s * 5120 + aoff;
        uint32_t baseBH = sb + OFF_BH + s * 20480 + boff;
#pragma unroll
        for (int ks = 0; ks < 2; ks++) {
            uint32_t ah[2][4];
            LDMX4(ah[0], baseAH + ks * 32);
            LDMX4(ah[1], baseAH + 1280 + ks * 32);
#pragma unroll
            for (int ntp = 0; ntp < 4; ntp++) {
                uint32_t bh[4];
                LDMX4(bh, baseBH + ntp * 1280 + ks * 32);
#pragma unroll
                for (int mt = 0; mt < 2; mt++) {
                    mma_f16(d[mt][2 * ntp],     ah[mt], &bh[0]);
                    mma_f16(d[mt][2 * ntp + 1], ah[mt], &bh[2]);
                }
            }
        }
        __syncthreads();
        if (c + 2 <= 11) { issueB(c + 2); CP_WAIT1(); }
        else if (c + 1 <= 11) { CP_WAIT0(); }
        __syncthreads();
    }

    // ---- epilogue: K warps (wn<2) write logits; V warps write V (fp16) ----
    if (wn < 2) {
#pragma unroll
        for (int mt = 0; mt < 2; mt++) {
#pragma unroll
            for (int hh2 = 0; hh2 < 2; hh2++) {
                int e = e0 + wm * 32 + mt * 16 + qr + hh2 * 8;
                int dsti = dst_idx[e];
                const float* q = &g_Qnodes[(size_t)dsti * DD];
                float part[4] = {0.f, 0.f, 0.f, 0.f};
#pragma unroll
                for (int nt = 0; nt < 8; nt++) {
                    int cc = wn * 64 + nt * 8 + qc;
                    float v0 = d[mt][nt][hh2 * 2 + 0] + sbk[cc];
                    float v1 = d[mt][nt][hh2 * 2 + 1] + sbk[cc + 1];
                    float2 qv = *(const float2*)&q[cc];
                    part[(nt * 8 + qc) >> 4] += v0 * qv.x + v1 * qv.y;
                }
#pragma unroll
                for (int i = 0; i < 4; i++) {
                    part[i] += __shfl_xor_sync(0xffffffffu, part[i], 1);
                    part[i] += __shfl_xor_sync(0xffffffffu, part[i], 2);
                }
                if ((lane & 3) == 0) {
#pragma unroll
                    for (int hh = 0; hh < 4; hh++) {
                        int head = wn * 4 + hh;
                        float p = part[hh];
                        float l = p > 0.f ? p : 0.2f * p;
                        g_logits[(size_t)e * NH + head] = l;
                    }
                }
            }
        }
    } else {
        int cvb = (wn - 2) * 64;
#pragma unroll
        for (int mt = 0; mt < 2; mt++) {
#pragma unroll
            for (int hh2 = 0; hh2 < 2; hh2++) {
                int e = e0 + wm * 32 + mt * 16 + qr + hh2 * 8;
#pragma unroll
                for (int nt = 0; nt < 8; nt++) {
                    int cc = cvb + nt * 8 + qc;
                    float v0 = d[mt][nt][hh2 * 2 + 0] + sbv[cc];
                    float v1 = d[mt][nt][hh2 * 2 + 1] + sbv[cc + 1];
                    *(uint32_t*)&g_Vh[(size_t)e * DD + cc] = pack2h(v0, v1);
                }
            }
        }
    }
}

// ================= Q projection via mma.sync fp16 (A hi/lo 2-product) =================
__global__ void __launch_bounds__(256, 2) k_gemmQT(const float* __restrict__ h) {
    __shared__ uint32_t sAH[2][64 * 20];
    __shared__ uint32_t sAL[2][64 * 20];
    __shared__ uint32_t sBH[2][128 * 20];
    __shared__ float sb_bq[128];

    int tid = threadIdx.x, wid = tid >> 5, lane = tid & 31;
    int m0 = blockIdx.x * 64;
    uint32_t sbAH = smem_u32(&sAH[0][0]);
    uint32_t sbAL = smem_u32(&sAL[0][0]);
    uint32_t sbBH = smem_u32(&sBH[0][0]);

    if (tid < 128) sb_bq[tid] = g_bqeff[tid];

    auto issueB = [&](int g) {
        int s = g & 1;
#pragma unroll
        for (int r = 0; r < 2; r++) {
            int idx = tid + r * 256;
            int n = idx >> 2, q4 = (idx & 3) * 4;
            CP_ASYNC16(sbBH + s * 10240 + (n * 20 + q4) * 4,
                       &g_WQH[(g * 128 + n) * 16 + q4]);
        }
        CP_COMMIT();
    };
    auto ldgA = [&](int g, float4* av) {
        const float* base = h + (size_t)m0 * DD + g * 32;
#pragma unroll
        for (int r = 0; r < 2; r++) {
            int idx = tid + r * 256;
            int m = idx >> 3, kq = (idx & 7) * 4;
            av[r] = *(const float4*)(base + (size_t)m * DD + kq);
        }
    };
    auto convA = [&](int g, const float4* av) {
        int s = g & 1;
        uint32_t* AH = (uint32_t*)&sAH[s][0];
        uint32_t* AL = (uint32_t*)&sAL[s][0];
#pragma unroll
        for (int r = 0; r < 2; r++) {
            int idx = tid + r * 256;
            int m = idx >> 3, kq = (idx & 7) * 4;
            cstoreHL(AH, AL, m * 20 + (kq >> 1), av[r]);
        }
    };

    int wm = wid & 1, wn = wid >> 1;
    int qr = lane >> 2, qc = (lane & 3) * 2;
    float d[2][4][4];
#pragma unroll
    for (int mt = 0; mt < 2; mt++)
#pragma unroll
        for (int nt = 0; nt < 4; nt++)
#pragma unroll
            for (int j = 0; j < 4; j++) d[mt][nt][j] = 0.f;

    uint32_t aoff = (uint32_t)(wm * 32 + (lane & 7) + ((lane >> 3) & 1) * 8) * 80
                  + ((lane >> 4) & 1) * 16;
    uint32_t boff = (uint32_t)(wn * 32 + (lane & 7) + ((lane >> 4) & 1) * 8) * 80
                  + ((lane >> 3) & 1) * 16;

    float4 av[2];
    issueB(0);
    issueB(1);
    ldgA(0, av);
    convA(0, av);
    ldgA(1, av);
    CP_WAIT1();
    __syncthreads();

    for (int c = 0; c < 4; c++) {
        int s = c & 1;
        if (c + 1 <= 3) convA(c + 1, av);
        if (c + 2 <= 3) ldgA(c + 2, av);

        uint32_t baseAH = sbAH + s * 5120 + aoff;
        uint32_t baseAL = sbAL + s * 5120 + aoff;
        uint32_t baseBH = sbBH + s * 10240 + boff;
#pragma unroll
        for (int ks = 0; ks < 2; ks++) {
            uint32_t ah[2][4], al[2][4];
            LDMX4(ah[0], baseAH + ks * 32);
            LDMX4(ah[1], baseAH + 1280 + ks * 32);
            LDMX4(al[0], baseAL + ks * 32);
            LDMX4(al[1], baseAL + 1280 + ks * 32);
#pragma unroll
            for (int ntp = 0; ntp < 2; ntp++) {
                uint32_t bh[4];
                LDMX4(bh, baseBH + ntp * 1280 + ks * 32);
#pragma unroll
                for (int mt = 0; mt < 2; mt++) {
                    mma_f16(d[mt][2 * ntp],     ah[mt], &bh[0]);
                    mma_f16(d[mt][2 * ntp],     al[mt], &bh[0]);
                    mma_f16(d[mt][2 * ntp + 1], ah[mt], &bh[2]);
                    mma_f16(d[mt][2 * ntp + 1], al[mt], &bh[2]);
                }
            }
        }
        __syncthreads();
        if (c + 2 <= 3) { issueB(c + 2); CP_WAIT1(); }
        else if (c + 1 <= 3) { CP_WAIT0(); }
        __syncthreads();
    }

#pragma unroll
    for (int mt = 0; mt < 2; mt++) {
#pragma unroll
        for (int hh2 = 0; hh2 < 2; hh2++) {
            int m = m0 + wm * 32 + mt * 16 + qr + hh2 * 8;
#pragma unroll
            for (int nt = 0; nt < 4; nt++) {
                int col = wn * 32 + nt * 8 + qc;
                float2 o;
                o.x = d[mt][nt][hh2 * 2 + 0] + sb_bq[col];
                o.y = d[mt][nt][hh2 * 2 + 1] + sb_bq[col + 1];
                *(float2*)&g_Qnodes[(size_t)m * DD + col] = o;
            }
        }
    }
}

// ---------------- per-node softmax + aggregation (warp per dst node, no atomics) ----------------
__global__ void __launch_bounds__(256) k_node() {
    int n = blockIdx.x * 8 + (threadIdx.x >> 5);
    int lane = threadIdx.x & 31;
    int beg = g_off[n], end = g_off[n + 1];

    float mx[NH];
#pragma unroll
    for (int hh = 0; hh < NH; hh++) mx[hh] = -1e30f;
    for (int i = beg + lane; i < end; i += 32) {
        int e = g_elist[i];
        float4 l0 = *(const float4*)&g_logits[(size_t)e * NH];
        float4 l1 = *(const float4*)&g_logits[(size_t)e * NH + 4];
        mx[0] = fmaxf(mx[0], l0.x); mx[1] = fmaxf(mx[1], l0.y);
        mx[2] = fmaxf(mx[2], l0.z); mx[3] = fmaxf(mx[3], l0.w);
        mx[4] = fmaxf(mx[4], l1.x); mx[5] = fmaxf(mx[5], l1.y);
        mx[6] = fmaxf(mx[6], l1.z); mx[7] = fmaxf(mx[7], l1.w);
    }
#pragma unroll
    for (int hh = 0; hh < NH; hh++)
#pragma unroll
        for (int off = 16; off >= 1; off >>= 1)
            mx[hh] = fmaxf(mx[hh], __shfl_xor_sync(0xffffffffu, mx[hh], off));

    float sm[NH];
#pragma unroll
    for (int hh = 0; hh < NH; hh++) sm[hh] = 0.f;
    for (int i = beg + lane; i < end; i += 32) {
        int e = g_elist[i];
        float4 l0 = *(const float4*)&g_logits[(size_t)e * NH];
        float4 l1 = *(const float4*)&g_logits[(size_t)e * NH + 4];
        sm[0] += expf(l0.x - mx[0]); sm[1] += expf(l0.y - mx[1]);
        sm[2] += expf(l0.z - mx[2]); sm[3] += expf(l0.w - mx[3]);
        sm[4] += expf(l1.x - mx[4]); sm[5] += expf(l1.y - mx[5]);
        sm[6] += expf(l1.z - mx[6]); sm[7] += expf(l1.w - mx[7]);
    }
#pragma unroll
    for (int hh = 0; hh < NH; hh++)
#pragma unroll
        for (int off = 16; off >= 1; off >>= 1)
            sm[hh] += __shfl_xor_sync(0xffffffffu, sm[hh], off);

    int head = lane >> 2;
    float mh = mx[head];
    float ish = (sm[head] > 0.f) ? 1.f / sm[head] : 0.f;
    float4 acc = make_float4(0.f, 0.f, 0.f, 0.f);
    int i = beg;
    for (; i + 2 <= end; i += 2) {
        int e0 = __ldg(&g_elist[i]);
        int e1 = __ldg(&g_elist[i + 1]);
        float lg0 = g_logits[(size_t)e0 * NH + head];
        float lg1 = g_logits[(size_t)e1 * NH + head];
        uint2 vp0 = *(const uint2*)&g_Vh[(size_t)e0 * DD + lane * 4];
        uint2 vp1 = *(const uint2*)&g_Vh[(size_t)e1 * DD + lane * 4];
        float a0 = expf(lg0 - mh) * ish;
        float a1 = expf(lg1 - mh) * ish;
        float2 v01 = __half22float2(*(const __half2*)&vp0.x);
        float2 v23 = __half22float2(*(const __half2*)&vp0.y);
        float2 w01 = __half22float2(*(const __half2*)&vp1.x);
        float2 w23 = __half22float2(*(const __half2*)&vp1.y);
        acc.x = fmaf(a0, v01.x, fmaf(a1, w01.x, acc.x));
        acc.y = fmaf(a0, v01.y, fmaf(a1, w01.y, acc.y));
        acc.z = fmaf(a0, v23.x, fmaf(a1, w23.x, acc.z));
        acc.w = fmaf(a0, v23.y, fmaf(a1, w23.y, acc.w));
    }
    for (; i < end; i++) {
        int e = __ldg(&g_elist[i]);
        float att = expf(g_logits[(size_t)e * NH + head] - mh) * ish;
        uint2 vp = *(const uint2*)&g_Vh[(size_t)e * DD + lane * 4];
        float2 v01 = __half22float2(*(const __half2*)&vp.x);
        float2 v23 = __half22float2(*(const __half2*)&vp.y);
        acc.x = fmaf(att, v01.x, acc.x);
        acc.y = fmaf(att, v01.y, acc.y);
        acc.z = fmaf(att, v23.x, acc.z);
        acc.w = fmaf(att, v23.y, acc.w);
    }
    *(float4*)&g_agg[n * DD + lane * 4] = acc;
}

// ================= output projection via mma.sync fp16 (A hi/lo 2-product) + relu + LN =================
__global__ void __launch_bounds__(256, 2) k_gemmOutT(const float* __restrict__ h,
                                                     const float* __restrict__ bout,
                                                     const float* __restrict__ gam,
                                                     const float* __restrict__ bet,
                                                     float* __restrict__ out) {
    __shared__ uint32_t sAH[2][64 * 20];
    __shared__ uint32_t sAL[2][64 * 20];
    __shared__ uint32_t sBH[2][128 * 20];
    __shared__ float sb_bout[128], sb_gam[128], sb_bet[128];
    __shared__ float rs[64], rs2[64];

    int tid = threadIdx.x, wid = tid >> 5, lane = tid & 31;
    int m0 = blockIdx.x * 64;
    uint32_t sbAH = smem_u32(&sAH[0][0]);
    uint32_t sbAL = smem_u32(&sAL[0][0]);
    uint32_t sbBH = smem_u32(&sBH[0][0]);

    if (tid < 128) {
        sb_bout[tid] = bout[tid];
        sb_gam[tid] = gam[tid];
        sb_bet[tid] = bet[tid];
        if (tid < 64) { rs[tid] = 0.f; rs2[tid] = 0.f; }
    }

    auto issueB = [&](int g) {
        int s = g & 1;
#pragma unroll
        for (int r = 0; r < 2; r++) {
            int idx = tid + r * 256;
            int n = idx >> 2, q4 = (idx & 3) * 4;
            CP_ASYNC16(sbBH + s * 10240 + (n * 20 + q4) * 4,
                       &g_WOH[(g * 128 + n) * 16 + q4]);
        }
        CP_COMMIT();
    };
    auto ldgA = [&](int g, float4* av) {
        const float* base = (g < 4) ? g_agg + (size_t)m0 * DD + g * 32
                                    : h + (size_t)m0 * DD + (g - 4) * 32;
#pragma unroll
        for (int r = 0; r < 2; r++) {
            int idx = tid + r * 256;
            int m = idx >> 3, kq = (idx & 7) * 4;
            av[r] = *(const float4*)(base + (size_t)m * DD + kq);
        }
    };
    auto convA = [&](int g, const float4* av) {
        int s = g & 1;
        uint32_t* AH = (uint32_t*)&sAH[s][0];
        uint32_t* AL = (uint32_t*)&sAL[s][0];
#pragma unroll
        for (int r = 0; r < 2; r++) {
            int idx = tid + r * 256;
            int m = idx >> 3, kq = (idx & 7) * 4;
            cstoreHL(AH, AL, m * 20 + (kq >> 1), av[r]);
        }
    };

    int wm = wid & 1, wn = wid >> 1;
    int qr = lane >> 2, qc = (lane & 3) * 2;
    float d[2][4][4];
#pragma unroll
    for (int mt = 0; mt < 2; mt++)
#pragma unroll
        for (int nt = 0; nt < 4; nt++)
#pragma unroll
            for (int j = 0; j < 4; j++) d[mt][nt][j] = 0.f;

    uint32_t aoff = (uint32_t)(wm * 32 + (lane & 7) + ((lane >> 3) & 1) * 8) * 80
                  + ((lane >> 4) & 1) * 16;
    uint32_t boff = (uint32_t)(wn * 32 + (lane & 7) + ((lane >> 4) & 1) * 8) * 80
                  + ((lane >> 3) & 1) * 16;

    float4 av[2];
    issueB(0);
    issueB(1);
    ldgA(0, av);
    convA(0, av);
    ldgA(1, av);
    CP_WAIT1();
    __syncthreads();

    for (int c = 0; c < 8; c++) {
        int s = c & 1;
        if (c + 1 <= 7) convA(c + 1, av);
        if (c + 2 <= 7) ldgA(c + 2, av);

        uint32_t baseAH = sbAH + s * 5120 + aoff;
        uint32_t baseAL = sbAL + s * 5120 + aoff;
        uint32_t baseBH = sbBH + s * 10240 + boff;
#pragma unroll
        for (int ks = 0; ks < 2; ks++) {
            uint32_t ah[2][4], al[2][4];
            LDMX4(ah[0], baseAH + ks * 32);
            LDMX4(ah[1], baseAH + 1280 + ks * 32);
            LDMX4(al[0], baseAL + ks * 32);
            LDMX4(al[1], baseAL + 1280 + ks * 32);
#pragma unroll
            for (int ntp = 0; ntp < 2; ntp++) {
                uint32_t bh[4];
                LDMX4(bh, baseBH + ntp * 1280 + ks * 32);
#pragma unroll
                for (int mt = 0; mt < 2; mt++) {
                    mma_f16(d[mt][2 * ntp],     ah[mt], &bh[0]);
                    mma_f16(d[mt][2 * ntp],     al[mt], &bh[0]);
                    mma_f16(d[mt][2 * ntp + 1], ah[mt], &bh[2]);
                    mma_f16(d[mt][2 * ntp + 1], al[mt], &bh[2]);
                }
            }
        }
        __syncthreads();
        if (c + 2 <= 7) { issueB(c + 2); CP_WAIT1(); }
        else if (c + 1 <= 7) { CP_WAIT0(); }
        __syncthreads();
    }

#pragma unroll
    for (int mt = 0; mt < 2; mt++) {
#pragma unroll
        for (int hh2 = 0; hh2 < 2; hh2++) {
            float s = 0.f, s2 = 0.f;
#pragma unroll
            for (int nt = 0; nt < 4; nt++) {
#pragma unroll
                for (int cc2 = 0; cc2 < 2; cc2++) {
                    int col = wn * 32 + nt * 8 + qc + cc2;
                    float xv = fmaxf(d[mt][nt][hh2 * 2 + cc2] + sb_bout[col], 0.f);
                    d[mt][nt][hh2 * 2 + cc2] = xv;
                    s += xv;
                    s2 += xv * xv;
                }
            }
            s  += __shfl_xor_sync(0xffffffffu, s, 1);
            s  += __shfl_xor_sync(0xffffffffu, s, 2);
            s2 += __shfl_xor_sync(0xffffffffu, s2, 1);
            s2 += __shfl_xor_sync(0xffffffffu, s2, 2);
            if ((lane & 3) == 0) {
                int r = wm * 32 + mt * 16 + qr + hh2 * 8;
                atomicAdd(&rs[r], s);
                atomicAdd(&rs2[r], s2);
            }
        }
    }
    __syncthreads();
#pragma unroll
    for (int mt = 0; mt < 2; mt++) {
#pragma unroll
        for (int hh2 = 0; hh2 < 2; hh2++) {
            int r = wm * 32 + mt * 16 + qr + hh2 * 8;
            float mu = rs[r] * (1.f / 128.f);
            float var = rs2[r] * (1.f / 128.f) - mu * mu;
            float inv = rsqrtf(fmaxf(var, 0.f) + 1e-5f);
            int m = m0 + r;
#pragma unroll
            for (int nt = 0; nt < 4; nt++) {
                int col = wn * 32 + nt * 8 + qc;
                float2 o;
                o.x = (d[mt][nt][hh2 * 2 + 0] - mu) * inv * sb_gam[col] + sb_bet[col];
                o.y = (d[mt][nt][hh2 * 2 + 1] - mu) * inv * sb_gam[col + 1] + sb_bet[col + 1];
                *(float2*)&out[(size_t)m * DD + col] = o;
            }
        }
    }
}

// ---------------- launch ----------------
extern "C" void kernel_launch(void* const* d_in, const int* in_sizes, int n_in,
                              void* d_out, int out_size) {
    const float* h    = (const float*)d_in[0];
    const float* f    = (const float*)d_in[1];
    const float* dt   = (const float*)d_in[2];
    const int*   dst  = (const int*)d_in[3];
    const float* freq = (const float*)d_in[4];
    const float* tb   = (const float*)d_in[5];
    const float* Wq   = (const float*)d_in[6];
    const float* bq   = (const float*)d_in[7];
    const float* Wk   = (const float*)d_in[8];
    const float* bk   = (const float*)d_in[9];
    const float* Wv   = (const float*)d_in[10];
    const float* bv   = (const float*)d_in[11];
    const float* Wout = (const float*)d_in[12];
    const float* bout = (const float*)d_in[13];
    const float* gam  = (const float*)d_in[14];
    const float* bet  = (const float*)d_in[15];
    float* out = (float*)d_out;

    cudaFuncSetAttribute(k_kv, cudaFuncAttributeMaxDynamicSharedMemorySize, KV_SMEM);

    k_wconv<<<48, 1024>>>(Wk, Wv);
    k_wconvO<<<16, 1024>>>(Wout);
    k_wconvQ<<<8, 1024>>>(Wq);
    k_bqeff<<<128, 128>>>(Wq, bq, tb);
    k_zero<<<ND / 256, 256>>>();
    k_count<<<NE / 256, 256>>>(dst);
    k_scan<<<1, 1024>>>();
    k_scatter<<<NE / 256, 256>>>(dst);
    k_gemmQT<<<ND / 64, 256>>>(h);
    k_kv<<<NE / 64, 256, KV_SMEM>>>(h, f, dt, freq, tb, bk, bv, dst);
    k_node<<<ND / 8, 256>>>();
    k_gemmOutT<<<ND / 64, 256>>>(h, bout, gam, bet, out);
}

// round 15
// speedup vs baseline: 1.2121x; 1.0063x over previous
#include <cuda_runtime.h>
#include <cuda_fp16.h>
#include <cstdint>

#define ND 32768
#define NE 524288
#define DD 128
#define NH 8

// ---------------- scratch (static device memory; no allocations) ----------------
__device__ float    g_Qnodes[(size_t)ND * DD];   // 16 MB
__device__ __half   g_Vh[(size_t)NE * DD];       // 128 MB (fp16 V, CSR order)
__device__ float    g_logits[(size_t)NE * NH];   // 16 MB (CSR order)
__device__ float    g_agg[ND * DD];              // 16 MB
__device__ float    g_bqeff[DD];
// preconverted weights fp16, chunk-tiled
__device__ uint32_t g_WH[12 * 256 * 16];   // [Wk;Wv]
__device__ uint32_t g_WOH[8 * 128 * 16];   // Wout
__device__ uint32_t g_WQH[4 * 128 * 16];   // Wq[:, :128]
// CSR edge binning
__device__ int g_cnt[ND];
__device__ int g_off[ND + 1];
__device__ int g_pos[ND];
__device__ int g_eperm[NE];   // e -> CSR position

// ---------------- CSR build ----------------
__global__ void k_zero() {
    int i = blockIdx.x * blockDim.x + threadIdx.x;
    if (i < ND) g_cnt[i] = 0;
}
__global__ void k_count(const int* __restrict__ dst_idx) {
    int e = blockIdx.x * blockDim.x + threadIdx.x;
    if (e < NE) atomicAdd(&g_cnt[dst_idx[e]], 1);
}
__global__ void __launch_bounds__(1024) k_scan() {
    __shared__ int ps[1024];
    int t = threadIdx.x;
    int base = t * 32;
    int loc[32];
    int s = 0;
#pragma unroll
    for (int j = 0; j < 32; j++) { loc[j] = s; s += g_cnt[base + j]; }
    ps[t] = s;
    __syncthreads();
    for (int off = 1; off < 1024; off <<= 1) {
        int v = (t >= off) ? ps[t - off] : 0;
        __syncthreads();
        ps[t] += v;
        __syncthreads();
    }
    int excl = (t == 0) ? 0 : ps[t - 1];
#pragma unroll
    for (int j = 0; j < 32; j++) {
        int o = excl + loc[j];
        g_off[base + j] = o;
        g_pos[base + j] = o;
    }
    if (t == 1023) g_off[ND] = ps[1023];
}
__global__ void k_scatter(const int* __restrict__ dst_idx) {
    int e = blockIdx.x * blockDim.x + threadIdx.x;
    if (e < NE) {
        int p = atomicAdd(&g_pos[dst_idx[e]], 1);
        g_eperm[e] = p;
    }
}

// bq_eff[j] = bq[j] + sum_t cos(tb[t]) * Wq[j, 128+t] — parallel: one block per j
__global__ void __launch_bounds__(128) k_bqeff(const float* __restrict__ Wq,
                                               const float* __restrict__ bq,
                                               const float* __restrict__ tb) {
    __shared__ float ws[4];
    int j = blockIdx.x, t = threadIdx.x;
    float v = cosf(tb[t]) * Wq[j * 256 + 128 + t];
#pragma unroll
    for (int off = 16; off >= 1; off >>= 1)
        v += __shfl_xor_sync(0xffffffffu, v, off);
    if ((t & 31) == 0) ws[t >> 5] = v;
    __syncthreads();
    if (t == 0) g_bqeff[j] = bq[j] + ws[0] + ws[1] + ws[2] + ws[3];
}

// ======== fp16 pack/split helpers ========
__device__ __forceinline__ uint32_t pack2h(float x, float y) {
    __half hx = __float2half_rn(x), hy = __float2half_rn(y);
    return (uint32_t)__half_as_ushort(hx) | ((uint32_t)__half_as_ushort(hy) << 16);
}
__device__ __forceinline__ void cstoreH(uint32_t* H, int i, float4 v) {
    *(uint2*)(H + i) = make_uint2(pack2h(v.x, v.y), pack2h(v.z, v.w));
}
__device__ __forceinline__ void split2h(float x, float y, uint32_t& hi, uint32_t& lo) {
    __half hx = __float2half_rn(x), hy = __float2half_rn(y);
    __half lx = __float2half_rn(x - __half2float(hx));
    __half ly = __float2half_rn(y - __half2float(hy));
    hi = (uint32_t)__half_as_ushort(hx) | ((uint32_t)__half_as_ushort(hy) << 16);
    lo = (uint32_t)__half_as_ushort(lx) | ((uint32_t)__half_as_ushort(ly) << 16);
}
__device__ __forceinline__ void cstoreHL(uint32_t* H, uint32_t* L, int i, float4 v) {
    uint32_t h0, l0, h1, l1;
    split2h(v.x, v.y, h0, l0);
    split2h(v.z, v.w, h1, l1);
    *(uint2*)(H + i) = make_uint2(h0, h1);
    *(uint2*)(L + i) = make_uint2(l0, l1);
}

// ---------------- weight preconversion ----------------
__global__ void k_wconv(const float* __restrict__ Wk, const float* __restrict__ Wv) {
    int i = blockIdx.x * blockDim.x + threadIdx.x;   // 49152 u32 slots
    int c = i >> 12;
    int n = (i >> 4) & 255;
    int q = i & 15;
    int k = c * 32 + q * 2;
    const float* src = (n < 128) ? &Wk[n * 384 + k] : &Wv[(n - 128) * 384 + k];
    g_WH[i] = pack2h(src[0], src[1]);
}
__global__ void k_wconvO(const float* __restrict__ Wout) {
    int i = blockIdx.x * blockDim.x + threadIdx.x;   // 16384 u32 slots
    int c = i >> 11;
    int n = (i >> 4) & 127;
    int q = i & 15;
    int k = c * 32 + q * 2;
    g_WOH[i] = pack2h(Wout[n * 256 + k], Wout[n * 256 + k + 1]);
}
__global__ void k_wconvQ(const float* __restrict__ Wq) {
    int i = blockIdx.x * blockDim.x + threadIdx.x;   // 8192 u32 slots
    int c = i >> 11;
    int n = (i >> 4) & 127;
    int q = i & 15;
    int k = c * 32 + q * 2;
    g_WQH[i] = pack2h(Wq[n * 256 + k], Wq[n * 256 + k + 1]);
}

// ======== mma.sync / ldmatrix / cp.async primitives ========
__device__ __forceinline__ void mma_f16(float* d, const uint32_t* a, const uint32_t* b) {
    asm volatile(
        "mma.sync.aligned.m16n8k16.row.col.f32.f16.f16.f32 "
        "{%0,%1,%2,%3},{%4,%5,%6,%7},{%8,%9},{%0,%1,%2,%3};"
        : "+f"(d[0]), "+f"(d[1]), "+f"(d[2]), "+f"(d[3])
        : "r"(a[0]), "r"(a[1]), "r"(a[2]), "r"(a[3]), "r"(b[0]), "r"(b[1]));
}
#define LDMX4(r, addr) \
    asm volatile("ldmatrix.sync.aligned.m8n8.x4.shared.b16 {%0,%1,%2,%3}, [%4];" \
        : "=r"((r)[0]), "=r"((r)[1]), "=r"((r)[2]), "=r"((r)[3]) : "r"(addr))

__device__ __forceinline__ uint32_t smem_u32(const void* p) {
    uint32_t a;
    asm("{ .reg .u64 t; cvta.to.shared.u64 t, %1; cvt.u32.u64 %0, t; }" : "=r"(a) : "l"(p));
    return a;
}
#define CP_ASYNC16(saddr, gptr) \
    asm volatile("cp.async.ca.shared.global [%0], [%1], 16;" :: "r"(saddr), "l"(gptr))
#define CP_COMMIT() asm volatile("cp.async.commit_group;" ::: "memory")
#define CP_WAIT1()  asm volatile("cp.async.wait_group 1;" ::: "memory")
#define CP_WAIT0()  asm volatile("cp.async.wait_group 0;" ::: "memory")

// ---------------- SMEM layout for k_kv (dynamic, 53760 B; 2 CTAs/SM) ----------------
#define OFF_BK    0
#define OFF_BV    512
#define OFF_DT    1024
#define OFF_FREQ  1536
#define OFF_TB    2048
#define OFF_AH    2560
#define OFF_BH    (OFF_AH + 10240)
#define KV_SMEM   (OFF_BH + 40960)            // 53760

// ================= fused K+V projection (M=64/CTA, 2 CTAs/SM, mma.sync fp16) =================
__global__ void __launch_bounds__(256, 2) k_kv(const float* __restrict__ h,
                                               const float* __restrict__ f,
                                               const float* __restrict__ dt,
                                               const float* __restrict__ freq,
                                               const float* __restrict__ tb,
                                               const float* __restrict__ bk,
                                               const float* __restrict__ bv,
                                               const int* __restrict__ dst_idx) {
    extern __shared__ char smem[];
    uint32_t sb = smem_u32(smem);
    int tid = threadIdx.x, wid = tid >> 5, lane = tid & 31;
    int e0 = blockIdx.x * 64;

    float* sbk   = (float*)(smem + OFF_BK);
    float* sbv   = (float*)(smem + OFF_BV);
    float* dts   = (float*)(smem + OFF_DT);
    float* freqs = (float*)(smem + OFF_FREQ);
    float* tbs   = (float*)(smem + OFF_TB);
    if (tid < 128) {
        sbk[tid] = bk[tid];
        sbv[tid] = bv[tid];
        freqs[tid] = freq[tid];
        tbs[tid] = tb[tid];
        if (tid < 64) dts[tid] = dt[e0 + tid];
    }

    auto issueB = [&](int g) {
        int s = g & 1;
#pragma unroll
        for (int r = 0; r < 4; r++) {
            int idx = tid + r * 256;
            int n = idx >> 2, q4 = (idx & 3) * 4;
            CP_ASYNC16(sb + OFF_BH + s * 20480 + (n * 20 + q4) * 4,
                       &g_WH[(g * 256 + n) * 16 + q4]);
        }
        CP_COMMIT();
    };

    auto ldgA = [&](int g, float4* av) {
        if (g < 8) {
            const float* base = (g < 4) ? h + (size_t)(ND + e0) * DD + g * 32
                                        : f + (size_t)e0 * DD + (g - 4) * 32;
#pragma unroll
            for (int r = 0; r < 2; r++) {
                int idx = tid + r * 256;
                int m = idx >> 3, kq = (idx & 7) * 4;
                av[r] = *(const float4*)(base + (size_t)m * DD + kq);
            }
        }
    };
    auto convA = [&](int g, const float4* av) {
        int s = g & 1;
        uint32_t* AH = (uint32_t*)(smem + OFF_AH + s * 5120);
#pragma unroll
        for (int r = 0; r < 2; r++) {
            int idx = tid + r * 256;
            int m = idx >> 3, kq = (idx & 7) * 4;
            float4 v;
            if (g < 8) v = av[r];
            else {
                int ko = (g - 8) * 32 + kq;
                float d = dts[m];
                v.x = __cosf(fmaf(d, freqs[ko + 0], tbs[ko + 0]));
                v.y = __cosf(fmaf(d, freqs[ko + 1], tbs[ko + 1]));
                v.z = __cosf(fmaf(d, freqs[ko + 2], tbs[ko + 2]));
                v.w = __cosf(fmaf(d, freqs[ko + 3], tbs[ko + 3]));
            }
            cstoreH(AH, m * 20 + (kq >> 1), v);
        }
    };

    int wm = wid & 1, wn = wid >> 1;
    int qr = lane >> 2, qc = (lane & 3) * 2;
    float d[2][8][4];
#pragma unroll
    for (int mt = 0; mt < 2; mt++)
#pragma unroll
        for (int nt = 0; nt < 8; nt++)
#pragma unroll
            for (int j = 0; j < 4; j++) d[mt][nt][j] = 0.f;

    uint32_t aoff = (uint32_t)(wm * 32 + (lane & 7) + ((lane >> 3) & 1) * 8) * 80
                  + ((lane >> 4) & 1) * 16;
    uint32_t boff = (uint32_t)(wn * 64 + (lane & 7) + ((lane >> 4) & 1) * 8) * 80
                  + ((lane >> 3) & 1) * 16;

    float4 av[2];
    issueB(0);
    issueB(1);
    ldgA(0, av);
    convA(0, av);
    ldgA(1, av);
    CP_WAIT1();
    __syncthreads();

    for (int c = 0; c < 12; c++) {
        int s = c & 1;
        if (c + 1 <= 11) convA(c + 1, av);
        if (c + 2 <= 11) ldgA(c + 2, av);

        uint32_t baseAH = sb + OFF_AH + s * 5120 + aoff;
        uint32_t baseBH = sb + OFF_BH + s * 20480 + boff;
#pragma unroll
        for (int ks = 0; ks < 2; ks++) {
            uint32_t ah[2][4];
            LDMX4(ah[0], baseAH + ks * 32);
            LDMX4(ah[1], baseAH + 1280 + ks * 32);
#pragma unroll
            for (int ntp = 0; ntp < 4; ntp++) {
                uint32_t bh[4];
                LDMX4(bh, baseBH + ntp * 1280 + ks * 32);
#pragma unroll
                for (int mt = 0; mt < 2; mt++) {
                    mma_f16(d[mt][2 * ntp],     ah[mt], &bh[0]);
                    mma_f16(d[mt][2 * ntp + 1], ah[mt], &bh[2]);
                }
            }
        }
        __syncthreads();
        if (c + 2 <= 11) { issueB(c + 2); CP_WAIT1(); }
        else if (c + 1 <= 11) { CP_WAIT0(); }
        __syncthreads();
    }

    // ---- epilogue: K warps write logits (CSR order); V warps write V (fp16, CSR order) ----
    if (wn < 2) {
#pragma unroll
        for (int mt = 0; mt < 2; mt++) {
#pragma unroll
            for (int hh2 = 0; hh2 < 2; hh2++) {
                int e = e0 + wm * 32 + mt * 16 + qr + hh2 * 8;
                int dsti = dst_idx[e];
                const float* q = &g_Qnodes[(size_t)dsti * DD];
                float part[4] = {0.f, 0.f, 0.f, 0.f};
#pragma unroll
                for (int nt = 0; nt < 8; nt++) {
                    int cc = wn * 64 + nt * 8 + qc;
                    float v0 = d[mt][nt][hh2 * 2 + 0] + sbk[cc];
                    float v1 = d[mt][nt][hh2 * 2 + 1] + sbk[cc + 1];
                    float2 qv = *(const float2*)&q[cc];
                    part[(nt * 8 + qc) >> 4] += v0 * qv.x + v1 * qv.y;
                }
#pragma unroll
                for (int i = 0; i < 4; i++) {
                    part[i] += __shfl_xor_sync(0xffffffffu, part[i], 1);
                    part[i] += __shfl_xor_sync(0xffffffffu, part[i], 2);
                }
                if ((lane & 3) == 0) {
                    int pe = g_eperm[e];
#pragma unroll
                    for (int hh = 0; hh < 4; hh++) {
                        int head = wn * 4 + hh;
                        float p = part[hh];
                        float l = p > 0.f ? p : 0.2f * p;
                        g_logits[(size_t)pe * NH + head] = l;
                    }
                }
            }
        }
    } else {
        int cvb = (wn - 2) * 64;
#pragma unroll
        for (int mt = 0; mt < 2; mt++) {
#pragma unroll
            for (int hh2 = 0; hh2 < 2; hh2++) {
                int e = e0 + wm * 32 + mt * 16 + qr + hh2 * 8;
                size_t pe = (size_t)g_eperm[e];
#pragma unroll
                for (int nt = 0; nt < 8; nt++) {
                    int cc = cvb + nt * 8 + qc;
                    float v0 = d[mt][nt][hh2 * 2 + 0] + sbv[cc];
                    float v1 = d[mt][nt][hh2 * 2 + 1] + sbv[cc + 1];
                    *(uint32_t*)&g_Vh[pe * DD + cc] = pack2h(v0, v1);
                }
            }
        }
    }
}

// ================= Q projection via mma.sync fp16 (A hi/lo 2-product) =================
__global__ void __launch_bounds__(256, 2) k_gemmQT(const float* __restrict__ h) {
    __shared__ uint32_t sAH[2][64 * 20];
    __shared__ uint32_t sAL[2][64 * 20];
    __shared__ uint32_t sBH[2][128 * 20];
    __shared__ float sb_bq[128];

    int tid = threadIdx.x, wid = tid >> 5, lane = tid & 31;
    int m0 = blockIdx.x * 64;
    uint32_t sbAH = smem_u32(&sAH[0][0]);
    uint32_t sbAL = smem_u32(&sAL[0][0]);
    uint32_t sbBH = smem_u32(&sBH[0][0]);

    if (tid < 128) sb_bq[tid] = g_bqeff[tid];

    auto issueB = [&](int g) {
        int s = g & 1;
#pragma unroll
        for (int r = 0; r < 2; r++) {
            int idx = tid + r * 256;
            int n = idx >> 2, q4 = (idx & 3) * 4;
            CP_ASYNC16(sbBH + s * 10240 + (n * 20 + q4) * 4,
                       &g_WQH[(g * 128 + n) * 16 + q4]);
        }
        CP_COMMIT();
    };
    auto ldgA = [&](int g, float4* av) {
        const float* base = h + (size_t)m0 * DD + g * 32;
#pragma unroll
        for (int r = 0; r < 2; r++) {
            int idx = tid + r * 256;
            int m = idx >> 3, kq = (idx & 7) * 4;
            av[r] = *(const float4*)(base + (size_t)m * DD + kq);
        }
    };
    auto convA = [&](int g, const float4* av) {
        int s = g & 1;
        uint32_t* AH = (uint32_t*)&sAH[s][0];
        uint32_t* AL = (uint32_t*)&sAL[s][0];
#pragma unroll
        for (int r = 0; r < 2; r++) {
            int idx = tid + r * 256;
            int m = idx >> 3, kq = (idx & 7) * 4;
            cstoreHL(AH, AL, m * 20 + (kq >> 1), av[r]);
        }
    };

    int wm = wid & 1, wn = wid >> 1;
    int qr = lane >> 2, qc = (lane & 3) * 2;
    float d[2][4][4];
#pragma unroll
    for (int mt = 0; mt < 2; mt++)
#pragma unroll
        for (int nt = 0; nt < 4; nt++)
#pragma unroll
            for (int j = 0; j < 4; j++) d[mt][nt][j] = 0.f;

    uint32_t aoff = (uint32_t)(wm * 32 + (lane & 7) + ((lane >> 3) & 1) * 8) * 80
                  + ((lane >> 4) & 1) * 16;
    uint32_t boff = (uint32_t)(wn * 32 + (lane & 7) + ((lane >> 4) & 1) * 8) * 80
                  + ((lane >> 3) & 1) * 16;

    float4 av[2];
    issueB(0);
    issueB(1);
    ldgA(0, av);
    convA(0, av);
    ldgA(1, av);
    CP_WAIT1();
    __syncthreads();

    for (int c = 0; c < 4; c++) {
        int s = c & 1;
        if (c + 1 <= 3) convA(c + 1, av);
        if (c + 2 <= 3) ldgA(c + 2, av);

        uint32_t baseAH = sbAH + s * 5120 + aoff;
        uint32_t baseAL = sbAL + s * 5120 + aoff;
        uint32_t baseBH = sbBH + s * 10240 + boff;
#pragma unroll
        for (int ks = 0; ks < 2; ks++) {
            uint32_t ah[2][4], al[2][4];
            LDMX4(ah[0], baseAH + ks * 32);
            LDMX4(ah[1], baseAH + 1280 + ks * 32);
            LDMX4(al[0], baseAL + ks * 32);
            LDMX4(al[1], baseAL + 1280 + ks * 32);
#pragma unroll
            for (int ntp = 0; ntp < 2; ntp++) {
                uint32_t bh[4];
                LDMX4(bh, baseBH + ntp * 1280 + ks * 32);
#pragma unroll
                for (int mt = 0; mt < 2; mt++) {
                    mma_f16(d[mt][2 * ntp],     ah[mt], &bh[0]);
                    mma_f16(d[mt][2 * ntp],     al[mt], &bh[0]);
                    mma_f16(d[mt][2 * ntp + 1], ah[mt], &bh[2]);
                    mma_f16(d[mt][2 * ntp + 1], al[mt], &bh[2]);
                }
            }
        }
        __syncthreads();
        if (c + 2 <= 3) { issueB(c + 2); CP_WAIT1(); }
        else if (c + 1 <= 3) { CP_WAIT0(); }
        __syncthreads();
    }

#pragma unroll
    for (int mt = 0; mt < 2; mt++) {
#pragma unroll
        for (int hh2 = 0; hh2 < 2; hh2++) {
            int m = m0 + wm * 32 + mt * 16 + qr + hh2 * 8;
#pragma unroll
            for (int nt = 0; nt < 4; nt++) {
                int col = wn * 32 + nt * 8 + qc;
                float2 o;
                o.x = d[mt][nt][hh2 * 2 + 0] + sb_bq[col];
                o.y = d[mt][nt][hh2 * 2 + 1] + sb_bq[col + 1];
                *(float2*)&g_Qnodes[(size_t)m * DD + col] = o;
            }
        }
    }
}

// ---------------- per-node softmax + aggregation (CSR order: fully streaming) ----------------
__global__ void __launch_bounds__(256) k_node() {
    int n = blockIdx.x * 8 + (threadIdx.x >> 5);
    int lane = threadIdx.x & 31;
    int beg = g_off[n], end = g_off[n + 1];

    float mx[NH];
#pragma unroll
    for (int hh = 0; hh < NH; hh++) mx[hh] = -1e30f;
    for (int i = beg + lane; i < end; i += 32) {
        float4 l0 = *(const float4*)&g_logits[(size_t)i * NH];
        float4 l1 = *(const float4*)&g_logits[(size_t)i * NH + 4];
        mx[0] = fmaxf(mx[0], l0.x); mx[1] = fmaxf(mx[1], l0.y);
        mx[2] = fmaxf(mx[2], l0.z); mx[3] = fmaxf(mx[3], l0.w);
        mx[4] = fmaxf(mx[4], l1.x); mx[5] = fmaxf(mx[5], l1.y);
        mx[6] = fmaxf(mx[6], l1.z); mx[7] = fmaxf(mx[7], l1.w);
    }
#pragma unroll
    for (int hh = 0; hh < NH; hh++)
#pragma unroll
        for (int off = 16; off >= 1; off >>= 1)
            mx[hh] = fmaxf(mx[hh], __shfl_xor_sync(0xffffffffu, mx[hh], off));

    float sm[NH];
#pragma unroll
    for (int hh = 0; hh < NH; hh++) sm[hh] = 0.f;
    for (int i = beg + lane; i < end; i += 32) {
        float4 l0 = *(const float4*)&g_logits[(size_t)i * NH];
        float4 l1 = *(const float4*)&g_logits[(size_t)i * NH + 4];
        sm[0] += expf(l0.x - mx[0]); sm[1] += expf(l0.y - mx[1]);
        sm[2] += expf(l0.z - mx[2]); sm[3] += expf(l0.w - mx[3]);
        sm[4] += expf(l1.x - mx[4]); sm[5] += expf(l1.y - mx[5]);
        sm[6] += expf(l1.z - mx[6]); sm[7] += expf(l1.w - mx[7]);
    }
#pragma unroll
    for (int hh = 0; hh < NH; hh++)
#pragma unroll
        for (int off = 16; off >= 1; off >>= 1)
            sm[hh] += __shfl_xor_sync(0xffffffffu, sm[hh], off);

    int head = lane >> 2;
    float mh = mx[head];
    float ish = (sm[head] > 0.f) ? 1.f / sm[head] : 0.f;
    float4 acc = make_float4(0.f, 0.f, 0.f, 0.f);
    int i = beg;
    for (; i + 2 <= end; i += 2) {
        float lg0 = g_logits[(size_t)i * NH + head];
        float lg1 = g_logits[(size_t)(i + 1) * NH + head];
        uint2 vp0 = *(const uint2*)&g_Vh[(size_t)i * DD + lane * 4];
        uint2 vp1 = *(const uint2*)&g_Vh[(size_t)(i + 1) * DD + lane * 4];
        float a0 = expf(lg0 - mh) * ish;
        float a1 = expf(lg1 - mh) * ish;
        float2 v01 = __half22float2(*(const __half2*)&vp0.x);
        float2 v23 = __half22float2(*(const __half2*)&vp0.y);
        float2 w01 = __half22float2(*(const __half2*)&vp1.x);
        float2 w23 = __half22float2(*(const __half2*)&vp1.y);
        acc.x = fmaf(a0, v01.x, fmaf(a1, w01.x, acc.x));
        acc.y = fmaf(a0, v01.y, fmaf(a1, w01.y, acc.y));
        acc.z = fmaf(a0, v23.x, fmaf(a1, w23.x, acc.z));
        acc.w = fmaf(a0, v23.y, fmaf(a1, w23.y, acc.w));
    }
    for (; i < end; i++) {
        float att = expf(g_logits[(size_t)i * NH + head] - mh) * ish;
        uint2 vp = *(const uint2*)&g_Vh[(size_t)i * DD + lane * 4];
        float2 v01 = __half22float2(*(const __half2*)&vp.x);
        float2 v23 = __half22float2(*(const __half2*)&vp.y);
        acc.x = fmaf(att, v01.x, acc.x);
        acc.y = fmaf(att, v01.y, acc.y);
        acc.z = fmaf(att, v23.x, acc.z);
        acc.w = fmaf(att, v23.y, acc.w);
    }
    *(float4*)&g_agg[n * DD + lane * 4] = acc;
}

// ================= output projection via mma.sync fp16 (A hi/lo 2-product) + relu + LN =================
__global__ void __launch_bounds__(256, 2) k_gemmOutT(const float* __restrict__ h,
                                                     const float* __restrict__ bout,
                                                     const float* __restrict__ gam,
                                                     const float* __restrict__ bet,
                                                     float* __restrict__ out) {
    __shared__ uint32_t sAH[2][64 * 20];
    __shared__ uint32_t sAL[2][64 * 20];
    __shared__ uint32_t sBH[2][128 * 20];
    __shared__ float sb_bout[128], sb_gam[128], sb_bet[128];
    __shared__ float rs[64], rs2[64];

    int tid = threadIdx.x, wid = tid >> 5, lane = tid & 31;
    int m0 = blockIdx.x * 64;
    uint32_t sbAH = smem_u32(&sAH[0][0]);
    uint32_t sbAL = smem_u32(&sAL[0][0]);
    uint32_t sbBH = smem_u32(&sBH[0][0]);

    if (tid < 128) {
        sb_bout[tid] = bout[tid];
        sb_gam[tid] = gam[tid];
        sb_bet[tid] = bet[tid];
        if (tid < 64) { rs[tid] = 0.f; rs2[tid] = 0.f; }
    }

    auto issueB = [&](int g) {
        int s = g & 1;
#pragma unroll
        for (int r = 0; r < 2; r++) {
            int idx = tid + r * 256;
            int n = idx >> 2, q4 = (idx & 3) * 4;
            CP_ASYNC16(sbBH + s * 10240 + (n * 20 + q4) * 4,
                       &g_WOH[(g * 128 + n) * 16 + q4]);
        }
        CP_COMMIT();
    };
    auto ldgA = [&](int g, float4* av) {
        const float* base = (g < 4) ? g_agg + (size_t)m0 * DD + g * 32
                                    : h + (size_t)m0 * DD + (g - 4) * 32;
#pragma unroll
        for (int r = 0; r < 2; r++) {
            int idx = tid + r * 256;
            int m = idx >> 3, kq = (idx & 7) * 4;
            av[r] = *(const float4*)(base + (size_t)m * DD + kq);
        }
    };
    auto convA = [&](int g, const float4* av) {
        int s = g & 1;
        uint32_t* AH = (uint32_t*)&sAH[s][0];
        uint32_t* AL = (uint32_t*)&sAL[s][0];
#pragma unroll
        for (int r = 0; r < 2; r++) {
            int idx = tid + r * 256;
            int m = idx >> 3, kq = (idx & 7) * 4;
            cstoreHL(AH, AL, m * 20 + (kq >> 1), av[r]);
        }
    };

    int wm = wid & 1, wn = wid >> 1;
    int qr = lane >> 2, qc = (lane & 3) * 2;
    float d[2][4][4];
#pragma unroll
    for (int mt = 0; mt < 2; mt++)
#pragma unroll
        for (int nt = 0; nt < 4; nt++)
#pragma unroll
            for (int j = 0; j < 4; j++) d[mt][nt][j] = 0.f;

    uint32_t aoff = (uint32_t)(wm * 32 + (lane & 7) + ((lane >> 3) & 1) * 8) * 80
                  + ((lane >> 4) & 1) * 16;
    uint32_t boff = (uint32_t)(wn * 32 + (lane & 7) + ((lane >> 4) & 1) * 8) * 80
                  + ((lane >> 3) & 1) * 16;

    float4 av[2];
    issueB(0);
    issueB(1);
    ldgA(0, av);
    convA(0, av);
    ldgA(1, av);
    CP_WAIT1();
    __syncthreads();

    for (int c = 0; c < 8; c++) {
        int s = c & 1;
        if (c + 1 <= 7) convA(c + 1, av);
        if (c + 2 <= 7) ldgA(c + 2, av);

        uint32_t baseAH = sbAH + s * 5120 + aoff;
        uint32_t baseAL = sbAL + s * 5120 + aoff;
        uint32_t baseBH = sbBH + s * 10240 + boff;
#pragma unroll
        for (int ks = 0; ks < 2; ks++) {
            uint32_t ah[2][4], al[2][4];
            LDMX4(ah[0], baseAH + ks * 32);
            LDMX4(ah[1], baseAH + 1280 + ks * 32);
            LDMX4(al[0], baseAL + ks * 32);
            LDMX4(al[1], baseAL + 1280 + ks * 32);
#pragma unroll
            for (int ntp = 0; ntp < 2; ntp++) {
                uint32_t bh[4];
                LDMX4(bh, baseBH + ntp * 1280 + ks * 32);
#pragma unroll
                for (int mt = 0; mt < 2; mt++) {
                    mma_f16(d[mt][2 * ntp],     ah[mt], &bh[0]);
                    mma_f16(d[mt][2 * ntp],     al[mt], &bh[0]);
                    mma_f16(d[mt][2 * ntp + 1], ah[mt], &bh[2]);
                    mma_f16(d[mt][2 * ntp + 1], al[mt], &bh[2]);
                }
            }
        }
        __syncthreads();
        if (c + 2 <= 7) { issueB(c + 2); CP_WAIT1(); }
        else if (c + 1 <= 7) { CP_WAIT0(); }
        __syncthreads();
    }

#pragma unroll
    for (int mt = 0; mt < 2; mt++) {
#pragma unroll
        for (int hh2 = 0; hh2 < 2; hh2++) {
            float s = 0.f, s2 = 0.f;
#pragma unroll
            for (int nt = 0; nt < 4; nt++) {
#pragma unroll
                for (int cc2 = 0; cc2 < 2; cc2++) {
                    int col = wn * 32 + nt * 8 + qc + cc2;
                    float xv = fmaxf(d[mt][nt][hh2 * 2 + cc2] + sb_bout[col], 0.f);
                    d[mt][nt][hh2 * 2 + cc2] = xv;
                    s += xv;
                    s2 += xv * xv;
                }
            }
            s  += __shfl_xor_sync(0xffffffffu, s, 1);
            s  += __shfl_xor_sync(0xffffffffu, s, 2);
            s2 += __shfl_xor_sync(0xffffffffu, s2, 1);
            s2 += __shfl_xor_sync(0xffffffffu, s2, 2);
            if ((lane & 3) == 0) {
                int r = wm * 32 + mt * 16 + qr + hh2 * 8;
                atomicAdd(&rs[r], s);
                atomicAdd(&rs2[r], s2);
            }
        }
    }
    __syncthreads();
#pragma unroll
    for (int mt = 0; mt < 2; mt++) {
#pragma unroll
        for (int hh2 = 0; hh2 < 2; hh2++) {
            int r = wm * 32 + mt * 16 + qr + hh2 * 8;
            float mu = rs[r] * (1.f / 128.f);
            float var = rs2[r] * (1.f / 128.f) - mu * mu;
            float inv = rsqrtf(fmaxf(var, 0.f) + 1e-5f);
            int m = m0 + r;
#pragma unroll
            for (int nt = 0; nt < 4; nt++) {
                int col = wn * 32 + nt * 8 + qc;
                float2 o;
                o.x = (d[mt][nt][hh2 * 2 + 0] - mu) * inv * sb_gam[col] + sb_bet[col];
                o.y = (d[mt][nt][hh2 * 2 + 1] - mu) * inv * sb_gam[col + 1] + sb_bet[col + 1];
                *(float2*)&out[(size_t)m * DD + col] = o;
            }
        }
    }
}

// ---------------- launch ----------------
extern "C" void kernel_launch(void* const* d_in, const int* in_sizes, int n_in,
                              void* d_out, int out_size) {
    const float* h    = (const float*)d_in[0];
    const float* f    = (const float*)d_in[1];
    const float* dt   = (const float*)d_in[2];
    const int*   dst  = (const int*)d_in[3];
    const float* freq = (const float*)d_in[4];
    const float* tb   = (const float*)d_in[5];
    const float* Wq   = (const float*)d_in[6];
    const float* bq   = (const float*)d_in[7];
    const float* Wk   = (const float*)d_in[8];
    const float* bk   = (const float*)d_in[9];
    const float* Wv   = (const float*)d_in[10];
    const float* bv   = (const float*)d_in[11];
    const float* Wout = (const float*)d_in[12];
    const float* bout = (const float*)d_in[13];
    const float* gam  = (const float*)d_in[14];
    const float* bet  = (const float*)d_in[15];
    float* out = (float*)d_out;

    cudaFuncSetAttribute(k_kv, cudaFuncAttributeMaxDynamicSharedMemorySize, KV_SMEM);

    k_wconv<<<48, 1024>>>(Wk, Wv);
    k_wconvO<<<16, 1024>>>(Wout);
    k_wconvQ<<<8, 1024>>>(Wq);
    k_bqeff<<<128, 128>>>(Wq, bq, tb);
    k_zero<<<ND / 256, 256>>>();
    k_count<<<NE / 256, 256>>>(dst);
    k_scan<<<1, 1024>>>();
    k_scatter<<<NE / 256, 256>>>(dst);
    k_gemmQT<<<ND / 64, 256>>>(h);
    k_kv<<<NE / 64, 256, KV_SMEM>>>(h, f, dt, freq, tb, bk, bv, dst);
    k_node<<<ND / 8, 256>>>();
    k_gemmOutT<<<ND / 64, 256>>>(h, bout, gam, bet, out);
}

// round 16
// speedup vs baseline: 1.2561x; 1.0363x over previous
#include <cuda_runtime.h>
#include <cuda_fp16.h>
#include <cstdint>

#define ND 32768
#define NE 524288
#define DD 128
#define NH 8

// ---------------- scratch (static device memory; no allocations) ----------------
__device__ float    g_Qnodes[(size_t)ND * DD];   // 16 MB
__device__ __half   g_Vh[(size_t)NE * DD];       // 128 MB (fp16 V, CSR order)
__device__ float    g_logits[(size_t)NE * NH];   // 16 MB (CSR order)
__device__ float    g_agg[ND * DD];              // 16 MB
__device__ float    g_bqeff[DD];
// preconverted weights fp16, chunk-tiled
__device__ uint32_t g_WH[12 * 256 * 16];   // [Wk;Wv]
__device__ uint32_t g_WOH[8 * 128 * 16];   // Wout
__device__ uint32_t g_WQH[4 * 128 * 16];   // Wq[:, :128]
// CSR edge binning
__device__ int g_cnt[ND];
__device__ int g_off[ND + 1];
__device__ int g_pos[ND];
__device__ int g_eperm[NE];   // e -> CSR position

// ---------------- CSR build ----------------
__global__ void k_zero() {
    int i = blockIdx.x * blockDim.x + threadIdx.x;
    if (i < ND) g_cnt[i] = 0;
}
__global__ void k_count(const int* __restrict__ dst_idx) {
    int e = blockIdx.x * blockDim.x + threadIdx.x;
    if (e < NE) atomicAdd(&g_cnt[dst_idx[e]], 1);
}
__global__ void __launch_bounds__(1024) k_scan() {
    __shared__ int ps[1024];
    int t = threadIdx.x;
    int base = t * 32;
    int loc[32];
    int s = 0;
#pragma unroll
    for (int j = 0; j < 32; j++) { loc[j] = s; s += g_cnt[base + j]; }
    ps[t] = s;
    __syncthreads();
    for (int off = 1; off < 1024; off <<= 1) {
        int v = (t >= off) ? ps[t - off] : 0;
        __syncthreads();
        ps[t] += v;
        __syncthreads();
    }
    int excl = (t == 0) ? 0 : ps[t - 1];
#pragma unroll
    for (int j = 0; j < 32; j++) {
        int o = excl + loc[j];
        g_off[base + j] = o;
        g_pos[base + j] = o;
    }
    if (t == 1023) g_off[ND] = ps[1023];
}
__global__ void k_scatter(const int* __restrict__ dst_idx) {
    int e = blockIdx.x * blockDim.x + threadIdx.x;
    if (e < NE) {
        int p = atomicAdd(&g_pos[dst_idx[e]], 1);
        g_eperm[e] = p;
    }
}

// bq_eff[j] = bq[j] + sum_t cos(tb[t]) * Wq[j, 128+t] — parallel: one block per j
__global__ void __launch_bounds__(128) k_bqeff(const float* __restrict__ Wq,
                                               const float* __restrict__ bq,
                                               const float* __restrict__ tb) {
    __shared__ float ws[4];
    int j = blockIdx.x, t = threadIdx.x;
    float v = cosf(tb[t]) * Wq[j * 256 + 128 + t];
#pragma unroll
    for (int off = 16; off >= 1; off >>= 1)
        v += __shfl_xor_sync(0xffffffffu, v, off);
    if ((t & 31) == 0) ws[t >> 5] = v;
    __syncthreads();
    if (t == 0) g_bqeff[j] = bq[j] + ws[0] + ws[1] + ws[2] + ws[3];
}

// ======== fp16 pack/split helpers ========
__device__ __forceinline__ uint32_t pack2h(float x, float y) {
    __half hx = __float2half_rn(x), hy = __float2half_rn(y);
    return (uint32_t)__half_as_ushort(hx) | ((uint32_t)__half_as_ushort(hy) << 16);
}
__device__ __forceinline__ void cstoreH(uint32_t* H, int i, float4 v) {
    *(uint2*)(H + i) = make_uint2(pack2h(v.x, v.y), pack2h(v.z, v.w));
}
__device__ __forceinline__ void split2h(float x, float y, uint32_t& hi, uint32_t& lo) {
    __half hx = __float2half_rn(x), hy = __float2half_rn(y);
    __half lx = __float2half_rn(x - __half2float(hx));
    __half ly = __float2half_rn(y - __half2float(hy));
    hi = (uint32_t)__half_as_ushort(hx) | ((uint32_t)__half_as_ushort(hy) << 16);
    lo = (uint32_t)__half_as_ushort(lx) | ((uint32_t)__half_as_ushort(ly) << 16);
}
__device__ __forceinline__ void cstoreHL(uint32_t* H, uint32_t* L, int i, float4 v) {
    uint32_t h0, l0, h1, l1;
    split2h(v.x, v.y, h0, l0);
    split2h(v.z, v.w, h1, l1);
    *(uint2*)(H + i) = make_uint2(h0, h1);
    *(uint2*)(L + i) = make_uint2(l0, l1);
}

// ---------------- weight preconversion (merged: Wk/Wv, Wout, Wq) ----------------
// blocks [0,48): g_WH; [48,64): g_WOH; [64,72): g_WQH
__global__ void __launch_bounds__(1024) k_wconvAll(const float* __restrict__ Wk,
                                                   const float* __restrict__ Wv,
                                                   const float* __restrict__ Wout,
                                                   const float* __restrict__ Wq) {
    int b = blockIdx.x;
    if (b < 48) {
        int i = b * 1024 + threadIdx.x;
        int c = i >> 12;
        int n = (i >> 4) & 255;
        int q = i & 15;
        int k = c * 32 + q * 2;
        const float* src = (n < 128) ? &Wk[n * 384 + k] : &Wv[(n - 128) * 384 + k];
        g_WH[i] = pack2h(src[0], src[1]);
    } else if (b < 64) {
        int i = (b - 48) * 1024 + threadIdx.x;
        int c = i >> 11;
        int n = (i >> 4) & 127;
        int q = i & 15;
        int k = c * 32 + q * 2;
        g_WOH[i] = pack2h(Wout[n * 256 + k], Wout[n * 256 + k + 1]);
    } else {
        int i = (b - 64) * 1024 + threadIdx.x;
        int c = i >> 11;
        int n = (i >> 4) & 127;
        int q = i & 15;
        int k = c * 32 + q * 2;
        g_WQH[i] = pack2h(Wq[n * 256 + k], Wq[n * 256 + k + 1]);
    }
}

// ======== mma.sync / ldmatrix / cp.async primitives ========
__device__ __forceinline__ void mma_f16(float* d, const uint32_t* a, const uint32_t* b) {
    asm volatile(
        "mma.sync.aligned.m16n8k16.row.col.f32.f16.f16.f32 "
        "{%0,%1,%2,%3},{%4,%5,%6,%7},{%8,%9},{%0,%1,%2,%3};"
        : "+f"(d[0]), "+f"(d[1]), "+f"(d[2]), "+f"(d[3])
        : "r"(a[0]), "r"(a[1]), "r"(a[2]), "r"(a[3]), "r"(b[0]), "r"(b[1]));
}
#define LDMX4(r, addr) \
    asm volatile("ldmatrix.sync.aligned.m8n8.x4.shared.b16 {%0,%1,%2,%3}, [%4];" \
        : "=r"((r)[0]), "=r"((r)[1]), "=r"((r)[2]), "=r"((r)[3]) : "r"(addr))

__device__ __forceinline__ uint32_t smem_u32(const void* p) {
    uint32_t a;
    asm("{ .reg .u64 t; cvta.to.shared.u64 t, %1; cvt.u32.u64 %0, t; }" : "=r"(a) : "l"(p));
    return a;
}
#define CP_ASYNC16(saddr, gptr) \
    asm volatile("cp.async.ca.shared.global [%0], [%1], 16;" :: "r"(saddr), "l"(gptr))
#define CP_COMMIT() asm volatile("cp.async.commit_group;" ::: "memory")
#define CP_WAIT1()  asm volatile("cp.async.wait_group 1;" ::: "memory")
#define CP_WAIT0()  asm volatile("cp.async.wait_group 0;" ::: "memory")

// ---------------- SMEM layout for k_kv (dynamic, 53760 B; 2 CTAs/SM) ----------------
#define OFF_BK    0
#define OFF_BV    512
#define OFF_DT    1024
#define OFF_FREQ  1536
#define OFF_TB    2048
#define OFF_AH    2560
#define OFF_BH    (OFF_AH + 10240)
#define KV_SMEM   (OFF_BH + 40960)            // 53760

// ================= fused K+V projection (M=64/CTA, 2 CTAs/SM, mma.sync fp16) =================
__global__ void __launch_bounds__(256, 2) k_kv(const float* __restrict__ h,
                                               const float* __restrict__ f,
                                               const float* __restrict__ dt,
                                               const float* __restrict__ freq,
                                               const float* __restrict__ tb,
                                               const float* __restrict__ bk,
                                               const float* __restrict__ bv,
                                               const int* __restrict__ dst_idx) {
    extern __shared__ char smem[];
    uint32_t sb = smem_u32(smem);
    int tid = threadIdx.x, wid = tid >> 5, lane = tid & 31;
    int e0 = blockIdx.x * 64;

    float* sbk   = (float*)(smem + OFF_BK);
    float* sbv   = (float*)(smem + OFF_BV);
    float* dts   = (float*)(smem + OFF_DT);
    float* freqs = (float*)(smem + OFF_FREQ);
    float* tbs   = (float*)(smem + OFF_TB);
    if (tid < 128) {
        sbk[tid] = bk[tid];
        sbv[tid] = bv[tid];
        freqs[tid] = freq[tid];
        tbs[tid] = tb[tid];
        if (tid < 64) dts[tid] = dt[e0 + tid];
    }

    auto issueB = [&](int g) {
        int s = g & 1;
#pragma unroll
        for (int r = 0; r < 4; r++) {
            int idx = tid + r * 256;
            int n = idx >> 2, q4 = (idx & 3) * 4;
            CP_ASYNC16(sb + OFF_BH + s * 20480 + (n * 20 + q4) * 4,
                       &g_WH[(g * 256 + n) * 16 + q4]);
        }
        CP_COMMIT();
    };

    auto ldgA = [&](int g, float4* av) {
        if (g < 8) {
            const float* base = (g < 4) ? h + (size_t)(ND + e0) * DD + g * 32
                                        : f + (size_t)e0 * DD + (g - 4) * 32;
#pragma unroll
            for (int r = 0; r < 2; r++) {
                int idx = tid + r * 256;
                int m = idx >> 3, kq = (idx & 7) * 4;
                av[r] = *(const float4*)(base + (size_t)m * DD + kq);
            }
        }
    };
    auto convA = [&](int g, const float4* av) {
        int s = g & 1;
        uint32_t* AH = (uint32_t*)(smem + OFF_AH + s * 5120);
#pragma unroll
        for (int r = 0; r < 2; r++) {
            int idx = tid + r * 256;
            int m = idx >> 3, kq = (idx & 7) * 4;
            float4 v;
            if (g < 8) v = av[r];
            else {
                int ko = (g - 8) * 32 + kq;
                float d = dts[m];
                v.x = __cosf(fmaf(d, freqs[ko + 0], tbs[ko + 0]));
                v.y = __cosf(fmaf(d, freqs[ko + 1], tbs[ko + 1]));
                v.z = __cosf(fmaf(d, freqs[ko + 2], tbs[ko + 2]));
                v.w = __cosf(fmaf(d, freqs[ko + 3], tbs[ko + 3]));
            }
            cstoreH(AH, m * 20 + (kq >> 1), v);
        }
    };

    int wm = wid & 1, wn = wid >> 1;
    int qr = lane >> 2, qc = (lane & 3) * 2;
    float d[2][8][4];
#pragma unroll
    for (int mt = 0; mt < 2; mt++)
#pragma unroll
        for (int nt = 0; nt < 8; nt++)
#pragma unroll
            for (int j = 0; j < 4; j++) d[mt][nt][j] = 0.f;

    uint32_t aoff = (uint32_t)(wm * 32 + (lane & 7) + ((lane >> 3) & 1) * 8) * 80
                  + ((lane >> 4) & 1) * 16;
    uint32_t boff = (uint32_t)(wn * 64 + (lane & 7) + ((lane >> 4) & 1) * 8) * 80
                  + ((lane >> 3) & 1) * 16;

    float4 av[2];
    issueB(0);
    issueB(1);
    ldgA(0, av);
    convA(0, av);
    ldgA(1, av);
    CP_WAIT1();
    __syncthreads();

    for (int c = 0; c < 12; c++) {
        int s = c & 1;
        if (c + 1 <= 11) convA(c + 1, av);
        if (c + 2 <= 11) ldgA(c + 2, av);

        uint32_t baseAH = sb + OFF_AH + s * 5120 + aoff;
        uint32_t baseBH = sb + OFF_BH + s * 20480 + boff;
#pragma unroll
        for (int ks = 0; ks < 2; ks++) {
            uint32_t ah[2][4];
            LDMX4(ah[0], baseAH + ks * 32);
            LDMX4(ah[1], baseAH + 1280 + ks * 32);
#pragma unroll
            for (int ntp = 0; ntp < 4; ntp++) {
                uint32_t bh[4];
                LDMX4(bh, baseBH + ntp * 1280 + ks * 32);
#pragma unroll
                for (int mt = 0; mt < 2; mt++) {
                    mma_f16(d[mt][2 * ntp],     ah[mt], &bh[0]);
                    mma_f16(d[mt][2 * ntp + 1], ah[mt], &bh[2]);
                }
            }
        }
        __syncthreads();
        if (c + 2 <= 11) { issueB(c + 2); CP_WAIT1(); }
        else if (c + 1 <= 11) { CP_WAIT0(); }
        __syncthreads();
    }

    // ---- epilogue: K warps write logits (CSR order); V warps write V (fp16, CSR order) ----
    if (wn < 2) {
#pragma unroll
        for (int mt = 0; mt < 2; mt++) {
#pragma unroll
            for (int hh2 = 0; hh2 < 2; hh2++) {
                int e = e0 + wm * 32 + mt * 16 + qr + hh2 * 8;
                int dsti = dst_idx[e];
                const float* q = &g_Qnodes[(size_t)dsti * DD];
                float part[4] = {0.f, 0.f, 0.f, 0.f};
#pragma unroll
                for (int nt = 0; nt < 8; nt++) {
                    int cc = wn * 64 + nt * 8 + qc;
                    float v0 = d[mt][nt][hh2 * 2 + 0] + sbk[cc];
                    float v1 = d[mt][nt][hh2 * 2 + 1] + sbk[cc + 1];
                    float2 qv = *(const float2*)&q[cc];
                    part[(nt * 8 + qc) >> 4] += v0 * qv.x + v1 * qv.y;
                }
#pragma unroll
                for (int i = 0; i < 4; i++) {
                    part[i] += __shfl_xor_sync(0xffffffffu, part[i], 1);
                    part[i] += __shfl_xor_sync(0xffffffffu, part[i], 2);
                }
                if ((lane & 3) == 0) {
                    int pe = g_eperm[e];
#pragma unroll
                    for (int hh = 0; hh < 4; hh++) {
                        int head = wn * 4 + hh;
                        float p = part[hh];
                        float l = p > 0.f ? p : 0.2f * p;
                        g_logits[(size_t)pe * NH + head] = l;
                    }
                }
            }
        }
    } else {
        int cvb = (wn - 2) * 64;
#pragma unroll
        for (int mt = 0; mt < 2; mt++) {
#pragma unroll
            for (int hh2 = 0; hh2 < 2; hh2++) {
                int e = e0 + wm * 32 + mt * 16 + qr + hh2 * 8;
                size_t pe = (size_t)g_eperm[e];
#pragma unroll
                for (int nt = 0; nt < 8; nt++) {
                    int cc = cvb + nt * 8 + qc;
                    float v0 = d[mt][nt][hh2 * 2 + 0] + sbv[cc];
                    float v1 = d[mt][nt][hh2 * 2 + 1] + sbv[cc + 1];
                    *(uint32_t*)&g_Vh[pe * DD + cc] = pack2h(v0, v1);
                }
            }
        }
    }
}

// ================= Q projection via mma.sync fp16 (A hi/lo 2-product) =================
__global__ void __launch_bounds__(256, 2) k_gemmQT(const float* __restrict__ h) {
    __shared__ uint32_t sAH[2][64 * 20];
    __shared__ uint32_t sAL[2][64 * 20];
    __shared__ uint32_t sBH[2][128 * 20];
    __shared__ float sb_bq[128];

    int tid = threadIdx.x, wid = tid >> 5, lane = tid & 31;
    int m0 = blockIdx.x * 64;
    uint32_t sbAH = smem_u32(&sAH[0][0]);
    uint32_t sbAL = smem_u32(&sAL[0][0]);
    uint32_t sbBH = smem_u32(&sBH[0][0]);

    if (tid < 128) sb_bq[tid] = g_bqeff[tid];

    auto issueB = [&](int g) {
        int s = g & 1;
#pragma unroll
        for (int r = 0; r < 2; r++) {
            int idx = tid + r * 256;
            int n = idx >> 2, q4 = (idx & 3) * 4;
            CP_ASYNC16(sbBH + s * 10240 + (n * 20 + q4) * 4,
                       &g_WQH[(g * 128 + n) * 16 + q4]);
        }
        CP_COMMIT();
    };
    auto ldgA = [&](int g, float4* av) {
        const float* base = h + (size_t)m0 * DD + g * 32;
#pragma unroll
        for (int r = 0; r < 2; r++) {
            int idx = tid + r * 256;
            int m = idx >> 3, kq = (idx & 7) * 4;
            av[r] = *(const float4*)(base + (size_t)m * DD + kq);
        }
    };
    auto convA = [&](int g, const float4* av) {
        int s = g & 1;
        uint32_t* AH = (uint32_t*)&sAH[s][0];
        uint32_t* AL = (uint32_t*)&sAL[s][0];
#pragma unroll
        for (int r = 0; r < 2; r++) {
            int idx = tid + r * 256;
            int m = idx >> 3, kq = (idx & 7) * 4;
            cstoreHL(AH, AL, m * 20 + (kq >> 1), av[r]);
        }
    };

    int wm = wid & 1, wn = wid >> 1;
    int qr = lane >> 2, qc = (lane & 3) * 2;
    float d[2][4][4];
#pragma unroll
    for (int mt = 0; mt < 2; mt++)
#pragma unroll
        for (int nt = 0; nt < 4; nt++)
#pragma unroll
            for (int j = 0; j < 4; j++) d[mt][nt][j] = 0.f;

    uint32_t aoff = (uint32_t)(wm * 32 + (lane & 7) + ((lane >> 3) & 1) * 8) * 80
                  + ((lane >> 4) & 1) * 16;
    uint32_t boff = (uint32_t)(wn * 32 + (lane & 7) + ((lane >> 4) & 1) * 8) * 80
                  + ((lane >> 3) & 1) * 16;

    float4 av[2];
    issueB(0);
    issueB(1);
    ldgA(0, av);
    convA(0, av);
    ldgA(1, av);
    CP_WAIT1();
    __syncthreads();

    for (int c = 0; c < 4; c++) {
        int s = c & 1;
        if (c + 1 <= 3) convA(c + 1, av);
        if (c + 2 <= 3) ldgA(c + 2, av);

        uint32_t baseAH = sbAH + s * 5120 + aoff;
        uint32_t baseAL = sbAL + s * 5120 + aoff;
        uint32_t baseBH = sbBH + s * 10240 + boff;
#pragma unroll
        for (int ks = 0; ks < 2; ks++) {
            uint32_t ah[2][4], al[2][4];
            LDMX4(ah[0], baseAH + ks * 32);
            LDMX4(ah[1], baseAH + 1280 + ks * 32);
            LDMX4(al[0], baseAL + ks * 32);
            LDMX4(al[1], baseAL + 1280 + ks * 32);
#pragma unroll
            for (int ntp = 0; ntp < 2; ntp++) {
                uint32_t bh[4];
                LDMX4(bh, baseBH + ntp * 1280 + ks * 32);
#pragma unroll
                for (int mt = 0; mt < 2; mt++) {
                    mma_f16(d[mt][2 * ntp],     ah[mt], &bh[0]);
                    mma_f16(d[mt][2 * ntp],     al[mt], &bh[0]);
                    mma_f16(d[mt][2 * ntp + 1], ah[mt], &bh[2]);
                    mma_f16(d[mt][2 * ntp + 1], al[mt], &bh[2]);
                }
            }
        }
        __syncthreads();
        if (c + 2 <= 3) { issueB(c + 2); CP_WAIT1(); }
        else if (c + 1 <= 3) { CP_WAIT0(); }
        __syncthreads();
    }

#pragma unroll
    for (int mt = 0; mt < 2; mt++) {
#pragma unroll
        for (int hh2 = 0; hh2 < 2; hh2++) {
            int m = m0 + wm * 32 + mt * 16 + qr + hh2 * 8;
#pragma unroll
            for (int nt = 0; nt < 4; nt++) {
                int col = wn * 32 + nt * 8 + qc;
                float2 o;
                o.x = d[mt][nt][hh2 * 2 + 0] + sb_bq[col];
                o.y = d[mt][nt][hh2 * 2 + 1] + sb_bq[col + 1];
                *(float2*)&g_Qnodes[(size_t)m * DD + col] = o;
            }
        }
    }
}

// ---------------- per-node single-pass online softmax + aggregation ----------------
__global__ void __launch_bounds__(256) k_node() {
    int n = blockIdx.x * 8 + (threadIdx.x >> 5);
    int lane = threadIdx.x & 31;
    int beg = g_off[n], end = g_off[n + 1];

    int head = lane >> 2;
    float m = -1e30f, s = 0.f;
    float4 acc = make_float4(0.f, 0.f, 0.f, 0.f);

    int i = beg;
    for (; i + 2 <= end; i += 2) {
        float l0 = g_logits[(size_t)i * NH + head];
        float l1 = g_logits[(size_t)(i + 1) * NH + head];
        uint2 vp0 = *(const uint2*)&g_Vh[(size_t)i * DD + lane * 4];
        uint2 vp1 = *(const uint2*)&g_Vh[(size_t)(i + 1) * DD + lane * 4];
        float nm = fmaxf(m, fmaxf(l0, l1));
        float sc = expf(m - nm);
        float w0 = expf(l0 - nm);
        float w1 = expf(l1 - nm);
        s = s * sc + w0 + w1;
        float2 v01 = __half22float2(*(const __half2*)&vp0.x);
        float2 v23 = __half22float2(*(const __half2*)&vp0.y);
        float2 u01 = __half22float2(*(const __half2*)&vp1.x);
        float2 u23 = __half22float2(*(const __half2*)&vp1.y);
        acc.x = fmaf(acc.x, sc, fmaf(w0, v01.x, w1 * u01.x));
        acc.y = fmaf(acc.y, sc, fmaf(w0, v01.y, w1 * u01.y));
        acc.z = fmaf(acc.z, sc, fmaf(w0, v23.x, w1 * u23.x));
        acc.w = fmaf(acc.w, sc, fmaf(w0, v23.y, w1 * u23.y));
        m = nm;
    }
    for (; i < end; i++) {
        float l0 = g_logits[(size_t)i * NH + head];
        uint2 vp = *(const uint2*)&g_Vh[(size_t)i * DD + lane * 4];
        float nm = fmaxf(m, l0);
        float sc = expf(m - nm);
        float w0 = expf(l0 - nm);
        s = s * sc + w0;
        float2 v01 = __half22float2(*(const __half2*)&vp.x);
        float2 v23 = __half22float2(*(const __half2*)&vp.y);
        acc.x = fmaf(acc.x, sc, w0 * v01.x);
        acc.y = fmaf(acc.y, sc, w0 * v01.y);
        acc.z = fmaf(acc.z, sc, w0 * v23.x);
        acc.w = fmaf(acc.w, sc, w0 * v23.y);
        m = nm;
    }
    float inv = (s > 0.f) ? 1.f / s : 0.f;
    acc.x *= inv; acc.y *= inv; acc.z *= inv; acc.w *= inv;
    *(float4*)&g_agg[n * DD + lane * 4] = acc;
}

// ================= output projection via mma.sync fp16 (A hi/lo 2-product) + relu + LN =================
__global__ void __launch_bounds__(256, 2) k_gemmOutT(const float* __restrict__ h,
                                                     const float* __restrict__ bout,
                                                     const float* __restrict__ gam,
                                                     const float* __restrict__ bet,
                                                     float* __restrict__ out) {
    __shared__ uint32_t sAH[2][64 * 20];
    __shared__ uint32_t sAL[2][64 * 20];
    __shared__ uint32_t sBH[2][128 * 20];
    __shared__ float sb_bout[128], sb_gam[128], sb_bet[128];
    __shared__ float rs[64], rs2[64];

    int tid = threadIdx.x, wid = tid >> 5, lane = tid & 31;
    int m0 = blockIdx.x * 64;
    uint32_t sbAH = smem_u32(&sAH[0][0]);
    uint32_t sbAL = smem_u32(&sAL[0][0]);
    uint32_t sbBH = smem_u32(&sBH[0][0]);

    if (tid < 128) {
        sb_bout[tid] = bout[tid];
        sb_gam[tid] = gam[tid];
        sb_bet[tid] = bet[tid];
        if (tid < 64) { rs[tid] = 0.f; rs2[tid] = 0.f; }
    }

    auto issueB = [&](int g) {
        int s = g & 1;
#pragma unroll
        for (int r = 0; r < 2; r++) {
            int idx = tid + r * 256;
            int n = idx >> 2, q4 = (idx & 3) * 4;
            CP_ASYNC16(sbBH + s * 10240 + (n * 20 + q4) * 4,
                       &g_WOH[(g * 128 + n) * 16 + q4]);
        }
        CP_COMMIT();
    };
    auto ldgA = [&](int g, float4* av) {
        const float* base = (g < 4) ? g_agg + (size_t)m0 * DD + g * 32
                                    : h + (size_t)m0 * DD + (g - 4) * 32;
#pragma unroll
        for (int r = 0; r < 2; r++) {
            int idx = tid + r * 256;
            int m = idx >> 3, kq = (idx & 7) * 4;
            av[r] = *(const float4*)(base + (size_t)m * DD + kq);
        }
    };
    auto convA = [&](int g, const float4* av) {
        int s = g & 1;
        uint32_t* AH = (uint32_t*)&sAH[s][0];
        uint32_t* AL = (uint32_t*)&sAL[s][0];
#pragma unroll
        for (int r = 0; r < 2; r++) {
            int idx = tid + r * 256;
            int m = idx >> 3, kq = (idx & 7) * 4;
            cstoreHL(AH, AL, m * 20 + (kq >> 1), av[r]);
        }
    };

    int wm = wid & 1, wn = wid >> 1;
    int qr = lane >> 2, qc = (lane & 3) * 2;
    float d[2][4][4];
#pragma unroll
    for (int mt = 0; mt < 2; mt++)
#pragma unroll
        for (int nt = 0; nt < 4; nt++)
#pragma unroll
            for (int j = 0; j < 4; j++) d[mt][nt][j] = 0.f;

    uint32_t aoff = (uint32_t)(wm * 32 + (lane & 7) + ((lane >> 3) & 1) * 8) * 80
                  + ((lane >> 4) & 1) * 16;
    uint32_t boff = (uint32_t)(wn * 32 + (lane & 7) + ((lane >> 4) & 1) * 8) * 80
                  + ((lane >> 3) & 1) * 16;

    float4 av[2];
    issueB(0);
    issueB(1);
    ldgA(0, av);
    convA(0, av);
    ldgA(1, av);
    CP_WAIT1();
    __syncthreads();

    for (int c = 0; c < 8; c++) {
        int s = c & 1;
        if (c + 1 <= 7) convA(c + 1, av);
        if (c + 2 <= 7) ldgA(c + 2, av);

        uint32_t baseAH = sbAH + s * 5120 + aoff;
        uint32_t baseAL = sbAL + s * 5120 + aoff;
        uint32_t baseBH = sbBH + s * 10240 + boff;
#pragma unroll
        for (int ks = 0; ks < 2; ks++) {
            uint32_t ah[2][4], al[2][4];
            LDMX4(ah[0], baseAH + ks * 32);
            LDMX4(ah[1], baseAH + 1280 + ks * 32);
            LDMX4(al[0], baseAL + ks * 32);
            LDMX4(al[1], baseAL + 1280 + ks * 32);
#pragma unroll
            for (int ntp = 0; ntp < 2; ntp++) {
                uint32_t bh[4];
                LDMX4(bh, baseBH + ntp * 1280 + ks * 32);
#pragma unroll
                for (int mt = 0; mt < 2; mt++) {
                    mma_f16(d[mt][2 * ntp],     ah[mt], &bh[0]);
                    mma_f16(d[mt][2 * ntp],     al[mt], &bh[0]);
                    mma_f16(d[mt][2 * ntp + 1], ah[mt], &bh[2]);
                    mma_f16(d[mt][2 * ntp + 1], al[mt], &bh[2]);
                }
            }
        }
        __syncthreads();
        if (c + 2 <= 7) { issueB(c + 2); CP_WAIT1(); }
        else if (c + 1 <= 7) { CP_WAIT0(); }
        __syncthreads();
    }

#pragma unroll
    for (int mt = 0; mt < 2; mt++) {
#pragma unroll
        for (int hh2 = 0; hh2 < 2; hh2++) {
            float s = 0.f, s2 = 0.f;
#pragma unroll
            for (int nt = 0; nt < 4; nt++) {
#pragma unroll
                for (int cc2 = 0; cc2 < 2; cc2++) {
                    int col = wn * 32 + nt * 8 + qc + cc2;
                    float xv = fmaxf(d[mt][nt][hh2 * 2 + cc2] + sb_bout[col], 0.f);
                    d[mt][nt][hh2 * 2 + cc2] = xv;
                    s += xv;
                    s2 += xv * xv;
                }
            }
            s  += __shfl_xor_sync(0xffffffffu, s, 1);
            s  += __shfl_xor_sync(0xffffffffu, s, 2);
            s2 += __shfl_xor_sync(0xffffffffu, s2, 1);
            s2 += __shfl_xor_sync(0xffffffffu, s2, 2);
            if ((lane & 3) == 0) {
                int r = wm * 32 + mt * 16 + qr + hh2 * 8;
                atomicAdd(&rs[r], s);
                atomicAdd(&rs2[r], s2);
            }
        }
    }
    __syncthreads();
#pragma unroll
    for (int mt = 0; mt < 2; mt++) {
#pragma unroll
        for (int hh2 = 0; hh2 < 2; hh2++) {
            int r = wm * 32 + mt * 16 + qr + hh2 * 8;
            float mu = rs[r] * (1.f / 128.f);
            float var = rs2[r] * (1.f / 128.f) - mu * mu;
            float inv = rsqrtf(fmaxf(var, 0.f) + 1e-5f);
            int m = m0 + r;
#pragma unroll
            for (int nt = 0; nt < 4; nt++) {
                int col = wn * 32 + nt * 8 + qc;
                float2 o;
                o.x = (d[mt][nt][hh2 * 2 + 0] - mu) * inv * sb_gam[col] + sb_bet[col];
                o.y = (d[mt][nt][hh2 * 2 + 1] - mu) * inv * sb_gam[col + 1] + sb_bet[col + 1];
                *(float2*)&out[(size_t)m * DD + col] = o;
            }
        }
    }
}

// ---------------- launch ----------------
extern "C" void kernel_launch(void* const* d_in, const int* in_sizes, int n_in,
                              void* d_out, int out_size) {
    const float* h    = (const float*)d_in[0];
    const float* f    = (const float*)d_in[1];
    const float* dt   = (const float*)d_in[2];
    const int*   dst  = (const int*)d_in[3];
    const float* freq = (const float*)d_in[4];
    const float* tb   = (const float*)d_in[5];
    const float* Wq   = (const float*)d_in[6];
    const float* bq   = (const float*)d_in[7];
    const float* Wk   = (const float*)d_in[8];
    const float* bk   = (const float*)d_in[9];
    const float* Wv   = (const float*)d_in[10];
    const float* bv   = (const float*)d_in[11];
    const float* Wout = (const float*)d_in[12];
    const float* bout = (const float*)d_in[13];
    const float* gam  = (const float*)d_in[14];
    const float* bet  = (const float*)d_in[15];
    float* out = (float*)d_out;

    cudaFuncSetAttribute(k_kv, cudaFuncAttributeMaxDynamicSharedMemorySize, KV_SMEM);

    k_wconvAll<<<72, 1024>>>(Wk, Wv, Wout, Wq);
    k_bqeff<<<128, 128>>>(Wq, bq, tb);
    k_zero<<<ND / 256, 256>>>();
    k_count<<<NE / 256, 256>>>(dst);
    k_scan<<<1, 1024>>>();
    k_scatter<<<NE / 256, 256>>>(dst);
    k_gemmQT<<<ND / 64, 256>>>(h);
    k_kv<<<NE / 64, 256, KV_SMEM>>>(h, f, dt, freq, tb, bk, bv, dst);
    k_node<<<ND / 8, 256>>>();
    k_gemmOutT<<<ND / 64, 256>>>(h, bout, gam, bet, out);
}